// round 1
// baseline (speedup 1.0000x reference)
#include <cuda_runtime.h>
#include <cstdint>

#define BB 4
#define NQ 1024
#define NKV 4096
#define NHEAD 8
#define DHEAD 64
#define INNER 512
#define VD 512
#define SCALE 0.125f

// ---------------- scratch ----------------
__device__ float g_q[BB * NQ * INNER];      // 8 MB
__device__ float g_k[BB * NKV * INNER];     // 32 MB
__device__ float g_v[BB * NKV * VD];        // 32 MB
__device__ float g_ao[BB * NQ * VD];        // 8 MB
__device__ int   g_mask_is_byte;

// ---------------- mask dtype detection ----------------
// If mask is int32 (0/1), bytes at offsets %4 != 0 are always zero.
// If mask is bool/uint8, ~half of those bytes are nonzero (P(all zero) ~ 2^-1500).
__global__ void detect_mask_kernel(const unsigned char* __restrict__ m) {
    __shared__ int any;
    if (threadIdx.x == 0) any = 0;
    __syncthreads();
    int found = 0;
    for (int i = threadIdx.x; i < 4096; i += blockDim.x)
        if ((i & 3) && m[i]) found = 1;
    if (found) atomicOr(&any, 1);
    __syncthreads();
    if (threadIdx.x == 0) g_mask_is_byte = any;
}

// ---------------- fp32 tiled GEMM: C[row] = A[M,K] @ W[K,N] + bias ----------------
// 64x64 tile, BK=16, 256 threads, 4x4 per thread.
// Output row remap: grow -> b = grow/Mb, n = grow%Mb, orow = b*bStride + rowOff + n
__global__ __launch_bounds__(256) void gemm_bias_kernel(
    const float* __restrict__ A, const float* __restrict__ W,
    const float* __restrict__ bias, float* __restrict__ C,
    int K, int N, int Mb, int rowOff, int bStride)
{
    __shared__ float As[16][64];
    __shared__ float Ws[16][64];
    const int tid = threadIdx.x;
    const int tx = tid & 15, ty = tid >> 4;
    const int row0 = blockIdx.y * 64;
    const int col0 = blockIdx.x * 64;

    const int aRow = tid >> 2, aC4 = tid & 3;   // A loader: 64 rows x 4 float4
    const int wRow = tid >> 4, wC = tid & 15;   // W loader: 16 rows x 16 float4

    float acc[4][4] = {};

    for (int k0 = 0; k0 < K; k0 += 16) {
        float4 av = *(const float4*)(A + (size_t)(row0 + aRow) * K + k0 + aC4 * 4);
        As[aC4 * 4 + 0][aRow] = av.x;
        As[aC4 * 4 + 1][aRow] = av.y;
        As[aC4 * 4 + 2][aRow] = av.z;
        As[aC4 * 4 + 3][aRow] = av.w;
        *(float4*)(&Ws[wRow][wC * 4]) =
            *(const float4*)(W + (size_t)(k0 + wRow) * N + col0 + wC * 4);
        __syncthreads();
#pragma unroll
        for (int kk = 0; kk < 16; ++kk) {
            float4 a4 = *(const float4*)(&As[kk][ty * 4]);
            float4 w4 = *(const float4*)(&Ws[kk][tx * 4]);
            float ar[4] = {a4.x, a4.y, a4.z, a4.w};
            float wr[4] = {w4.x, w4.y, w4.z, w4.w};
#pragma unroll
            for (int i = 0; i < 4; ++i)
#pragma unroll
                for (int j = 0; j < 4; ++j) acc[i][j] += ar[i] * wr[j];
        }
        __syncthreads();
    }

    float bv[4];
#pragma unroll
    for (int j = 0; j < 4; ++j) bv[j] = bias[col0 + tx * 4 + j];

#pragma unroll
    for (int i = 0; i < 4; ++i) {
        int grow = row0 + ty * 4 + i;
        int b = grow / Mb, n = grow - b * Mb;
        size_t orow = (size_t)b * bStride + rowOff + n;
        float4 outv = make_float4(acc[i][0] + bv[0], acc[i][1] + bv[1],
                                  acc[i][2] + bv[2], acc[i][3] + bv[3]);
        *(float4*)(C + orow * (size_t)N + col0 + tx * 4) = outv;
    }
}

// ---------------- flash attention (fp32) ----------------
// Block: one (b, h, 64-query tile). 256 threads = 16x16, 4x4 register tiles.
// Online softmax over 64 KV tiles of 64 keys.
__global__ __launch_bounds__(256) void attn_kernel(
    const float* __restrict__ qb, const float* __restrict__ kb,
    const float* __restrict__ vb,
    const void* __restrict__ m1, const void* __restrict__ m2,
    const void* __restrict__ m3,
    float* __restrict__ ob)
{
    extern __shared__ float sm[];
    float* Qt = sm;                    // [64 d][64 q]
    float* Kt = sm + 4096;             // [64 d][64 k]
    float* Vs = sm + 8192;             // [64 k][64 d]
    float* Ps = sm + 12288;            // [64 q][65]
    unsigned char* Ms = (unsigned char*)(sm + 12288 + 64 * 65); // [64 q][64 k] bytes

    const int tid = threadIdx.x;
    const int tx = tid & 15, ty = tid >> 4;
    const int b = blockIdx.z, h = blockIdx.y, q0 = blockIdx.x * 64;
    const int mask_is_byte = g_mask_is_byte;

    // Load Q tile transposed: Qt[d][q]
#pragma unroll
    for (int it = 0; it < 4; ++it) {
        int idx = tid + it * 256;
        int r = idx >> 4, c4 = idx & 15;
        float4 v = *(const float4*)(qb + ((size_t)(b * NQ + q0 + r)) * INNER + h * DHEAD + c4 * 4);
        Qt[(c4 * 4 + 0) * 64 + r] = v.x;
        Qt[(c4 * 4 + 1) * 64 + r] = v.y;
        Qt[(c4 * 4 + 2) * 64 + r] = v.z;
        Qt[(c4 * 4 + 3) * 64 + r] = v.w;
    }

    float m_i[4], l_i[4], o[4][4];
#pragma unroll
    for (int i = 0; i < 4; ++i) {
        m_i[i] = -1e30f; l_i[i] = 0.f;
#pragma unroll
        for (int j = 0; j < 4; ++j) o[i][j] = 0.f;
    }

    for (int t = 0; t < 64; ++t) {
        const int j0 = t * 64;
        __syncthreads();  // protect Kt/Vs/Ms from previous iteration's readers

        // Load K (transposed) and V tiles
#pragma unroll
        for (int it = 0; it < 4; ++it) {
            int idx = tid + it * 256;
            int r = idx >> 4, c4 = idx & 15;
            size_t goff = ((size_t)(b * NKV + j0 + r)) * INNER + h * DHEAD + c4 * 4;
            float4 kv = *(const float4*)(kb + goff);
            Kt[(c4 * 4 + 0) * 64 + r] = kv.x;
            Kt[(c4 * 4 + 1) * 64 + r] = kv.y;
            Kt[(c4 * 4 + 2) * 64 + r] = kv.z;
            Kt[(c4 * 4 + 3) * 64 + r] = kv.w;
            *(float4*)(Vs + r * 64 + c4 * 4) = *(const float4*)(vb + goff);
        }

        // Load mask tile (segment selection matches K/V concat order)
        {
            const void* mp; int nseg, jloc;
            if (j0 < 1024)      { mp = m1; nseg = 1024; jloc = j0; }
            else if (j0 < 2048) { mp = m2; nseg = 1024; jloc = j0 - 1024; }
            else                { mp = m3; nseg = 2048; jloc = j0 - 2048; }
            int r = tid >> 2, u = tid & 3;
            size_t rowbase = ((size_t)(b * NQ + q0 + r)) * nseg + jloc;
            if (mask_is_byte) {
                *((uint4*)(Ms + r * 64 + u * 16)) =
                    *(const uint4*)((const unsigned char*)mp + rowbase + u * 16);
            } else {
                const int* src = (const int*)mp + rowbase + u * 16;
                unsigned char* dst = Ms + r * 64 + u * 16;
#pragma unroll
                for (int e = 0; e < 16; ++e) dst[e] = (unsigned char)(src[e] != 0);
            }
        }
        __syncthreads();

        // S = Q K^T  (4x4 register tile per thread)
        float s[4][4] = {};
#pragma unroll 8
        for (int d = 0; d < 64; ++d) {
            float4 a4 = *(const float4*)(Qt + d * 64 + ty * 4);
            float4 k4 = *(const float4*)(Kt + d * 64 + tx * 4);
            float ar[4] = {a4.x, a4.y, a4.z, a4.w};
            float kr[4] = {k4.x, k4.y, k4.z, k4.w};
#pragma unroll
            for (int i = 0; i < 4; ++i)
#pragma unroll
                for (int j = 0; j < 4; ++j) s[i][j] += ar[i] * kr[j];
        }

        // mask + scale + online softmax update (rows reduced across 16 lanes)
#pragma unroll
        for (int i = 0; i < 4; ++i) {
            int qr = ty * 4 + i;
            float rm = -1e30f;
            unsigned vbits = 0;
#pragma unroll
            for (int j = 0; j < 4; ++j) {
                bool valid = Ms[qr * 64 + tx * 4 + j] != 0;
                float sv = valid ? s[i][j] * SCALE : -1e30f;
                s[i][j] = sv;
                if (valid) vbits |= (1u << j);
                rm = fmaxf(rm, sv);
            }
#pragma unroll
            for (int off = 8; off; off >>= 1)
                rm = fmaxf(rm, __shfl_xor_sync(0xffffffffu, rm, off, 16));
            float mn = fmaxf(m_i[i], rm);
            float alpha = __expf(m_i[i] - mn);
            float rs = 0.f;
#pragma unroll
            for (int j = 0; j < 4; ++j) {
                float p = (vbits & (1u << j)) ? __expf(s[i][j] - mn) : 0.f;
                s[i][j] = p;
                rs += p;
            }
#pragma unroll
            for (int off = 8; off; off >>= 1)
                rs += __shfl_xor_sync(0xffffffffu, rs, off, 16);
            l_i[i] = l_i[i] * alpha + rs;
            m_i[i] = mn;
#pragma unroll
            for (int j = 0; j < 4; ++j) {
                o[i][j] *= alpha;
                Ps[qr * 65 + tx * 4 + j] = s[i][j];
            }
        }
        __syncthreads();

        // O += P @ V
#pragma unroll 4
        for (int kk = 0; kk < 64; ++kk) {
            float4 v4 = *(const float4*)(Vs + kk * 64 + tx * 4);
            float vr[4] = {v4.x, v4.y, v4.z, v4.w};
#pragma unroll
            for (int i = 0; i < 4; ++i) {
                float p = Ps[(ty * 4 + i) * 65 + kk];
#pragma unroll
                for (int j = 0; j < 4; ++j) o[i][j] += p * vr[j];
            }
        }
    }

    // finalize and write [b, q, h*64 + d]
#pragma unroll
    for (int i = 0; i < 4; ++i) {
        float inv = 1.f / l_i[i];
        int qr = q0 + ty * 4 + i;
        float4 outv = make_float4(o[i][0] * inv, o[i][1] * inv,
                                  o[i][2] * inv, o[i][3] * inv);
        *(float4*)(ob + ((size_t)(b * NQ + qr)) * VD + h * DHEAD + tx * 4) = outv;
    }
}

// ---------------- launcher ----------------
extern "C" void kernel_launch(void* const* d_in, const int* in_sizes, int n_in,
                              void* d_out, int out_size) {
    const float* x        = (const float*)d_in[0];
    const float* context  = (const float*)d_in[1];
    const float* context2 = (const float*)d_in[2];
    const float* context3 = (const float*)d_in[3];
    const void*  mask1    = d_in[4];
    const void*  mask2    = d_in[5];
    const void*  mask3    = d_in[6];
    const float* Wq  = (const float*)d_in[7];
    const float* bq  = (const float*)d_in[8];
    const float* Wk1 = (const float*)d_in[9];
    const float* bk1 = (const float*)d_in[10];
    const float* Wv1 = (const float*)d_in[11];
    const float* bv1 = (const float*)d_in[12];
    const float* Wk2 = (const float*)d_in[13];
    const float* bk2 = (const float*)d_in[14];
    const float* Wv2 = (const float*)d_in[15];
    const float* bv2 = (const float*)d_in[16];
    const float* Wk3 = (const float*)d_in[17];
    const float* bk3 = (const float*)d_in[18];
    const float* Wv3 = (const float*)d_in[19];
    const float* bv3 = (const float*)d_in[20];
    const float* Wo  = (const float*)d_in[21];
    const float* bo  = (const float*)d_in[22];
    float* out = (float*)d_out;

    float *qp, *kp, *vp, *aop;
    cudaGetSymbolAddress((void**)&qp,  g_q);
    cudaGetSymbolAddress((void**)&kp,  g_k);
    cudaGetSymbolAddress((void**)&vp,  g_v);
    cudaGetSymbolAddress((void**)&aop, g_ao);

    static bool once = false;
    static int smem_attn = (3 * 4096 + 64 * 65) * (int)sizeof(float) + 64 * 64;
    if (!once) {
        cudaFuncSetAttribute(attn_kernel, cudaFuncAttributeMaxDynamicSharedMemorySize,
                             smem_attn);
        once = true;
    }

    detect_mask_kernel<<<1, 256>>>((const unsigned char*)mask1);

    dim3 thr(256);
    // Q: [4096,512] @ [512,512]
    gemm_bias_kernel<<<dim3(8, 64), thr>>>(x, Wq, bq, qp, 512, 512, 1024, 0, 1024);
    // K segments -> g_k [B,4096,512] with row offsets {0,1024,2048}
    gemm_bias_kernel<<<dim3(8, 64),  thr>>>(context,  Wk1, bk1, kp, 512, 512, 1024, 0,    4096);
    gemm_bias_kernel<<<dim3(8, 64),  thr>>>(context2, Wk2, bk2, kp, 768, 512, 1024, 1024, 4096);
    gemm_bias_kernel<<<dim3(8, 128), thr>>>(context3, Wk3, bk3, kp, 256, 512, 2048, 2048, 4096);
    // V segments -> g_v
    gemm_bias_kernel<<<dim3(8, 64),  thr>>>(context,  Wv1, bv1, vp, 512, 512, 1024, 0,    4096);
    gemm_bias_kernel<<<dim3(8, 64),  thr>>>(context2, Wv2, bv2, vp, 768, 512, 1024, 1024, 4096);
    gemm_bias_kernel<<<dim3(8, 128), thr>>>(context3, Wv3, bv3, vp, 256, 512, 2048, 2048, 4096);

    // attention
    attn_kernel<<<dim3(16, NHEAD, BB), thr, smem_attn>>>(
        qp, kp, vp, mask1, mask2, mask3, aop);

    // output projection -> d_out
    gemm_bias_kernel<<<dim3(8, 64), thr>>>(aop, Wo, bo, out, 512, 512, 1024, 0, 1024);
}

// round 2
// speedup vs baseline: 1.0007x; 1.0007x over previous
#include <cuda_runtime.h>
#include <cstdint>

#define BB 4
#define NQ 1024
#define NKV 4096
#define NHEAD 8
#define DHEAD 64
#define INNER 512
#define VD 512
#define SCALE 0.125f

// ---------------- scratch ----------------
__device__ float g_q[BB * NQ * INNER];      // 8 MB
__device__ float g_k[BB * NKV * INNER];     // 32 MB
__device__ float g_v[BB * NKV * VD];        // 32 MB
__device__ float g_ao[BB * NQ * VD];        // 8 MB
__device__ int   g_mask_is_byte;

// ---------------- mask dtype detection ----------------
// If mask is int32 (0/1), bytes at offsets %4 != 0 are always zero.
// If mask is bool/uint8, ~half of those bytes are nonzero (P(all zero) ~ 2^-1500).
__global__ void detect_mask_kernel(const unsigned char* __restrict__ m) {
    __shared__ int any;
    if (threadIdx.x == 0) any = 0;
    __syncthreads();
    int found = 0;
    for (int i = threadIdx.x; i < 4096; i += blockDim.x)
        if ((i & 3) && m[i]) found = 1;
    if (found) atomicOr(&any, 1);
    __syncthreads();
    if (threadIdx.x == 0) g_mask_is_byte = any;
}

// ---------------- fp32 tiled GEMM: C[row] = A[M,K] @ W[K,N] + bias ----------------
// 64x64 tile, BK=16, 256 threads, 4x4 per thread.
// Output row remap: grow -> b = grow/Mb, n = grow%Mb, orow = b*bStride + rowOff + n
__global__ __launch_bounds__(256) void gemm_bias_kernel(
    const float* __restrict__ A, const float* __restrict__ W,
    const float* __restrict__ bias, float* __restrict__ C,
    int K, int N, int Mb, int rowOff, int bStride)
{
    __shared__ float As[16][64];
    __shared__ float Ws[16][64];
    const int tid = threadIdx.x;
    const int tx = tid & 15, ty = tid >> 4;
    const int row0 = blockIdx.y * 64;
    const int col0 = blockIdx.x * 64;

    const int aRow = tid >> 2, aC4 = tid & 3;   // A loader: 64 rows x 4 float4
    const int wRow = tid >> 4, wC = tid & 15;   // W loader: 16 rows x 16 float4

    float acc[4][4] = {};

    for (int k0 = 0; k0 < K; k0 += 16) {
        float4 av = *(const float4*)(A + (size_t)(row0 + aRow) * K + k0 + aC4 * 4);
        As[aC4 * 4 + 0][aRow] = av.x;
        As[aC4 * 4 + 1][aRow] = av.y;
        As[aC4 * 4 + 2][aRow] = av.z;
        As[aC4 * 4 + 3][aRow] = av.w;
        *(float4*)(&Ws[wRow][wC * 4]) =
            *(const float4*)(W + (size_t)(k0 + wRow) * N + col0 + wC * 4);
        __syncthreads();
#pragma unroll
        for (int kk = 0; kk < 16; ++kk) {
            float4 a4 = *(const float4*)(&As[kk][ty * 4]);
            float4 w4 = *(const float4*)(&Ws[kk][tx * 4]);
            float ar[4] = {a4.x, a4.y, a4.z, a4.w};
            float wr[4] = {w4.x, w4.y, w4.z, w4.w};
#pragma unroll
            for (int i = 0; i < 4; ++i)
#pragma unroll
                for (int j = 0; j < 4; ++j) acc[i][j] += ar[i] * wr[j];
        }
        __syncthreads();
    }

    float bv[4];
#pragma unroll
    for (int j = 0; j < 4; ++j) bv[j] = bias[col0 + tx * 4 + j];

#pragma unroll
    for (int i = 0; i < 4; ++i) {
        int grow = row0 + ty * 4 + i;
        int b = grow / Mb, n = grow - b * Mb;
        size_t orow = (size_t)b * bStride + rowOff + n;
        float4 outv = make_float4(acc[i][0] + bv[0], acc[i][1] + bv[1],
                                  acc[i][2] + bv[2], acc[i][3] + bv[3]);
        *(float4*)(C + orow * (size_t)N + col0 + tx * 4) = outv;
    }
}

// ---------------- flash attention (fp32) ----------------
// Block: one (b, h, 64-query tile). 256 threads = 16x16, 4x4 register tiles.
// Online softmax over 64 KV tiles of 64 keys.
__global__ __launch_bounds__(256) void attn_kernel(
    const float* __restrict__ qb, const float* __restrict__ kb,
    const float* __restrict__ vb,
    const void* __restrict__ m1, const void* __restrict__ m2,
    const void* __restrict__ m3,
    float* __restrict__ ob)
{
    extern __shared__ float sm[];
    float* Qt = sm;                    // [64 d][64 q]
    float* Kt = sm + 4096;             // [64 d][64 k]
    float* Vs = sm + 8192;             // [64 k][64 d]
    float* Ps = sm + 12288;            // [64 q][65]
    unsigned char* Ms = (unsigned char*)(sm + 12288 + 64 * 65); // [64 q][64 k] bytes

    const int tid = threadIdx.x;
    const int tx = tid & 15, ty = tid >> 4;
    const int b = blockIdx.z, h = blockIdx.y, q0 = blockIdx.x * 64;
    const int mask_is_byte = g_mask_is_byte;

    // Load Q tile transposed: Qt[d][q]
#pragma unroll
    for (int it = 0; it < 4; ++it) {
        int idx = tid + it * 256;
        int r = idx >> 4, c4 = idx & 15;
        float4 v = *(const float4*)(qb + ((size_t)(b * NQ + q0 + r)) * INNER + h * DHEAD + c4 * 4);
        Qt[(c4 * 4 + 0) * 64 + r] = v.x;
        Qt[(c4 * 4 + 1) * 64 + r] = v.y;
        Qt[(c4 * 4 + 2) * 64 + r] = v.z;
        Qt[(c4 * 4 + 3) * 64 + r] = v.w;
    }

    float m_i[4], l_i[4], o[4][4];
#pragma unroll
    for (int i = 0; i < 4; ++i) {
        m_i[i] = -1e30f; l_i[i] = 0.f;
#pragma unroll
        for (int j = 0; j < 4; ++j) o[i][j] = 0.f;
    }

    for (int t = 0; t < 64; ++t) {
        const int j0 = t * 64;
        __syncthreads();  // protect Kt/Vs/Ms from previous iteration's readers

        // Load K (transposed) and V tiles
#pragma unroll
        for (int it = 0; it < 4; ++it) {
            int idx = tid + it * 256;
            int r = idx >> 4, c4 = idx & 15;
            size_t goff = ((size_t)(b * NKV + j0 + r)) * INNER + h * DHEAD + c4 * 4;
            float4 kv = *(const float4*)(kb + goff);
            Kt[(c4 * 4 + 0) * 64 + r] = kv.x;
            Kt[(c4 * 4 + 1) * 64 + r] = kv.y;
            Kt[(c4 * 4 + 2) * 64 + r] = kv.z;
            Kt[(c4 * 4 + 3) * 64 + r] = kv.w;
            *(float4*)(Vs + r * 64 + c4 * 4) = *(const float4*)(vb + goff);
        }

        // Load mask tile (segment selection matches K/V concat order)
        {
            const void* mp; int nseg, jloc;
            if (j0 < 1024)      { mp = m1; nseg = 1024; jloc = j0; }
            else if (j0 < 2048) { mp = m2; nseg = 1024; jloc = j0 - 1024; }
            else                { mp = m3; nseg = 2048; jloc = j0 - 2048; }
            int r = tid >> 2, u = tid & 3;
            size_t rowbase = ((size_t)(b * NQ + q0 + r)) * nseg + jloc;
            if (mask_is_byte) {
                *((uint4*)(Ms + r * 64 + u * 16)) =
                    *(const uint4*)((const unsigned char*)mp + rowbase + u * 16);
            } else {
                const int* src = (const int*)mp + rowbase + u * 16;
                unsigned char* dst = Ms + r * 64 + u * 16;
#pragma unroll
                for (int e = 0; e < 16; ++e) dst[e] = (unsigned char)(src[e] != 0);
            }
        }
        __syncthreads();

        // S = Q K^T  (4x4 register tile per thread)
        float s[4][4] = {};
#pragma unroll 8
        for (int d = 0; d < 64; ++d) {
            float4 a4 = *(const float4*)(Qt + d * 64 + ty * 4);
            float4 k4 = *(const float4*)(Kt + d * 64 + tx * 4);
            float ar[4] = {a4.x, a4.y, a4.z, a4.w};
            float kr[4] = {k4.x, k4.y, k4.z, k4.w};
#pragma unroll
            for (int i = 0; i < 4; ++i)
#pragma unroll
                for (int j = 0; j < 4; ++j) s[i][j] += ar[i] * kr[j];
        }

        // mask + scale + online softmax update (rows reduced across 16 lanes)
#pragma unroll
        for (int i = 0; i < 4; ++i) {
            int qr = ty * 4 + i;
            float rm = -1e30f;
            unsigned vbits = 0;
#pragma unroll
            for (int j = 0; j < 4; ++j) {
                bool valid = Ms[qr * 64 + tx * 4 + j] != 0;
                float sv = valid ? s[i][j] * SCALE : -1e30f;
                s[i][j] = sv;
                if (valid) vbits |= (1u << j);
                rm = fmaxf(rm, sv);
            }
#pragma unroll
            for (int off = 8; off; off >>= 1)
                rm = fmaxf(rm, __shfl_xor_sync(0xffffffffu, rm, off, 16));
            float mn = fmaxf(m_i[i], rm);
            float alpha = __expf(m_i[i] - mn);
            float rs = 0.f;
#pragma unroll
            for (int j = 0; j < 4; ++j) {
                float p = (vbits & (1u << j)) ? __expf(s[i][j] - mn) : 0.f;
                s[i][j] = p;
                rs += p;
            }
#pragma unroll
            for (int off = 8; off; off >>= 1)
                rs += __shfl_xor_sync(0xffffffffu, rs, off, 16);
            l_i[i] = l_i[i] * alpha + rs;
            m_i[i] = mn;
#pragma unroll
            for (int j = 0; j < 4; ++j) {
                o[i][j] *= alpha;
                Ps[qr * 65 + tx * 4 + j] = s[i][j];
            }
        }
        __syncthreads();

        // O += P @ V
#pragma unroll 4
        for (int kk = 0; kk < 64; ++kk) {
            float4 v4 = *(const float4*)(Vs + kk * 64 + tx * 4);
            float vr[4] = {v4.x, v4.y, v4.z, v4.w};
#pragma unroll
            for (int i = 0; i < 4; ++i) {
                float p = Ps[(ty * 4 + i) * 65 + kk];
#pragma unroll
                for (int j = 0; j < 4; ++j) o[i][j] += p * vr[j];
            }
        }
    }

    // finalize and write [b, q, h*64 + d]
#pragma unroll
    for (int i = 0; i < 4; ++i) {
        float inv = 1.f / l_i[i];
        int qr = q0 + ty * 4 + i;
        float4 outv = make_float4(o[i][0] * inv, o[i][1] * inv,
                                  o[i][2] * inv, o[i][3] * inv);
        *(float4*)(ob + ((size_t)(b * NQ + qr)) * VD + h * DHEAD + tx * 4) = outv;
    }
}

// ---------------- launcher ----------------
extern "C" void kernel_launch(void* const* d_in, const int* in_sizes, int n_in,
                              void* d_out, int out_size) {
    const float* x        = (const float*)d_in[0];
    const float* context  = (const float*)d_in[1];
    const float* context2 = (const float*)d_in[2];
    const float* context3 = (const float*)d_in[3];
    const void*  mask1    = d_in[4];
    const void*  mask2    = d_in[5];
    const void*  mask3    = d_in[6];
    const float* Wq  = (const float*)d_in[7];
    const float* bq  = (const float*)d_in[8];
    const float* Wk1 = (const float*)d_in[9];
    const float* bk1 = (const float*)d_in[10];
    const float* Wv1 = (const float*)d_in[11];
    const float* bv1 = (const float*)d_in[12];
    const float* Wk2 = (const float*)d_in[13];
    const float* bk2 = (const float*)d_in[14];
    const float* Wv2 = (const float*)d_in[15];
    const float* bv2 = (const float*)d_in[16];
    const float* Wk3 = (const float*)d_in[17];
    const float* bk3 = (const float*)d_in[18];
    const float* Wv3 = (const float*)d_in[19];
    const float* bv3 = (const float*)d_in[20];
    const float* Wo  = (const float*)d_in[21];
    const float* bo  = (const float*)d_in[22];
    float* out = (float*)d_out;

    float *qp, *kp, *vp, *aop;
    cudaGetSymbolAddress((void**)&qp,  g_q);
    cudaGetSymbolAddress((void**)&kp,  g_k);
    cudaGetSymbolAddress((void**)&vp,  g_v);
    cudaGetSymbolAddress((void**)&aop, g_ao);

    static bool once = false;
    static int smem_attn = (3 * 4096 + 64 * 65) * (int)sizeof(float) + 64 * 64;
    if (!once) {
        cudaFuncSetAttribute(attn_kernel, cudaFuncAttributeMaxDynamicSharedMemorySize,
                             smem_attn);
        once = true;
    }

    detect_mask_kernel<<<1, 256>>>((const unsigned char*)mask1);

    dim3 thr(256);
    // Q: [4096,512] @ [512,512]
    gemm_bias_kernel<<<dim3(8, 64), thr>>>(x, Wq, bq, qp, 512, 512, 1024, 0, 1024);
    // K segments -> g_k [B,4096,512] with row offsets {0,1024,2048}
    gemm_bias_kernel<<<dim3(8, 64),  thr>>>(context,  Wk1, bk1, kp, 512, 512, 1024, 0,    4096);
    gemm_bias_kernel<<<dim3(8, 64),  thr>>>(context2, Wk2, bk2, kp, 768, 512, 1024, 1024, 4096);
    gemm_bias_kernel<<<dim3(8, 128), thr>>>(context3, Wk3, bk3, kp, 256, 512, 2048, 2048, 4096);
    // V segments -> g_v
    gemm_bias_kernel<<<dim3(8, 64),  thr>>>(context,  Wv1, bv1, vp, 512, 512, 1024, 0,    4096);
    gemm_bias_kernel<<<dim3(8, 64),  thr>>>(context2, Wv2, bv2, vp, 768, 512, 1024, 1024, 4096);
    gemm_bias_kernel<<<dim3(8, 128), thr>>>(context3, Wv3, bv3, vp, 256, 512, 2048, 2048, 4096);

    // attention
    attn_kernel<<<dim3(16, NHEAD, BB), thr, smem_attn>>>(
        qp, kp, vp, mask1, mask2, mask3, aop);

    // output projection -> d_out
    gemm_bias_kernel<<<dim3(8, 64), thr>>>(aop, Wo, bo, out, 512, 512, 1024, 0, 1024);
}

// round 4
// speedup vs baseline: 2.1668x; 2.1653x over previous
#include <cuda_runtime.h>
#include <cstdint>

#define EXP2C 0.1803368801111204f   /* (1/8) * log2(e) */

// ================= scratch =================
__device__ float    g_q[4 * 1024 * 512];
__device__ float    g_k[4 * 4096 * 512];
__device__ float    g_v[4 * 4096 * 512];
__device__ float    g_ao[4 * 1024 * 512];
__device__ uint32_t g_mbits[4 * 1024 * 128];
__device__ int      g_mask_is_byte;

// ================= numeric helpers =================
__device__ __forceinline__ float tf32_rn(float x) {
    return __uint_as_float((__float_as_uint(x) + 0x1000u) & 0xFFFFE000u);
}
__device__ __forceinline__ void tf32_split(float x, float& h, float& l) {
    h = tf32_rn(x);
    l = x - h;            // exact; HW truncates l to tf32 (residual ~2^-23 x)
}
__device__ __forceinline__ float fast_exp2(float y) {
    float z = y + 12582912.0f;
    int n = __float_as_int(z) - 0x4B400000;
    float f = y - (z - 12582912.0f);
    float p = 1.3333558146e-3f;
    p = fmaf(p, f, 9.6181291076e-3f);
    p = fmaf(p, f, 5.5504108664e-2f);
    p = fmaf(p, f, 2.4022650696e-1f);
    p = fmaf(p, f, 6.9314718056e-1f);
    p = fmaf(p, f, 1.0f);
    return __int_as_float(__float_as_int(p) + (n << 23));
}
// m16n8k8 tf32 HMMA, D += A*B
__device__ __forceinline__ void mma8(float* c, const uint32_t* a, const uint32_t* b) {
    asm volatile("mma.sync.aligned.m16n8k8.row.col.f32.tf32.tf32.f32 "
        "{%0,%1,%2,%3},{%4,%5,%6,%7},{%8,%9},{%0,%1,%2,%3};"
        : "+f"(c[0]), "+f"(c[1]), "+f"(c[2]), "+f"(c[3])
        : "r"(a[0]), "r"(a[1]), "r"(a[2]), "r"(a[3]), "r"(b[0]), "r"(b[1]));
}

// ================= mask detect + bit-pack =================
__global__ void detect_mask_kernel(const unsigned char* __restrict__ m) {
    __shared__ int any;
    if (threadIdx.x == 0) any = 0;
    __syncthreads();
    int found = 0;
    for (int i = threadIdx.x; i < 4096; i += blockDim.x)
        if ((i & 3) == 1 && m[i]) found = 1;
    if (found) atomicOr(&any, 1);
    __syncthreads();
    if (threadIdx.x == 0) g_mask_is_byte = any;
}

__global__ void pack_mask_kernel(const void* __restrict__ m1, const void* __restrict__ m2,
                                 const void* __restrict__ m3) {
    int idx = blockIdx.x * blockDim.x + threadIdx.x;
    if (idx >= 4 * 1024 * 128) return;
    int w = idx & 127, q = (idx >> 7) & 1023, b = idx >> 17;
    int k0 = w * 32;
    const void* mp; int nseg, jl;
    if (k0 < 1024)      { mp = m1; nseg = 1024; jl = k0; }
    else if (k0 < 2048) { mp = m2; nseg = 1024; jl = k0 - 1024; }
    else                { mp = m3; nseg = 2048; jl = k0 - 2048; }
    size_t base = (size_t)(b * 1024 + q) * nseg + jl;
    uint32_t bits = 0;
    if (g_mask_is_byte) {
        const uint4* p = (const uint4*)((const unsigned char*)mp + base);
        uint4 a = p[0], c = p[1];
        uint32_t ws[8] = {a.x, a.y, a.z, a.w, c.x, c.y, c.z, c.w};
#pragma unroll
        for (int wi = 0; wi < 8; ++wi)
#pragma unroll
            for (int by = 0; by < 4; ++by)
                if ((ws[wi] >> (8 * by)) & 0xFFu) bits |= 1u << (wi * 4 + by);
    } else {
        const uint4* p = (const uint4*)((const uint32_t*)mp + base);
#pragma unroll
        for (int wi = 0; wi < 8; ++wi) {
            uint4 v = p[wi];
            if (v.x) bits |= 1u << (wi * 4 + 0);
            if (v.y) bits |= 1u << (wi * 4 + 1);
            if (v.z) bits |= 1u << (wi * 4 + 2);
            if (v.w) bits |= 1u << (wi * 4 + 3);
        }
    }
    g_mbits[idx] = bits;
}

// ================= 3xTF32 HMMA GEMM =================
// C[orow,512] = A[M,K]@W[K,512]+bias. Block 128Mx64N, 8 warps (4m x 2n), warp 32x32.
#define SA 36
__global__ __launch_bounds__(256, 2) void gemm_mma(
    const float* __restrict__ A, const float* __restrict__ W,
    const float* __restrict__ bias, float* __restrict__ C,
    int K, int Mb, int rowOff, int bStride)
{
    extern __shared__ float sm[];
    float* Ah = sm;                    // [128][36]
    float* Al = Ah + 128 * SA;
    float* Bh = Al + 128 * SA;         // [64][36]
    float* Bl = Bh + 64 * SA;
    const uint32_t* Ahu = (const uint32_t*)Ah;
    const uint32_t* Alu = (const uint32_t*)Al;
    const uint32_t* Bhu = (const uint32_t*)Bh;
    const uint32_t* Blu = (const uint32_t*)Bl;

    const int tid = threadIdx.x, lane = tid & 31, wid = tid >> 5;
    const int wm = wid & 3, wn = wid >> 2;
    const int lr = lane >> 2, lc = lane & 3;
    const int m0 = blockIdx.y * 128, n0 = blockIdx.x * 64;

    float acc[2][4][4];
#pragma unroll
    for (int i = 0; i < 2; ++i)
#pragma unroll
        for (int j = 0; j < 4; ++j)
#pragma unroll
            for (int e = 0; e < 4; ++e) acc[i][j][e] = 0.f;

    const int nK = K >> 5;
    for (int c = 0; c < nK; ++c) {
        // stage A chunk [128 x 32] hi/lo
        const float* Ab = A + (size_t)m0 * K + c * 32;
#pragma unroll
        for (int it = 0; it < 4; ++it) {
            int id = it * 256 + tid;
            int row = id >> 3, c4 = id & 7;
            float4 v = *(const float4*)(Ab + (size_t)row * K + c4 * 4);
            float4 h, l;
            tf32_split(v.x, h.x, l.x); tf32_split(v.y, h.y, l.y);
            tf32_split(v.z, h.z, l.z); tf32_split(v.w, h.w, l.w);
            *(float4*)(Ah + row * SA + c4 * 4) = h;
            *(float4*)(Al + row * SA + c4 * 4) = l;
        }
        // stage B chunk: W[k][n] -> Bs[n][k], hi/lo
        const float* Wb = W + (size_t)(c * 32) * 512 + n0;
#pragma unroll
        for (int it = 0; it < 8; ++it) {
            int id = it * 256 + tid;
            int k = id >> 6, n = id & 63;
            float x = Wb[(size_t)k * 512 + n];
            float h, l; tf32_split(x, h, l);
            Bh[n * SA + k] = h;
            Bl[n * SA + k] = l;
        }
        __syncthreads();
#pragma unroll
        for (int ks = 0; ks < 4; ++ks) {
            const int kb = ks * 8;
            uint32_t bh[4][2], bl[4][2];
#pragma unroll
            for (int nf = 0; nf < 4; ++nf) {
                int nrow = wn * 32 + nf * 8 + lr;
                bh[nf][0] = Bhu[nrow * SA + kb + lc];
                bh[nf][1] = Bhu[nrow * SA + kb + 4 + lc];
                bl[nf][0] = Blu[nrow * SA + kb + lc];
                bl[nf][1] = Blu[nrow * SA + kb + 4 + lc];
            }
#pragma unroll
            for (int mf = 0; mf < 2; ++mf) {
                int ar = wm * 32 + mf * 16 + lr;
                uint32_t ah[4] = {Ahu[ar * SA + kb + lc], Ahu[(ar + 8) * SA + kb + lc],
                                  Ahu[ar * SA + kb + 4 + lc], Ahu[(ar + 8) * SA + kb + 4 + lc]};
                uint32_t al[4] = {Alu[ar * SA + kb + lc], Alu[(ar + 8) * SA + kb + lc],
                                  Alu[ar * SA + kb + 4 + lc], Alu[(ar + 8) * SA + kb + 4 + lc]};
#pragma unroll
                for (int nf = 0; nf < 4; ++nf) {
                    mma8(acc[mf][nf], ah, bh[nf]);
                    mma8(acc[mf][nf], ah, bl[nf]);
                    mma8(acc[mf][nf], al, bh[nf]);
                }
            }
        }
        __syncthreads();
    }
    // epilogue
#pragma unroll
    for (int mf = 0; mf < 2; ++mf) {
        int r = m0 + wm * 32 + mf * 16 + lr;
        int b0i = r / Mb;
        size_t or0 = (size_t)b0i * bStride + rowOff + (r - b0i * Mb);
        int r2 = r + 8;
        int b1i = r2 / Mb;
        size_t or1 = (size_t)b1i * bStride + rowOff + (r2 - b1i * Mb);
#pragma unroll
        for (int nf = 0; nf < 4; ++nf) {
            int col = n0 + wn * 32 + nf * 8 + 2 * lc;
            float bv0 = bias[col], bv1 = bias[col + 1];
            *(float2*)(C + or0 * 512 + col) =
                make_float2(acc[mf][nf][0] + bv0, acc[mf][nf][1] + bv1);
            *(float2*)(C + or1 * 512 + col) =
                make_float2(acc[mf][nf][2] + bv0, acc[mf][nf][3] + bv1);
        }
    }
}

// ================= HMMA flash attention =================
// Block 256 thr = 8 warps (4m x 2n). Tile 128q x 128k, 32 tiles. O in registers.
#define SQ 68
#define SV 132
__global__ __launch_bounds__(256, 1) void attn_mma(
    const float* __restrict__ qb, const float* __restrict__ kb,
    const float* __restrict__ vb, float* __restrict__ ob)
{
    extern __shared__ float sm[];
    float* sQ  = sm;                    // [128][68]
    float* sK  = sQ + 128 * SQ;         // [128][68]
    float* sVh = sK + 128 * SQ;         // [64][132]
    float* sVl = sVh + 64 * SV;         // [64][132]
    float* sP  = sVl + 64 * SV;         // [128][132]
    uint32_t* sM = (uint32_t*)(sP + 128 * SV);   // [128][4]
    float* sL = (float*)(sM + 512);              // [2][128]
    const uint32_t* sQu = (const uint32_t*)sQ;
    const uint32_t* sKu = (const uint32_t*)sK;
    const uint32_t* sVhu = (const uint32_t*)sVh;
    const uint32_t* sVlu = (const uint32_t*)sVl;
    const uint32_t* sPu = (const uint32_t*)sP;

    const int tid = threadIdx.x, lane = tid & 31, wid = tid >> 5;
    const int wm = wid & 3, wn = wid >> 2;
    const int lr = lane >> 2, lc = lane & 3;
    const int q0 = blockIdx.x * 128, h = blockIdx.y, b = blockIdx.z;

    // stage Q (tf32-rounded)
    const float* Qg = qb + ((size_t)(b * 1024 + q0)) * 512 + h * 64;
#pragma unroll
    for (int it = 0; it < 8; ++it) {
        int id = it * 256 + tid;
        int row = id >> 4, c4 = id & 15;
        float4 v = *(const float4*)(Qg + (size_t)row * 512 + c4 * 4);
        v.x = tf32_rn(v.x); v.y = tf32_rn(v.y); v.z = tf32_rn(v.z); v.w = tf32_rn(v.w);
        *(float4*)(sQ + row * SQ + c4 * 4) = v;
    }

    float o[2][4][4];
    float l_acc[2][2];
#pragma unroll
    for (int i = 0; i < 2; ++i) {
        l_acc[i][0] = 0.f; l_acc[i][1] = 0.f;
#pragma unroll
        for (int j = 0; j < 4; ++j)
#pragma unroll
            for (int e = 0; e < 4; ++e) o[i][j][e] = 0.f;
    }

    const uint32_t* mbase = g_mbits + ((size_t)(b * 1024 + q0)) * 128;

    for (int t = 0; t < 32; ++t) {
        const int j0 = t * 128;
        __syncthreads();   // protect sK/sV/sM from previous tile's readers
        // stage K (rounded)
#pragma unroll
        for (int it = 0; it < 8; ++it) {
            int id = it * 256 + tid;
            int row = id >> 4, c4 = id & 15;
            float4 v = *(const float4*)(kb + (size_t)(b * 4096 + j0 + row) * 512 + h * 64 + c4 * 4);
            v.x = tf32_rn(v.x); v.y = tf32_rn(v.y); v.z = tf32_rn(v.z); v.w = tf32_rn(v.w);
            *(float4*)(sK + row * SQ + c4 * 4) = v;
        }
        // stage V transposed, hi/lo
#pragma unroll
        for (int it = 0; it < 8; ++it) {
            int id = it * 256 + tid;
            int key = id >> 4, d4 = id & 15;
            float4 v = *(const float4*)(vb + (size_t)(b * 4096 + j0 + key) * 512 + h * 64 + d4 * 4);
            float vv[4] = {v.x, v.y, v.z, v.w};
#pragma unroll
            for (int e = 0; e < 4; ++e) {
                float hh, ll; tf32_split(vv[e], hh, ll);
                sVh[(d4 * 4 + e) * SV + key] = hh;
                sVl[(d4 * 4 + e) * SV + key] = ll;
            }
        }
        // stage mask tile
#pragma unroll
        for (int it = 0; it < 2; ++it) {
            int id = it * 256 + tid;
            int row = id >> 2, w = id & 3;
            sM[row * 4 + w] = mbase[(size_t)row * 128 + t * 4 + w];
        }
        __syncthreads();

        // S = Q K^T  (warp: 32q x 64k)
        float s[2][8][4];
#pragma unroll
        for (int i = 0; i < 2; ++i)
#pragma unroll
            for (int j = 0; j < 8; ++j)
#pragma unroll
                for (int e = 0; e < 4; ++e) s[i][j][e] = 0.f;
#pragma unroll
        for (int ks = 0; ks < 8; ++ks) {
            const int kbs = ks * 8;
            uint32_t bk[8][2];
#pragma unroll
            for (int nf = 0; nf < 8; ++nf) {
                int nrow = wn * 64 + nf * 8 + lr;
                bk[nf][0] = sKu[nrow * SQ + kbs + lc];
                bk[nf][1] = sKu[nrow * SQ + kbs + 4 + lc];
            }
#pragma unroll
            for (int mf = 0; mf < 2; ++mf) {
                int ar = wm * 32 + mf * 16 + lr;
                uint32_t aq[4] = {sQu[ar * SQ + kbs + lc], sQu[(ar + 8) * SQ + kbs + lc],
                                  sQu[ar * SQ + kbs + 4 + lc], sQu[(ar + 8) * SQ + kbs + 4 + lc]};
#pragma unroll
                for (int nf = 0; nf < 8; ++nf) mma8(s[mf][nf], aq, bk[nf]);
            }
        }

        // masked exp softmax (no-max) + write P
        uint64_t mk[2][2];
#pragma unroll
        for (int mf = 0; mf < 2; ++mf)
#pragma unroll
            for (int u = 0; u < 2; ++u) {
                int row = wm * 32 + mf * 16 + lr + u * 8;
                uint32_t w0 = sM[row * 4 + wn * 2];
                uint32_t w1 = sM[row * 4 + wn * 2 + 1];
                mk[mf][u] = ((uint64_t)w1 << 32) | w0;
            }
#pragma unroll
        for (int mf = 0; mf < 2; ++mf)
#pragma unroll
            for (int nf = 0; nf < 8; ++nf)
#pragma unroll
                for (int cr = 0; cr < 4; ++cr) {
                    int u = cr >> 1;
                    int cl = nf * 8 + 2 * lc + (cr & 1);
                    float p = tf32_rn(fast_exp2(s[mf][nf][cr] * EXP2C));
                    p = ((mk[mf][u] >> cl) & 1ull) ? p : 0.f;
                    l_acc[mf][u] += p;
                    s[mf][nf][cr] = p;
                }
#pragma unroll
        for (int mf = 0; mf < 2; ++mf)
#pragma unroll
            for (int u = 0; u < 2; ++u) {
                int row = wm * 32 + mf * 16 + lr + u * 8;
#pragma unroll
                for (int nf = 0; nf < 8; ++nf)
                    *(float2*)(sP + row * SV + wn * 64 + nf * 8 + 2 * lc) =
                        make_float2(s[mf][nf][u * 2], s[mf][nf][u * 2 + 1]);
            }
        __syncthreads();

        // O += P @ V  (warp: 32q x 32d), V hi + lo
#pragma unroll
        for (int ks = 0; ks < 16; ++ks) {
            const int kbs = ks * 8;
            uint32_t bh[4][2], bl[4][2];
#pragma unroll
            for (int nf = 0; nf < 4; ++nf) {
                int nrow = wn * 32 + nf * 8 + lr;
                bh[nf][0] = sVhu[nrow * SV + kbs + lc];
                bh[nf][1] = sVhu[nrow * SV + kbs + 4 + lc];
                bl[nf][0] = sVlu[nrow * SV + kbs + lc];
                bl[nf][1] = sVlu[nrow * SV + kbs + 4 + lc];
            }
#pragma unroll
            for (int mf = 0; mf < 2; ++mf) {
                int ar = wm * 32 + mf * 16 + lr;
                uint32_t ap[4] = {sPu[ar * SV + kbs + lc], sPu[(ar + 8) * SV + kbs + lc],
                                  sPu[ar * SV + kbs + 4 + lc], sPu[(ar + 8) * SV + kbs + 4 + lc]};
#pragma unroll
                for (int nf = 0; nf < 4; ++nf) {
                    mma8(o[mf][nf], ap, bh[nf]);
                    mma8(o[mf][nf], ap, bl[nf]);
                }
            }
        }
    }

    // l reduction: quad shuffle, then across the 2 n-warps via SMEM
#pragma unroll
    for (int mf = 0; mf < 2; ++mf)
#pragma unroll
        for (int u = 0; u < 2; ++u) {
            float v = l_acc[mf][u];
            v += __shfl_xor_sync(0xffffffffu, v, 1);
            v += __shfl_xor_sync(0xffffffffu, v, 2);
            l_acc[mf][u] = v;
        }
    __syncthreads();
    if (lc == 0) {
#pragma unroll
        for (int mf = 0; mf < 2; ++mf)
#pragma unroll
            for (int u = 0; u < 2; ++u) {
                int row = wm * 32 + mf * 16 + lr + u * 8;
                sL[wn * 128 + row] = l_acc[mf][u];
            }
    }
    __syncthreads();

    // normalize + store
    float* Og = ob + ((size_t)(b * 1024 + q0)) * 512 + h * 64;
#pragma unroll
    for (int mf = 0; mf < 2; ++mf)
#pragma unroll
        for (int u = 0; u < 2; ++u) {
            int row = wm * 32 + mf * 16 + lr + u * 8;
            float linv = 1.f / (sL[row] + sL[128 + row]);
#pragma unroll
            for (int nf = 0; nf < 4; ++nf) {
                int col = wn * 32 + nf * 8 + 2 * lc;
                *(float2*)(Og + (size_t)row * 512 + col) =
                    make_float2(o[mf][nf][u * 2] * linv, o[mf][nf][u * 2 + 1] * linv);
            }
        }
}

// ================= launcher =================
extern "C" void kernel_launch(void* const* d_in, const int* in_sizes, int n_in,
                              void* d_out, int out_size) {
    const float* x        = (const float*)d_in[0];
    const float* context  = (const float*)d_in[1];
    const float* context2 = (const float*)d_in[2];
    const float* context3 = (const float*)d_in[3];
    const void*  mask1 = d_in[4];
    const void*  mask2 = d_in[5];
    const void*  mask3 = d_in[6];
    const float* Wq  = (const float*)d_in[7];
    const float* bq  = (const float*)d_in[8];
    const float* Wk1 = (const float*)d_in[9];
    const float* bk1 = (const float*)d_in[10];
    const float* Wv1 = (const float*)d_in[11];
    const float* bv1 = (const float*)d_in[12];
    const float* Wk2 = (const float*)d_in[13];
    const float* bk2 = (const float*)d_in[14];
    const float* Wv2 = (const float*)d_in[15];
    const float* bv2 = (const float*)d_in[16];
    const float* Wk3 = (const float*)d_in[17];
    const float* bk3 = (const float*)d_in[18];
    const float* Wv3 = (const float*)d_in[19];
    const float* bv3 = (const float*)d_in[20];
    const float* Wo  = (const float*)d_in[21];
    const float* bo  = (const float*)d_in[22];
    float* out = (float*)d_out;

    float *qp, *kp, *vp, *aop;
    cudaGetSymbolAddress((void**)&qp,  g_q);
    cudaGetSymbolAddress((void**)&kp,  g_k);
    cudaGetSymbolAddress((void**)&vp,  g_v);
    cudaGetSymbolAddress((void**)&aop, g_ao);

    const int smem_gemm = (128 * SA * 2 + 64 * SA * 2) * 4;            // 55296
    const int smem_attn = (128 * SQ * 2 + 64 * SV * 2 + 128 * SV) * 4 + 2048 + 1024;
    static bool once = false;
    if (!once) {
        cudaFuncSetAttribute(gemm_mma, cudaFuncAttributeMaxDynamicSharedMemorySize, smem_gemm);
        cudaFuncSetAttribute(attn_mma, cudaFuncAttributeMaxDynamicSharedMemorySize, smem_attn);
        once = true;
    }

    detect_mask_kernel<<<1, 256>>>((const unsigned char*)mask1);
    pack_mask_kernel<<<2048, 256>>>(mask1, mask2, mask3);

    dim3 thr(256);
    gemm_mma<<<dim3(8, 32), thr, smem_gemm>>>(x,        Wq,  bq,  qp, 512, 1024, 0,    1024);
    gemm_mma<<<dim3(8, 32), thr, smem_gemm>>>(context,  Wk1, bk1, kp, 512, 1024, 0,    4096);
    gemm_mma<<<dim3(8, 32), thr, smem_gemm>>>(context2, Wk2, bk2, kp, 768, 1024, 1024, 4096);
    gemm_mma<<<dim3(8, 64), thr, smem_gemm>>>(context3, Wk3, bk3, kp, 256, 2048, 2048, 4096);
    gemm_mma<<<dim3(8, 32), thr, smem_gemm>>>(context,  Wv1, bv1, vp, 512, 1024, 0,    4096);
    gemm_mma<<<dim3(8, 32), thr, smem_gemm>>>(context2, Wv2, bv2, vp, 768, 1024, 1024, 4096);
    gemm_mma<<<dim3(8, 64), thr, smem_gemm>>>(context3, Wv3, bv3, vp, 256, 2048, 2048, 4096);

    attn_mma<<<dim3(8, 8, 4), thr, smem_attn>>>(qp, kp, vp, aop);

    gemm_mma<<<dim3(8, 32), thr, smem_gemm>>>(aop, Wo, bo, out, 512, 1024, 0, 1024);
}

// round 5
// speedup vs baseline: 2.9473x; 1.3602x over previous
#include <cuda_runtime.h>
#include <cstdint>

#define EXP2C 0.1803368801111204f   /* (1/8) * log2(e) */

// ================= scratch =================
__device__ float    g_q[4 * 1024 * 512];
__device__ float    g_k[4 * 4096 * 512];
__device__ float    g_v[4 * 4096 * 512];
__device__ float    g_ao[4 * 1024 * 512];
__device__ uint32_t g_mbits[4 * 1024 * 128];
__device__ int      g_mask_is_byte;

// ================= helpers =================
__device__ __forceinline__ uint32_t smem_u32(const void* p) {
    uint32_t a;
    asm("{ .reg .u64 t; cvta.to.shared.u64 t, %1; cvt.u32.u64 %0, t; }" : "=r"(a) : "l"(p));
    return a;
}
#define CP16(dst, src) \
    asm volatile("cp.async.cg.shared.global [%0], [%1], 16;" :: "r"(dst), "l"(src))
#define CP_COMMIT() asm volatile("cp.async.commit_group;" ::: "memory")
#define CP_WAIT(n)  asm volatile("cp.async.wait_group %0;" :: "n"(n) : "memory")

__device__ __forceinline__ float tf32_rn(float x) {
    return __uint_as_float((__float_as_uint(x) + 0x1000u) & 0xFFFFE000u);
}
__device__ __forceinline__ float fast_exp2(float y) {
    float z = y + 12582912.0f;
    int n = __float_as_int(z) - 0x4B400000;
    float f = y - (z - 12582912.0f);
    float p = 1.3333558146e-3f;
    p = fmaf(p, f, 9.6181291076e-3f);
    p = fmaf(p, f, 5.5504108664e-2f);
    p = fmaf(p, f, 2.4022650696e-1f);
    p = fmaf(p, f, 6.9314718056e-1f);
    p = fmaf(p, f, 1.0f);
    return __int_as_float(__float_as_int(p) + (n << 23));
}
__device__ __forceinline__ void mma8(float* c, const uint32_t* a, const uint32_t* b) {
    asm volatile("mma.sync.aligned.m16n8k8.row.col.f32.tf32.tf32.f32 "
        "{%0,%1,%2,%3},{%4,%5,%6,%7},{%8,%9},{%0,%1,%2,%3};"
        : "+f"(c[0]), "+f"(c[1]), "+f"(c[2]), "+f"(c[3])
        : "r"(a[0]), "r"(a[1]), "r"(a[2]), "r"(a[3]), "r"(b[0]), "r"(b[1]));
}

// ================= mask detect + bit-pack =================
__global__ void detect_mask_kernel(const unsigned char* __restrict__ m) {
    __shared__ int any;
    if (threadIdx.x == 0) any = 0;
    __syncthreads();
    int found = 0;
    for (int i = threadIdx.x; i < 4096; i += blockDim.x)
        if ((i & 3) == 1 && m[i]) found = 1;
    if (found) atomicOr(&any, 1);
    __syncthreads();
    if (threadIdx.x == 0) g_mask_is_byte = any;
}

__global__ void pack_mask_kernel(const void* __restrict__ m1, const void* __restrict__ m2,
                                 const void* __restrict__ m3) {
    int idx = blockIdx.x * blockDim.x + threadIdx.x;
    if (idx >= 4 * 1024 * 128) return;
    int w = idx & 127, q = (idx >> 7) & 1023, b = idx >> 17;
    int k0 = w * 32;
    const void* mp; int nseg, jl;
    if (k0 < 1024)      { mp = m1; nseg = 1024; jl = k0; }
    else if (k0 < 2048) { mp = m2; nseg = 1024; jl = k0 - 1024; }
    else                { mp = m3; nseg = 2048; jl = k0 - 2048; }
    size_t base = (size_t)(b * 1024 + q) * nseg + jl;
    uint32_t bits = 0;
    if (g_mask_is_byte) {
        const uint4* p = (const uint4*)((const unsigned char*)mp + base);
        uint4 a = p[0], c = p[1];
        uint32_t ws[8] = {a.x, a.y, a.z, a.w, c.x, c.y, c.z, c.w};
#pragma unroll
        for (int wi = 0; wi < 8; ++wi)
#pragma unroll
            for (int by = 0; by < 4; ++by)
                if ((ws[wi] >> (8 * by)) & 0xFFu) bits |= 1u << (wi * 4 + by);
    } else {
        const uint4* p = (const uint4*)((const uint32_t*)mp + base);
#pragma unroll
        for (int wi = 0; wi < 8; ++wi) {
            uint4 v = p[wi];
            if (v.x) bits |= 1u << (wi * 4 + 0);
            if (v.y) bits |= 1u << (wi * 4 + 1);
            if (v.z) bits |= 1u << (wi * 4 + 2);
            if (v.w) bits |= 1u << (wi * 4 + 3);
        }
    }
    g_mbits[idx] = bits;
}

// ================= 3xTF32 HMMA GEMM, cp.async 2-stage =================
// C[orow,512] = A[M,K]@W[K,512]+bias. Block 128Mx64N, 8 warps (4m x 2n).
// SMEM raw; hi/lo split at fragment load. rnd=1 => store tf32-rounded output.
#define GA 36
#define GB 68
__global__ __launch_bounds__(256, 2) void gemm_mma(
    const float* __restrict__ A, const float* __restrict__ W,
    const float* __restrict__ bias, float* __restrict__ C,
    int K, int Mb, int rowOff, int bStride, int rnd)
{
    extern __shared__ float sm[];
    float* AsB = sm;                    // 2 x [128][GA]
    float* BsB = sm + 2 * 128 * GA;     // 2 x [32][GB]

    const int tid = threadIdx.x, lane = tid & 31, wid = tid >> 5;
    const int wm = wid & 3, wn = wid >> 2;
    const int lr = lane >> 2, lc = lane & 3;
    const int m0 = blockIdx.y * 128, n0 = blockIdx.x * 64;

    float acc[2][4][4];
#pragma unroll
    for (int i = 0; i < 2; ++i)
#pragma unroll
        for (int j = 0; j < 4; ++j)
#pragma unroll
            for (int e = 0; e < 4; ++e) acc[i][j][e] = 0.f;

    const int nK = K >> 5;
    const uint32_t dA[2] = {smem_u32(AsB), smem_u32(AsB + 128 * GA)};
    const uint32_t dB[2] = {smem_u32(BsB), smem_u32(BsB + 32 * GB)};

#define STAGE(c, s) do { \
    const float* Ab_ = A + (size_t)m0 * K + (c) * 32; \
    _Pragma("unroll") \
    for (int it = 0; it < 4; ++it) { \
        int id = it * 256 + tid, row = id >> 3, seg = id & 7; \
        CP16(dA[s] + (row * GA + seg * 4) * 4, Ab_ + (size_t)row * K + seg * 4); \
    } \
    const float* Wb_ = W + (size_t)((c) * 32) * 512 + n0; \
    _Pragma("unroll") \
    for (int it = 0; it < 2; ++it) { \
        int id = it * 256 + tid, row = id >> 4, seg = id & 15; \
        CP16(dB[s] + (row * GB + seg * 4) * 4, Wb_ + (size_t)row * 512 + seg * 4); \
    } \
    CP_COMMIT(); \
} while (0)

    STAGE(0, 0);
    for (int c = 0; c < nK; ++c) {
        const int s = c & 1;
        if (c + 1 < nK) { STAGE(c + 1, s ^ 1); CP_WAIT(1); }
        else            { CP_WAIT(0); }
        __syncthreads();
        const float* As = AsB + s * 128 * GA;
        const float* Bs = BsB + s * 32 * GB;
#pragma unroll
        for (int ks = 0; ks < 4; ++ks) {
            const int kb = ks * 8;
            uint32_t bh[4][2], bl[4][2];
#pragma unroll
            for (int nf = 0; nf < 4; ++nf) {
                int nrow = wn * 32 + nf * 8 + lr;
                float x0 = Bs[(kb + lc) * GB + nrow];
                float x1 = Bs[(kb + 4 + lc) * GB + nrow];
                float h0 = tf32_rn(x0), h1 = tf32_rn(x1);
                bh[nf][0] = __float_as_uint(h0); bh[nf][1] = __float_as_uint(h1);
                bl[nf][0] = __float_as_uint(x0 - h0); bl[nf][1] = __float_as_uint(x1 - h1);
            }
#pragma unroll
            for (int mf = 0; mf < 2; ++mf) {
                int ar = wm * 32 + mf * 16 + lr;
                float a0 = As[ar * GA + kb + lc];
                float a1 = As[(ar + 8) * GA + kb + lc];
                float a2 = As[ar * GA + kb + 4 + lc];
                float a3 = As[(ar + 8) * GA + kb + 4 + lc];
                float h0 = tf32_rn(a0), h1 = tf32_rn(a1), h2 = tf32_rn(a2), h3 = tf32_rn(a3);
                uint32_t ah[4] = {__float_as_uint(h0), __float_as_uint(h1),
                                  __float_as_uint(h2), __float_as_uint(h3)};
                uint32_t al[4] = {__float_as_uint(a0 - h0), __float_as_uint(a1 - h1),
                                  __float_as_uint(a2 - h2), __float_as_uint(a3 - h3)};
#pragma unroll
                for (int nf = 0; nf < 4; ++nf) {
                    mma8(acc[mf][nf], ah, bh[nf]);
                    mma8(acc[mf][nf], ah, bl[nf]);
                    mma8(acc[mf][nf], al, bh[nf]);
                }
            }
        }
        __syncthreads();
    }
#undef STAGE
    // epilogue
#pragma unroll
    for (int mf = 0; mf < 2; ++mf) {
        int r = m0 + wm * 32 + mf * 16 + lr;
        int b0i = r / Mb;
        size_t or0 = (size_t)b0i * bStride + rowOff + (r - b0i * Mb);
        int r2 = r + 8;
        int b1i = r2 / Mb;
        size_t or1 = (size_t)b1i * bStride + rowOff + (r2 - b1i * Mb);
#pragma unroll
        for (int nf = 0; nf < 4; ++nf) {
            int col = n0 + wn * 32 + nf * 8 + 2 * lc;
            float bv0 = bias[col], bv1 = bias[col + 1];
            float v00 = acc[mf][nf][0] + bv0, v01 = acc[mf][nf][1] + bv1;
            float v10 = acc[mf][nf][2] + bv0, v11 = acc[mf][nf][3] + bv1;
            if (rnd) { v00 = tf32_rn(v00); v01 = tf32_rn(v01); v10 = tf32_rn(v10); v11 = tf32_rn(v11); }
            *(float2*)(C + or0 * 512 + col) = make_float2(v00, v01);
            *(float2*)(C + or1 * 512 + col) = make_float2(v10, v11);
        }
    }
}

// ================= HMMA flash attention, 512 threads =================
// 16 warps (4m x 4n). Tile 128q x 128k, 32 tiles. Inputs pre-rounded tf32.
#define SQ 68
#define SVt 133
#define SP 132
// smem float offsets
#define OF_Q  0
#define OF_K  (128 * SQ)
#define OF_V  (2 * 128 * SQ)
#define OF_P  (OF_V + 2 * 64 * SVt)
#define OF_M  (OF_P + 128 * SP)
#define OF_L  (OF_M + 512)
#define ATTN_SMEM_FLOATS (OF_L + 512)

__global__ __launch_bounds__(512, 1) void attn_mma(
    const float* __restrict__ qb, const float* __restrict__ kb,
    const float* __restrict__ vb, float* __restrict__ ob)
{
    extern __shared__ float sm[];
    float* sQ = sm + OF_Q;
    float* sK = sm + OF_K;
    float* sV = sm + OF_V;           // 2 x [64][SVt]
    float* sP = sm + OF_P;
    uint32_t* sM = (uint32_t*)(sm + OF_M);
    float* sL = sm + OF_L;
    const uint32_t* sQu = (const uint32_t*)sQ;
    const uint32_t* sKu = (const uint32_t*)sK;
    const uint32_t* sPu = (const uint32_t*)sP;

    const int tid = threadIdx.x, lane = tid & 31, wid = tid >> 5;
    const int wm = wid & 3, wn = wid >> 2;
    const int lr = lane >> 2, lc = lane & 3;
    const int q0 = blockIdx.x * 128, h = blockIdx.y, b = blockIdx.z;

    const float* Qg = qb + ((size_t)(b * 1024 + q0)) * 512 + h * 64;
    const float* Kg = kb + ((size_t)(b * 4096)) * 512 + h * 64;
    const float* Vg = vb + ((size_t)(b * 4096)) * 512 + h * 64;
    const uint32_t* mbase = g_mbits + ((size_t)(b * 1024 + q0)) * 128;
    const uint32_t uQ = smem_u32(sQ), uK = smem_u32(sK), uM = smem_u32(sM);

    // ---- prologue: cp.async Q, K(0), M(0); LDG V(0) ----
#pragma unroll
    for (int it = 0; it < 4; ++it) {
        int id = it * 512 + tid, row = id >> 4, seg = id & 15;
        CP16(uQ + (row * SQ + seg * 4) * 4, Qg + (size_t)row * 512 + seg * 4);
        CP16(uK + (row * SQ + seg * 4) * 4, Kg + (size_t)row * 512 + seg * 4);
    }
    if (tid < 128) CP16(uM + tid * 16, mbase + (size_t)tid * 128);
    CP_COMMIT();

    float4 vreg[4];
    int vkey[4], vd4[4];
#pragma unroll
    for (int it = 0; it < 4; ++it) {
        int id = it * 512 + tid;
        vkey[it] = id >> 4; vd4[it] = id & 15;
        vreg[it] = *(const float4*)(Vg + (size_t)vkey[it] * 512 + vd4[it] * 4);
    }
    CP_WAIT(0);
    __syncthreads();
    // store V(0) into buffer 0 (transposed)
#pragma unroll
    for (int it = 0; it < 4; ++it) {
        float vv[4] = {vreg[it].x, vreg[it].y, vreg[it].z, vreg[it].w};
#pragma unroll
        for (int e = 0; e < 4; ++e)
            sV[(vd4[it] * 4 + e) * SVt + vkey[it]] = vv[e];
    }

    float o[2][2][4];
    float l_acc[2][2];
#pragma unroll
    for (int i = 0; i < 2; ++i) {
        l_acc[i][0] = 0.f; l_acc[i][1] = 0.f;
#pragma unroll
        for (int j = 0; j < 2; ++j)
#pragma unroll
            for (int e = 0; e < 4; ++e) o[i][j][e] = 0.f;
    }

    for (int t = 0; t < 32; ++t) {
        const int vbuf = t & 1;
        // prefetch V(t+1) into regs
        if (t < 31) {
            const float* Vn = Vg + (size_t)(t + 1) * 128 * 512;
#pragma unroll
            for (int it = 0; it < 4; ++it)
                vreg[it] = *(const float4*)(Vn + (size_t)vkey[it] * 512 + vd4[it] * 4);
        }

        // ---- S = Q K^T (warp: 32q x 32k) ----
        float s[2][4][4];
#pragma unroll
        for (int i = 0; i < 2; ++i)
#pragma unroll
            for (int j = 0; j < 4; ++j)
#pragma unroll
                for (int e = 0; e < 4; ++e) s[i][j][e] = 0.f;
#pragma unroll
        for (int ks = 0; ks < 8; ++ks) {
            const int kbs = ks * 8;
            uint32_t bk[4][2];
#pragma unroll
            for (int nf = 0; nf < 4; ++nf) {
                int nrow = wn * 32 + nf * 8 + lr;
                bk[nf][0] = sKu[nrow * SQ + kbs + lc];
                bk[nf][1] = sKu[nrow * SQ + kbs + 4 + lc];
            }
#pragma unroll
            for (int mf = 0; mf < 2; ++mf) {
                int ar = wm * 32 + mf * 16 + lr;
                uint32_t aq[4] = {sQu[ar * SQ + kbs + lc], sQu[(ar + 8) * SQ + kbs + lc],
                                  sQu[ar * SQ + kbs + 4 + lc], sQu[(ar + 8) * SQ + kbs + 4 + lc]};
#pragma unroll
                for (int nf = 0; nf < 4; ++nf) mma8(s[mf][nf], aq, bk[nf]);
            }
        }

        // ---- masked no-max softmax + P write ----
#pragma unroll
        for (int mf = 0; mf < 2; ++mf)
#pragma unroll
            for (int u = 0; u < 2; ++u) {
                int row = wm * 32 + mf * 16 + lr + u * 8;
                uint32_t mw = sM[row * 4 + wn];
                float rs = 0.f;
#pragma unroll
                for (int nf = 0; nf < 4; ++nf) {
#pragma unroll
                    for (int q2 = 0; q2 < 2; ++q2) {
                        int cr = u * 2 + q2;
                        int cl = nf * 8 + 2 * lc + q2;
                        float p = tf32_rn(fast_exp2(s[mf][nf][cr] * EXP2C));
                        p = ((mw >> cl) & 1u) ? p : 0.f;
                        rs += p;
                        s[mf][nf][cr] = p;
                    }
                }
                l_acc[mf][u] += rs;
#pragma unroll
                for (int nf = 0; nf < 4; ++nf)
                    *(float2*)(sP + row * SP + wn * 32 + nf * 8 + 2 * lc) =
                        make_float2(s[mf][nf][u * 2], s[mf][nf][u * 2 + 1]);
            }
        __syncthreads();   // P complete; all warps done reading sK, sM

        // stage K(t+1), M(t+1) via cp.async; V(t+1) regs -> other buffer
        if (t < 31) {
            const float* Kn = Kg + (size_t)(t + 1) * 128 * 512;
#pragma unroll
            for (int it = 0; it < 4; ++it) {
                int id = it * 512 + tid, row = id >> 4, seg = id & 15;
                CP16(uK + (row * SQ + seg * 4) * 4, Kn + (size_t)row * 512 + seg * 4);
            }
            if (tid < 128) CP16(uM + tid * 16, mbase + (size_t)tid * 128 + (t + 1) * 4);
            CP_COMMIT();
            float* sVn = sV + (vbuf ^ 1) * 64 * SVt;
#pragma unroll
            for (int it = 0; it < 4; ++it) {
                float vv[4] = {vreg[it].x, vreg[it].y, vreg[it].z, vreg[it].w};
#pragma unroll
                for (int e = 0; e < 4; ++e)
                    sVn[(vd4[it] * 4 + e) * SVt + vkey[it]] = vv[e];
            }
        }

        // ---- O += P @ V (warp: 32q x 16d) ----
        const uint32_t* sVu = (const uint32_t*)(sV + vbuf * 64 * SVt);
#pragma unroll
        for (int ks = 0; ks < 16; ++ks) {
            const int kbs = ks * 8;
            uint32_t bv[2][2];
#pragma unroll
            for (int nf = 0; nf < 2; ++nf) {
                int drow = wn * 16 + nf * 8 + lr;
                bv[nf][0] = sVu[drow * SVt + kbs + lc];
                bv[nf][1] = sVu[drow * SVt + kbs + 4 + lc];
            }
#pragma unroll
            for (int mf = 0; mf < 2; ++mf) {
                int ar = wm * 32 + mf * 16 + lr;
                uint32_t ap[4] = {sPu[ar * SP + kbs + lc], sPu[(ar + 8) * SP + kbs + lc],
                                  sPu[ar * SP + kbs + 4 + lc], sPu[(ar + 8) * SP + kbs + 4 + lc]};
#pragma unroll
                for (int nf = 0; nf < 2; ++nf) mma8(o[mf][nf], ap, bv[nf]);
            }
        }
        CP_WAIT(0);
        __syncthreads();   // K/M next visible; P safe to overwrite
    }

    // ---- l reduction across quads + 4 n-warps ----
#pragma unroll
    for (int mf = 0; mf < 2; ++mf)
#pragma unroll
        for (int u = 0; u < 2; ++u) {
            float v = l_acc[mf][u];
            v += __shfl_xor_sync(0xffffffffu, v, 1);
            v += __shfl_xor_sync(0xffffffffu, v, 2);
            l_acc[mf][u] = v;
        }
    if (lc == 0) {
#pragma unroll
        for (int mf = 0; mf < 2; ++mf)
#pragma unroll
            for (int u = 0; u < 2; ++u) {
                int row = wm * 32 + mf * 16 + lr + u * 8;
                sL[wn * 128 + row] = l_acc[mf][u];
            }
    }
    __syncthreads();

    float* Og = ob + ((size_t)(b * 1024 + q0)) * 512 + h * 64;
#pragma unroll
    for (int mf = 0; mf < 2; ++mf)
#pragma unroll
        for (int u = 0; u < 2; ++u) {
            int row = wm * 32 + mf * 16 + lr + u * 8;
            float linv = 1.f / (sL[row] + sL[128 + row] + sL[256 + row] + sL[384 + row]);
#pragma unroll
            for (int nf = 0; nf < 2; ++nf) {
                int col = wn * 16 + nf * 8 + 2 * lc;
                *(float2*)(Og + (size_t)row * 512 + col) =
                    make_float2(o[mf][nf][u * 2] * linv, o[mf][nf][u * 2 + 1] * linv);
            }
        }
}

// ================= launcher =================
extern "C" void kernel_launch(void* const* d_in, const int* in_sizes, int n_in,
                              void* d_out, int out_size) {
    const float* x        = (const float*)d_in[0];
    const float* context  = (const float*)d_in[1];
    const float* context2 = (const float*)d_in[2];
    const float* context3 = (const float*)d_in[3];
    const void*  mask1 = d_in[4];
    const void*  mask2 = d_in[5];
    const void*  mask3 = d_in[6];
    const float* Wq  = (const float*)d_in[7];
    const float* bq  = (const float*)d_in[8];
    const float* Wk1 = (const float*)d_in[9];
    const float* bk1 = (const float*)d_in[10];
    const float* Wv1 = (const float*)d_in[11];
    const float* bv1 = (const float*)d_in[12];
    const float* Wk2 = (const float*)d_in[13];
    const float* bk2 = (const float*)d_in[14];
    const float* Wv2 = (const float*)d_in[15];
    const float* bv2 = (const float*)d_in[16];
    const float* Wk3 = (const float*)d_in[17];
    const float* bk3 = (const float*)d_in[18];
    const float* Wv3 = (const float*)d_in[19];
    const float* bv3 = (const float*)d_in[20];
    const float* Wo  = (const float*)d_in[21];
    const float* bo  = (const float*)d_in[22];
    float* out = (float*)d_out;

    float *qp, *kp, *vp, *aop;
    cudaGetSymbolAddress((void**)&qp,  g_q);
    cudaGetSymbolAddress((void**)&kp,  g_k);
    cudaGetSymbolAddress((void**)&vp,  g_v);
    cudaGetSymbolAddress((void**)&aop, g_ao);

    const int smem_gemm = 2 * (128 * GA + 32 * GB) * 4;
    const int smem_attn = ATTN_SMEM_FLOATS * 4;
    static bool once = false;
    if (!once) {
        cudaFuncSetAttribute(gemm_mma, cudaFuncAttributeMaxDynamicSharedMemorySize, smem_gemm);
        cudaFuncSetAttribute(attn_mma, cudaFuncAttributeMaxDynamicSharedMemorySize, smem_attn);
        once = true;
    }

    detect_mask_kernel<<<1, 256>>>((const unsigned char*)mask1);
    pack_mask_kernel<<<2048, 256>>>(mask1, mask2, mask3);

    dim3 thr(256);
    gemm_mma<<<dim3(8, 32), thr, smem_gemm>>>(x,        Wq,  bq,  qp, 512, 1024, 0,    1024, 1);
    gemm_mma<<<dim3(8, 32), thr, smem_gemm>>>(context,  Wk1, bk1, kp, 512, 1024, 0,    4096, 1);
    gemm_mma<<<dim3(8, 32), thr, smem_gemm>>>(context2, Wk2, bk2, kp, 768, 1024, 1024, 4096, 1);
    gemm_mma<<<dim3(8, 64), thr, smem_gemm>>>(context3, Wk3, bk3, kp, 256, 2048, 2048, 4096, 1);
    gemm_mma<<<dim3(8, 32), thr, smem_gemm>>>(context,  Wv1, bv1, vp, 512, 1024, 0,    4096, 1);
    gemm_mma<<<dim3(8, 32), thr, smem_gemm>>>(context2, Wv2, bv2, vp, 768, 1024, 1024, 4096, 1);
    gemm_mma<<<dim3(8, 64), thr, smem_gemm>>>(context3, Wv3, bv3, vp, 256, 2048, 2048, 4096, 1);

    attn_mma<<<dim3(8, 8, 4), dim3(512), smem_attn>>>(qp, kp, vp, aop);

    gemm_mma<<<dim3(8, 32), thr, smem_gemm>>>(aop, Wo, bo, out, 512, 1024, 0, 1024, 0);
}

// round 6
// speedup vs baseline: 3.0486x; 1.0344x over previous
#include <cuda_runtime.h>
#include <cstdint>

#define EXP2C 0.1803368801111204f   /* (1/8) * log2(e) */

// ================= scratch =================
__device__ float    g_q[4 * 1024 * 512];
__device__ float    g_k[4 * 4096 * 512];
__device__ float    g_v[4 * 4096 * 512];
__device__ float    g_ao[4 * 1024 * 512];
__device__ uint32_t g_mbits[4 * 1024 * 128];
__device__ int      g_mask_is_byte;

// ================= helpers =================
__device__ __forceinline__ uint32_t smem_u32(const void* p) {
    uint32_t a;
    asm("{ .reg .u64 t; cvta.to.shared.u64 t, %1; cvt.u32.u64 %0, t; }" : "=r"(a) : "l"(p));
    return a;
}
#define CP16(dst, src) \
    asm volatile("cp.async.cg.shared.global [%0], [%1], 16;" :: "r"(dst), "l"(src))
#define CP8(dst, src) \
    asm volatile("cp.async.ca.shared.global [%0], [%1], 8;" :: "r"(dst), "l"(src))
#define CP_COMMIT() asm volatile("cp.async.commit_group;" ::: "memory")
#define CP_WAIT(n)  asm volatile("cp.async.wait_group %0;" :: "n"(n) : "memory")

__device__ __forceinline__ float tf32_rn(float x) {
    return __uint_as_float((__float_as_uint(x) + 0x1000u) & 0xFFFFE000u);
}
__device__ __forceinline__ float fast_exp2(float y) {
    float z = y + 12582912.0f;
    int n = __float_as_int(z) - 0x4B400000;
    float f = y - (z - 12582912.0f);
    float p = 1.3333558146e-3f;
    p = fmaf(p, f, 9.6181291076e-3f);
    p = fmaf(p, f, 5.5504108664e-2f);
    p = fmaf(p, f, 2.4022650696e-1f);
    p = fmaf(p, f, 6.9314718056e-1f);
    p = fmaf(p, f, 1.0f);
    return __int_as_float(__float_as_int(p) + (n << 23));
}
__device__ __forceinline__ void mma8(float* c, const uint32_t* a, const uint32_t* b) {
    asm volatile("mma.sync.aligned.m16n8k8.row.col.f32.tf32.tf32.f32 "
        "{%0,%1,%2,%3},{%4,%5,%6,%7},{%8,%9},{%0,%1,%2,%3};"
        : "+f"(c[0]), "+f"(c[1]), "+f"(c[2]), "+f"(c[3])
        : "r"(a[0]), "r"(a[1]), "r"(a[2]), "r"(a[3]), "r"(b[0]), "r"(b[1]));
}

// ================= mask detect + bit-pack =================
__global__ void detect_mask_kernel(const unsigned char* __restrict__ m) {
    __shared__ int any;
    if (threadIdx.x == 0) any = 0;
    __syncthreads();
    int found = 0;
    for (int i = threadIdx.x; i < 4096; i += blockDim.x)
        if ((i & 3) == 1 && m[i]) found = 1;
    if (found) atomicOr(&any, 1);
    __syncthreads();
    if (threadIdx.x == 0) g_mask_is_byte = any;
}

__global__ void pack_mask_kernel(const void* __restrict__ m1, const void* __restrict__ m2,
                                 const void* __restrict__ m3) {
    int idx = blockIdx.x * blockDim.x + threadIdx.x;
    if (idx >= 4 * 1024 * 128) return;
    int w = idx & 127, q = (idx >> 7) & 1023, b = idx >> 17;
    int k0 = w * 32;
    const void* mp; int nseg, jl;
    if (k0 < 1024)      { mp = m1; nseg = 1024; jl = k0; }
    else if (k0 < 2048) { mp = m2; nseg = 1024; jl = k0 - 1024; }
    else                { mp = m3; nseg = 2048; jl = k0 - 2048; }
    size_t base = (size_t)(b * 1024 + q) * nseg + jl;
    uint32_t bits = 0;
    if (g_mask_is_byte) {
        const uint4* p = (const uint4*)((const unsigned char*)mp + base);
        uint4 a = p[0], c = p[1];
        uint32_t ws[8] = {a.x, a.y, a.z, a.w, c.x, c.y, c.z, c.w};
#pragma unroll
        for (int wi = 0; wi < 8; ++wi)
#pragma unroll
            for (int by = 0; by < 4; ++by)
                if ((ws[wi] >> (8 * by)) & 0xFFu) bits |= 1u << (wi * 4 + by);
    } else {
        const uint4* p = (const uint4*)((const uint32_t*)mp + base);
#pragma unroll
        for (int wi = 0; wi < 8; ++wi) {
            uint4 v = p[wi];
            if (v.x) bits |= 1u << (wi * 4 + 0);
            if (v.y) bits |= 1u << (wi * 4 + 1);
            if (v.z) bits |= 1u << (wi * 4 + 2);
            if (v.w) bits |= 1u << (wi * 4 + 3);
        }
    }
    g_mbits[idx] = bits;
}

// ================= 3xTF32 HMMA GEMM, k-chunk 64, cp.async 2-stage =================
// C[orow,512] = A[M,K]@W[K,512]+bias. Block 128Mx64N, 8 warps (4m x 2n).
#define GA 68
#define GB 72
__global__ __launch_bounds__(256, 2) void gemm_mma(
    const float* __restrict__ A, const float* __restrict__ W,
    const float* __restrict__ bias, float* __restrict__ C,
    int K, int Mb, int rowOff, int bStride, int rnd)
{
    extern __shared__ float sm[];
    float* AsB = sm;                    // 2 x [128][GA]
    float* BsB = sm + 2 * 128 * GA;     // 2 x [64][GB]

    const int tid = threadIdx.x, lane = tid & 31, wid = tid >> 5;
    const int wm = wid & 3, wn = wid >> 2;
    const int lr = lane >> 2, lc = lane & 3;
    const int m0 = blockIdx.y * 128, n0 = blockIdx.x * 64;

    float acc[2][4][4];
#pragma unroll
    for (int i = 0; i < 2; ++i)
#pragma unroll
        for (int j = 0; j < 4; ++j)
#pragma unroll
            for (int e = 0; e < 4; ++e) acc[i][j][e] = 0.f;

    const int nK = K >> 6;
    const uint32_t dA[2] = {smem_u32(AsB), smem_u32(AsB + 128 * GA)};
    const uint32_t dB[2] = {smem_u32(BsB), smem_u32(BsB + 64 * GB)};

#define STAGE(c, s) do { \
    const float* Ab_ = A + (size_t)m0 * K + (c) * 64; \
    _Pragma("unroll") \
    for (int it = 0; it < 8; ++it) { \
        int id = it * 256 + tid, row = id >> 4, seg = id & 15; \
        CP16(dA[s] + (row * GA + seg * 4) * 4, Ab_ + (size_t)row * K + seg * 4); \
    } \
    const float* Wb_ = W + (size_t)((c) * 64) * 512 + n0; \
    _Pragma("unroll") \
    for (int it = 0; it < 4; ++it) { \
        int id = it * 256 + tid, row = id >> 4, seg = id & 15; \
        CP16(dB[s] + (row * GB + seg * 4) * 4, Wb_ + (size_t)row * 512 + seg * 4); \
    } \
    CP_COMMIT(); \
} while (0)

    STAGE(0, 0);
    for (int c = 0; c < nK; ++c) {
        const int s = c & 1;
        if (c + 1 < nK) { STAGE(c + 1, s ^ 1); CP_WAIT(1); }
        else            { CP_WAIT(0); }
        __syncthreads();
        const float* As = AsB + s * 128 * GA;
        const float* Bs = BsB + s * 64 * GB;
#pragma unroll
        for (int ks = 0; ks < 8; ++ks) {
            const int kb = ks * 8;
            uint32_t bh[4][2], bl[4][2];
#pragma unroll
            for (int nf = 0; nf < 4; ++nf) {
                int nrow = wn * 32 + nf * 8 + lr;
                float x0 = Bs[(kb + lc) * GB + nrow];
                float x1 = Bs[(kb + 4 + lc) * GB + nrow];
                float h0 = tf32_rn(x0), h1 = tf32_rn(x1);
                bh[nf][0] = __float_as_uint(h0); bh[nf][1] = __float_as_uint(h1);
                bl[nf][0] = __float_as_uint(x0 - h0); bl[nf][1] = __float_as_uint(x1 - h1);
            }
#pragma unroll
            for (int mf = 0; mf < 2; ++mf) {
                int ar = wm * 32 + mf * 16 + lr;
                float a0 = As[ar * GA + kb + lc];
                float a1 = As[(ar + 8) * GA + kb + lc];
                float a2 = As[ar * GA + kb + 4 + lc];
                float a3 = As[(ar + 8) * GA + kb + 4 + lc];
                float h0 = tf32_rn(a0), h1 = tf32_rn(a1), h2 = tf32_rn(a2), h3 = tf32_rn(a3);
                uint32_t ah[4] = {__float_as_uint(h0), __float_as_uint(h1),
                                  __float_as_uint(h2), __float_as_uint(h3)};
                uint32_t al[4] = {__float_as_uint(a0 - h0), __float_as_uint(a1 - h1),
                                  __float_as_uint(a2 - h2), __float_as_uint(a3 - h3)};
#pragma unroll
                for (int nf = 0; nf < 4; ++nf) {
                    mma8(acc[mf][nf], ah, bh[nf]);
                    mma8(acc[mf][nf], ah, bl[nf]);
                    mma8(acc[mf][nf], al, bh[nf]);
                }
            }
        }
        __syncthreads();
    }
#undef STAGE
    // epilogue
#pragma unroll
    for (int mf = 0; mf < 2; ++mf) {
        int r = m0 + wm * 32 + mf * 16 + lr;
        int b0i = r / Mb;
        size_t or0 = (size_t)b0i * bStride + rowOff + (r - b0i * Mb);
        int r2 = r + 8;
        int b1i = r2 / Mb;
        size_t or1 = (size_t)b1i * bStride + rowOff + (r2 - b1i * Mb);
#pragma unroll
        for (int nf = 0; nf < 4; ++nf) {
            int col = n0 + wn * 32 + nf * 8 + 2 * lc;
            float bv0 = bias[col], bv1 = bias[col + 1];
            float v00 = acc[mf][nf][0] + bv0, v01 = acc[mf][nf][1] + bv1;
            float v10 = acc[mf][nf][2] + bv0, v11 = acc[mf][nf][3] + bv1;
            if (rnd) { v00 = tf32_rn(v00); v01 = tf32_rn(v01); v10 = tf32_rn(v10); v11 = tf32_rn(v11); }
            *(float2*)(C + or0 * 512 + col) = make_float2(v00, v01);
            *(float2*)(C + or1 * 512 + col) = make_float2(v10, v11);
        }
    }
}

// ================= HMMA flash attention, 64q x 64k tiles, 2 CTAs/SM =================
// 256 threads = 8 warps (4m x 2n). Q frags in registers. K/V/M double-buffered cp.async.
#define AK 68
#define AV 72
#define AP 68
#define AOF_V (2 * 64 * AK)
#define AOF_P (AOF_V + 2 * 64 * AV)
#define AOF_M (AOF_P + 64 * AP)
#define AOF_L (AOF_M + 256)
#define ATTN_FLOATS (AOF_L + 128)

__global__ __launch_bounds__(256, 2) void attn_mma(
    const float* __restrict__ qb, const float* __restrict__ kb,
    const float* __restrict__ vb, float* __restrict__ ob)
{
    extern __shared__ float sm[];
    float* sK = sm;                       // 2 x [64][AK]
    float* sV = sm + AOF_V;               // 2 x [64][AV]
    float* sP = sm + AOF_P;               // [64][AP]  (Q staged here first)
    uint32_t* sM = (uint32_t*)(sm + AOF_M);  // 2 x [64][2]
    float* sL = sm + AOF_L;               // [2][64]

    const int tid = threadIdx.x, lane = tid & 31, wid = tid >> 5;
    const int wm = wid & 3, wn = wid >> 2;
    const int lr = lane >> 2, lc = lane & 3;
    const int q0 = blockIdx.x * 64, h = blockIdx.y, b = blockIdx.z;

    const float* Qg = qb + ((size_t)(b * 1024 + q0)) * 512 + h * 64;
    const float* Kg = kb + ((size_t)(b * 4096)) * 512 + h * 64;
    const float* Vg = vb + ((size_t)(b * 4096)) * 512 + h * 64;
    const uint32_t* mbase = g_mbits + ((size_t)(b * 1024 + q0)) * 128;
    const uint32_t uK = smem_u32(sK), uV = smem_u32(sV);
    const uint32_t uP = smem_u32(sP), uM = smem_u32(sM);

    // ---- prologue: Q -> sP, K(0), V(0), M(0) ----
#pragma unroll
    for (int it = 0; it < 4; ++it) {
        int id = it * 256 + tid, row = id >> 4, seg = id & 15;
        CP16(uP + (row * AP + seg * 4) * 4, Qg + (size_t)row * 512 + seg * 4);
        CP16(uK + (row * AK + seg * 4) * 4, Kg + (size_t)row * 512 + seg * 4);
        CP16(uV + (row * AV + seg * 4) * 4, Vg + (size_t)row * 512 + seg * 4);
    }
    if (tid < 64) CP8(uM + tid * 8, (const char*)(mbase + (size_t)tid * 128));
    CP_COMMIT();
    CP_WAIT(0);
    __syncthreads();

    // Q fragments -> registers (32 regs)
    const uint32_t* sPu = (const uint32_t*)sP;
    const int ar = wm * 16 + lr;
    uint32_t aq[8][4];
#pragma unroll
    for (int ks = 0; ks < 8; ++ks) {
        const int kb0 = ks * 8;
        aq[ks][0] = sPu[ar * AP + kb0 + lc];
        aq[ks][1] = sPu[(ar + 8) * AP + kb0 + lc];
        aq[ks][2] = sPu[ar * AP + kb0 + 4 + lc];
        aq[ks][3] = sPu[(ar + 8) * AP + kb0 + 4 + lc];
    }
    __syncthreads();   // everyone done reading Q before sP becomes P

    float o[4][4];
    float l_acc[2] = {0.f, 0.f};
#pragma unroll
    for (int j = 0; j < 4; ++j)
#pragma unroll
        for (int e = 0; e < 4; ++e) o[j][e] = 0.f;

    for (int t = 0; t < 64; ++t) {
        const int s = t & 1;
        if (t > 0) { CP_WAIT(0); __syncthreads(); }

        // ---- S = Q K^T (warp: 16q x 32k) ----
        const uint32_t* sKu = (const uint32_t*)(sK + s * 64 * AK);
        float sv[4][4];
#pragma unroll
        for (int j = 0; j < 4; ++j)
#pragma unroll
            for (int e = 0; e < 4; ++e) sv[j][e] = 0.f;
#pragma unroll
        for (int ks = 0; ks < 8; ++ks) {
            const int kb0 = ks * 8;
            uint32_t bk[4][2];
#pragma unroll
            for (int nf = 0; nf < 4; ++nf) {
                int nrow = wn * 32 + nf * 8 + lr;
                bk[nf][0] = sKu[nrow * AK + kb0 + lc];
                bk[nf][1] = sKu[nrow * AK + kb0 + 4 + lc];
            }
#pragma unroll
            for (int nf = 0; nf < 4; ++nf) mma8(sv[nf], aq[ks], bk[nf]);
        }

        // ---- masked no-max softmax + P write ----
#pragma unroll
        for (int u = 0; u < 2; ++u) {
            int row = wm * 16 + lr + u * 8;
            uint32_t mw = sM[s * 128 + row * 2 + wn];
            float rs = 0.f;
#pragma unroll
            for (int nf = 0; nf < 4; ++nf) {
#pragma unroll
                for (int q2 = 0; q2 < 2; ++q2) {
                    int cr = u * 2 + q2;
                    int cl = nf * 8 + 2 * lc + q2;
                    float p = tf32_rn(fast_exp2(sv[nf][cr] * EXP2C));
                    p = ((mw >> cl) & 1u) ? p : 0.f;
                    rs += p;
                    sv[nf][cr] = p;
                }
            }
            l_acc[u] += rs;
#pragma unroll
            for (int nf = 0; nf < 4; ++nf)
                *(float2*)(sP + row * AP + wn * 32 + nf * 8 + 2 * lc) =
                    make_float2(sv[nf][u * 2], sv[nf][u * 2 + 1]);
        }
        __syncthreads();   // P visible; sK[s], sM[s] free

        // ---- stage tile t+1 into buffer s^1 ----
        if (t < 63) {
            const float* Kn = Kg + (size_t)(t + 1) * 64 * 512;
            const float* Vn = Vg + (size_t)(t + 1) * 64 * 512;
            const uint32_t dK = uK + (s ^ 1) * 64 * AK * 4;
            const uint32_t dV = uV + (s ^ 1) * 64 * AV * 4;
#pragma unroll
            for (int it = 0; it < 4; ++it) {
                int id = it * 256 + tid, row = id >> 4, seg = id & 15;
                CP16(dK + (row * AK + seg * 4) * 4, Kn + (size_t)row * 512 + seg * 4);
                CP16(dV + (row * AV + seg * 4) * 4, Vn + (size_t)row * 512 + seg * 4);
            }
            if (tid < 64)
                CP8(uM + (s ^ 1) * 512 + tid * 8,
                    (const char*)(mbase + (size_t)tid * 128 + (t + 1) * 2));
            CP_COMMIT();
        }

        // ---- O += P @ V (warp: 16q x 32d) ----
        const uint32_t* sVu = (const uint32_t*)(sV + s * 64 * AV);
#pragma unroll
        for (int ks = 0; ks < 8; ++ks) {
            const int kb0 = ks * 8;
            uint32_t ap[4] = {sPu[ar * AP + kb0 + lc], sPu[(ar + 8) * AP + kb0 + lc],
                              sPu[ar * AP + kb0 + 4 + lc], sPu[(ar + 8) * AP + kb0 + 4 + lc]};
            uint32_t bv[4][2];
#pragma unroll
            for (int nf = 0; nf < 4; ++nf) {
                int drow = wn * 32 + nf * 8 + lr;
                bv[nf][0] = sVu[(kb0 + lc) * AV + drow];
                bv[nf][1] = sVu[(kb0 + 4 + lc) * AV + drow];
            }
#pragma unroll
            for (int nf = 0; nf < 4; ++nf) mma8(o[nf], ap, bv[nf]);
        }
    }

    // ---- l reduce: quads, then the 2 n-warps via smem ----
#pragma unroll
    for (int u = 0; u < 2; ++u) {
        float v = l_acc[u];
        v += __shfl_xor_sync(0xffffffffu, v, 1);
        v += __shfl_xor_sync(0xffffffffu, v, 2);
        l_acc[u] = v;
    }
    if (lc == 0) {
#pragma unroll
        for (int u = 0; u < 2; ++u)
            sL[wn * 64 + wm * 16 + lr + u * 8] = l_acc[u];
    }
    __syncthreads();

    float* Og = ob + ((size_t)(b * 1024 + q0)) * 512 + h * 64;
#pragma unroll
    for (int u = 0; u < 2; ++u) {
        int row = wm * 16 + lr + u * 8;
        float linv = 1.f / (sL[row] + sL[64 + row]);
#pragma unroll
        for (int nf = 0; nf < 4; ++nf) {
            int col = wn * 32 + nf * 8 + 2 * lc;
            *(float2*)(Og + (size_t)row * 512 + col) =
                make_float2(o[nf][u * 2] * linv, o[nf][u * 2 + 1] * linv);
        }
    }
}

// ================= launcher =================
extern "C" void kernel_launch(void* const* d_in, const int* in_sizes, int n_in,
                              void* d_out, int out_size) {
    const float* x        = (const float*)d_in[0];
    const float* context  = (const float*)d_in[1];
    const float* context2 = (const float*)d_in[2];
    const float* context3 = (const float*)d_in[3];
    const void*  mask1 = d_in[4];
    const void*  mask2 = d_in[5];
    const void*  mask3 = d_in[6];
    const float* Wq  = (const float*)d_in[7];
    const float* bq  = (const float*)d_in[8];
    const float* Wk1 = (const float*)d_in[9];
    const float* bk1 = (const float*)d_in[10];
    const float* Wv1 = (const float*)d_in[11];
    const float* bv1 = (const float*)d_in[12];
    const float* Wk2 = (const float*)d_in[13];
    const float* bk2 = (const float*)d_in[14];
    const float* Wv2 = (const float*)d_in[15];
    const float* bv2 = (const float*)d_in[16];
    const float* Wk3 = (const float*)d_in[17];
    const float* bk3 = (const float*)d_in[18];
    const float* Wv3 = (const float*)d_in[19];
    const float* bv3 = (const float*)d_in[20];
    const float* Wo  = (const float*)d_in[21];
    const float* bo  = (const float*)d_in[22];
    float* out = (float*)d_out;

    float *qp, *kp, *vp, *aop;
    cudaGetSymbolAddress((void**)&qp,  g_q);
    cudaGetSymbolAddress((void**)&kp,  g_k);
    cudaGetSymbolAddress((void**)&vp,  g_v);
    cudaGetSymbolAddress((void**)&aop, g_ao);

    const int smem_gemm = 2 * (128 * GA + 64 * GB) * 4;
    const int smem_attn = ATTN_FLOATS * 4;
    static bool once = false;
    if (!once) {
        cudaFuncSetAttribute(gemm_mma, cudaFuncAttributeMaxDynamicSharedMemorySize, smem_gemm);
        cudaFuncSetAttribute(attn_mma, cudaFuncAttributeMaxDynamicSharedMemorySize, smem_attn);
        once = true;
    }

    detect_mask_kernel<<<1, 256>>>((const unsigned char*)mask1);
    pack_mask_kernel<<<2048, 256>>>(mask1, mask2, mask3);

    dim3 thr(256);
    gemm_mma<<<dim3(8, 32), thr, smem_gemm>>>(x,        Wq,  bq,  qp, 512, 1024, 0,    1024, 1);
    gemm_mma<<<dim3(8, 32), thr, smem_gemm>>>(context,  Wk1, bk1, kp, 512, 1024, 0,    4096, 1);
    gemm_mma<<<dim3(8, 32), thr, smem_gemm>>>(context2, Wk2, bk2, kp, 768, 1024, 1024, 4096, 1);
    gemm_mma<<<dim3(8, 64), thr, smem_gemm>>>(context3, Wk3, bk3, kp, 256, 2048, 2048, 4096, 1);
    gemm_mma<<<dim3(8, 32), thr, smem_gemm>>>(context,  Wv1, bv1, vp, 512, 1024, 0,    4096, 1);
    gemm_mma<<<dim3(8, 32), thr, smem_gemm>>>(context2, Wv2, bv2, vp, 768, 1024, 1024, 4096, 1);
    gemm_mma<<<dim3(8, 64), thr, smem_gemm>>>(context3, Wv3, bv3, vp, 256, 2048, 2048, 4096, 1);

    attn_mma<<<dim3(16, 8, 4), thr, smem_attn>>>(qp, kp, vp, aop);

    gemm_mma<<<dim3(8, 32), thr, smem_gemm>>>(aop, Wo, bo, out, 512, 1024, 0, 1024, 0);
}

// round 7
// speedup vs baseline: 3.6448x; 1.1956x over previous
#include <cuda_runtime.h>
#include <cstdint>

#define EXP2C 0.1803368801111204f   /* (1/8) * log2(e) */

// ================= scratch =================
__device__ float    g_q[4 * 1024 * 512];
__device__ float    g_k[4 * 4096 * 512];
__device__ float    g_v[4 * 4096 * 512];
__device__ float    g_ao[4 * 1024 * 512];
__device__ uint32_t g_mbits[4 * 1024 * 128];
__device__ int      g_mask_is_byte;

// ================= helpers =================
__device__ __forceinline__ uint32_t smem_u32(const void* p) {
    uint32_t a;
    asm("{ .reg .u64 t; cvta.to.shared.u64 t, %1; cvt.u32.u64 %0, t; }" : "=r"(a) : "l"(p));
    return a;
}
#define CP16(dst, src) \
    asm volatile("cp.async.cg.shared.global [%0], [%1], 16;" :: "r"(dst), "l"(src))
#define CP8(dst, src) \
    asm volatile("cp.async.ca.shared.global [%0], [%1], 8;" :: "r"(dst), "l"(src))
#define CP_COMMIT() asm volatile("cp.async.commit_group;" ::: "memory")
#define CP_WAIT(n)  asm volatile("cp.async.wait_group %0;" :: "n"(n) : "memory")

__device__ __forceinline__ float tf32_rn(float x) {
    return __uint_as_float((__float_as_uint(x) + 0x1000u) & 0xFFFFE000u);
}
__device__ __forceinline__ float bf16_rn(float x) {
    uint32_t u = __float_as_uint(x);
    u += 0x7FFFu + ((u >> 16) & 1u);
    return __uint_as_float(u & 0xFFFF0000u);
}
// pack two bf16-exact floats (low = a, high = b)
__device__ __forceinline__ uint32_t pkh(float a, float b) {
    return (__float_as_uint(b) & 0xFFFF0000u) | (__float_as_uint(a) >> 16);
}
// RNE pack arbitrary floats to bf16x2 (low = a, high = b)
__device__ __forceinline__ uint32_t bf2(float a, float b) {
    uint32_t r;
    asm("cvt.rn.bf16x2.f32 %0, %1, %2;" : "=r"(r) : "f"(b), "f"(a));
    return r;
}
__device__ __forceinline__ float fast_exp2(float y) {
    float z = y + 12582912.0f;
    int n = __float_as_int(z) - 0x4B400000;
    float f = y - (z - 12582912.0f);
    float p = 1.3333558146e-3f;
    p = fmaf(p, f, 9.6181291076e-3f);
    p = fmaf(p, f, 5.5504108664e-2f);
    p = fmaf(p, f, 2.4022650696e-1f);
    p = fmaf(p, f, 6.9314718056e-1f);
    p = fmaf(p, f, 1.0f);
    return __int_as_float(__float_as_int(p) + (n << 23));
}
__device__ __forceinline__ void mma8(float* c, const uint32_t* a, const uint32_t* b) {
    asm volatile("mma.sync.aligned.m16n8k8.row.col.f32.tf32.tf32.f32 "
        "{%0,%1,%2,%3},{%4,%5,%6,%7},{%8,%9},{%0,%1,%2,%3};"
        : "+f"(c[0]), "+f"(c[1]), "+f"(c[2]), "+f"(c[3])
        : "r"(a[0]), "r"(a[1]), "r"(a[2]), "r"(a[3]), "r"(b[0]), "r"(b[1]));
}
__device__ __forceinline__ void mma16(float* c, const uint32_t* a, const uint32_t* b) {
    asm volatile("mma.sync.aligned.m16n8k16.row.col.f32.bf16.bf16.f32 "
        "{%0,%1,%2,%3},{%4,%5,%6,%7},{%8,%9},{%0,%1,%2,%3};"
        : "+f"(c[0]), "+f"(c[1]), "+f"(c[2]), "+f"(c[3])
        : "r"(a[0]), "r"(a[1]), "r"(a[2]), "r"(a[3]), "r"(b[0]), "r"(b[1]));
}
__device__ __forceinline__ void ldsm_x4(uint32_t* r, uint32_t addr) {
    asm volatile("ldmatrix.sync.aligned.m8n8.x4.shared.b16 {%0,%1,%2,%3}, [%4];"
        : "=r"(r[0]), "=r"(r[1]), "=r"(r[2]), "=r"(r[3]) : "r"(addr));
}
__device__ __forceinline__ void ldsm_x4_t(uint32_t* r, uint32_t addr) {
    asm volatile("ldmatrix.sync.aligned.m8n8.x4.trans.shared.b16 {%0,%1,%2,%3}, [%4];"
        : "=r"(r[0]), "=r"(r[1]), "=r"(r[2]), "=r"(r[3]) : "r"(addr));
}

// ================= mask detect + bit-pack =================
__global__ void detect_mask_kernel(const unsigned char* __restrict__ m) {
    __shared__ int any;
    if (threadIdx.x == 0) any = 0;
    __syncthreads();
    int found = 0;
    for (int i = threadIdx.x; i < 4096; i += blockDim.x)
        if ((i & 3) == 1 && m[i]) found = 1;
    if (found) atomicOr(&any, 1);
    __syncthreads();
    if (threadIdx.x == 0) g_mask_is_byte = any;
}

__global__ void pack_mask_kernel(const void* __restrict__ m1, const void* __restrict__ m2,
                                 const void* __restrict__ m3) {
    int idx = blockIdx.x * blockDim.x + threadIdx.x;
    if (idx >= 4 * 1024 * 128) return;
    int w = idx & 127, q = (idx >> 7) & 1023, b = idx >> 17;
    int k0 = w * 32;
    const void* mp; int nseg, jl;
    if (k0 < 1024)      { mp = m1; nseg = 1024; jl = k0; }
    else if (k0 < 2048) { mp = m2; nseg = 1024; jl = k0 - 1024; }
    else                { mp = m3; nseg = 2048; jl = k0 - 2048; }
    size_t base = (size_t)(b * 1024 + q) * nseg + jl;
    uint32_t bits = 0;
    if (g_mask_is_byte) {
        const uint4* p = (const uint4*)((const unsigned char*)mp + base);
        uint4 a = p[0], c = p[1];
        uint32_t ws[8] = {a.x, a.y, a.z, a.w, c.x, c.y, c.z, c.w};
#pragma unroll
        for (int wi = 0; wi < 8; ++wi)
#pragma unroll
            for (int by = 0; by < 4; ++by)
                if ((ws[wi] >> (8 * by)) & 0xFFu) bits |= 1u << (wi * 4 + by);
    } else {
        const uint4* p = (const uint4*)((const uint32_t*)mp + base);
#pragma unroll
        for (int wi = 0; wi < 8; ++wi) {
            uint4 v = p[wi];
            if (v.x) bits |= 1u << (wi * 4 + 0);
            if (v.y) bits |= 1u << (wi * 4 + 1);
            if (v.z) bits |= 1u << (wi * 4 + 2);
            if (v.w) bits |= 1u << (wi * 4 + 3);
        }
    }
    g_mbits[idx] = bits;
}

// ================= 3xBF16 HMMA GEMM (ldmatrix + reg-prefetch pipeline) =================
// C[orow,512] = A[M,K]@W[K,512]+bias. Block 128Mx64N, 8 warps (4m x 2n), chunk K=64.
// SMEM per stage (words): Ah[128][36] Al[128][36] Bh[64][36] Bl[64][36]  (72 bf16 rows)
#define G_OAL 4608
#define G_OBH 9216
#define G_OBL 11520
#define G_STW 13824
__global__ __launch_bounds__(256, 2) void gemm_mma(
    const float* __restrict__ A, const float* __restrict__ W,
    const float* __restrict__ bias, float* __restrict__ C,
    int K, int Mb, int rowOff, int bStride, int rnd)
{
    extern __shared__ uint32_t smw[];
    const int tid = threadIdx.x, lane = tid & 31, wid = tid >> 5;
    const int wm = wid & 3, wn = wid >> 2;
    const int lr = lane >> 2, lc = lane & 3;
    const int m0 = blockIdx.y * 128, n0 = blockIdx.x * 64;
    const int l16 = lane & 15, lh8 = (lane >> 4) << 3;   // 0 or 8

    float acc[2][4][4];
#pragma unroll
    for (int i = 0; i < 2; ++i)
#pragma unroll
        for (int j = 0; j < 4; ++j)
#pragma unroll
            for (int e = 0; e < 4; ++e) acc[i][j][e] = 0.f;

    const int nK = K >> 6;
    const uint32_t ub = smem_u32(smw);
    float4 pa[8], pb[4];

#define LDG_CHUNK(c) do { \
    const float* Ab_ = A + (size_t)m0 * K + (c) * 64; \
    _Pragma("unroll") \
    for (int it = 0; it < 8; ++it) { \
        int id = it * 256 + tid, row = id >> 4, seg = id & 15; \
        pa[it] = *(const float4*)(Ab_ + (size_t)row * K + seg * 4); \
    } \
    const float* Wb_ = W + (size_t)((c) * 64) * 512 + n0; \
    _Pragma("unroll") \
    for (int it = 0; it < 4; ++it) { \
        int id = it * 256 + tid, row = id >> 4, seg = id & 15; \
        pb[it] = *(const float4*)(Wb_ + (size_t)row * 512 + seg * 4); \
    } \
} while (0)

#define CVT_STS(v, bp, woff) do { \
    float h0 = bf16_rn((v).x), h1 = bf16_rn((v).y), h2 = bf16_rn((v).z), h3 = bf16_rn((v).w); \
    *(uint2*)((bp) + (woff)) = make_uint2(pkh(h0, h1), pkh(h2, h3)); \
    *(uint2*)((bp) + (woff) + G_OAL_CUR) = \
        make_uint2(bf2((v).x - h0, (v).y - h1), bf2((v).z - h2, (v).w - h3)); \
} while (0)

    LDG_CHUNK(0);
    for (int c = 0; c < nK; ++c) {
        const int s = c & 1;
        uint32_t* bp = smw + s * G_STW;
        // STS (convert + split)
#pragma unroll
        for (int it = 0; it < 8; ++it) {
            int id = it * 256 + tid, row = id >> 4, seg = id & 15;
#define G_OAL_CUR G_OAL
            CVT_STS(pa[it], bp, row * 36 + seg * 2);
#undef G_OAL_CUR
        }
#pragma unroll
        for (int it = 0; it < 4; ++it) {
            int id = it * 256 + tid, row = id >> 4, seg = id & 15;
#define G_OAL_CUR (G_OBL - G_OBH)
            CVT_STS(pb[it], bp + G_OBH, row * 36 + seg * 2);
#undef G_OAL_CUR
        }
        if (c + 1 < nK) LDG_CHUNK(c + 1);
        __syncthreads();

        const uint32_t sb = ub + s * G_STW * 4;
#pragma unroll
        for (int st = 0; st < 4; ++st) {
            const int k0 = st * 16;
            uint32_t ah[2][4], al_[2][4], bh[2][4], bl_[2][4];
#pragma unroll
            for (int mf = 0; mf < 2; ++mf) {
                int row = wm * 32 + mf * 16 + l16;
                uint32_t ad = sb + (row * 36 + ((k0 + lh8) >> 1)) * 4;
                ldsm_x4(ah[mf], ad);
                ldsm_x4(al_[mf], ad + G_OAL * 4);
            }
#pragma unroll
            for (int p = 0; p < 2; ++p) {
                int row = k0 + l16;
                int col = wn * 32 + p * 16 + lh8;
                uint32_t bd = sb + (G_OBH + row * 36 + (col >> 1)) * 4;
                ldsm_x4_t(bh[p], bd);
                ldsm_x4_t(bl_[p], bd + (G_OBL - G_OBH) * 4);
            }
#pragma unroll
            for (int mf = 0; mf < 2; ++mf)
#pragma unroll
                for (int p = 0; p < 2; ++p) {
                    mma16(acc[mf][p * 2 + 0], ah[mf], &bh[p][0]);
                    mma16(acc[mf][p * 2 + 1], ah[mf], &bh[p][2]);
                    mma16(acc[mf][p * 2 + 0], ah[mf], &bl_[p][0]);
                    mma16(acc[mf][p * 2 + 1], ah[mf], &bl_[p][2]);
                    mma16(acc[mf][p * 2 + 0], al_[mf], &bh[p][0]);
                    mma16(acc[mf][p * 2 + 1], al_[mf], &bh[p][2]);
                }
        }
    }
#undef LDG_CHUNK
#undef CVT_STS
    // epilogue
#pragma unroll
    for (int mf = 0; mf < 2; ++mf) {
        int r = m0 + wm * 32 + mf * 16 + lr;
        int b0i = r / Mb;
        size_t or0 = (size_t)b0i * bStride + rowOff + (r - b0i * Mb);
        int r2 = r + 8;
        int b1i = r2 / Mb;
        size_t or1 = (size_t)b1i * bStride + rowOff + (r2 - b1i * Mb);
#pragma unroll
        for (int nf = 0; nf < 4; ++nf) {
            int col = n0 + wn * 32 + nf * 8 + 2 * lc;
            float bv0 = bias[col], bv1 = bias[col + 1];
            float v00 = acc[mf][nf][0] + bv0, v01 = acc[mf][nf][1] + bv1;
            float v10 = acc[mf][nf][2] + bv0, v11 = acc[mf][nf][3] + bv1;
            if (rnd) { v00 = tf32_rn(v00); v01 = tf32_rn(v01); v10 = tf32_rn(v10); v11 = tf32_rn(v11); }
            *(float2*)(C + or0 * 512 + col) = make_float2(v00, v01);
            *(float2*)(C + or1 * 512 + col) = make_float2(v10, v11);
        }
    }
}

// ================= HMMA flash attention, 64q x 64k tiles, 2 CTAs/SM =================
#define AK 68
#define AV 72
#define AP 68
#define AOF_V (2 * 64 * AK)
#define AOF_P (AOF_V + 2 * 64 * AV)
#define AOF_M (AOF_P + 64 * AP)
#define AOF_L (AOF_M + 256)
#define ATTN_FLOATS (AOF_L + 128)

__global__ __launch_bounds__(256, 2) void attn_mma(
    const float* __restrict__ qb, const float* __restrict__ kb,
    const float* __restrict__ vb, float* __restrict__ ob)
{
    extern __shared__ float sm[];
    float* sK = sm;
    float* sV = sm + AOF_V;
    float* sP = sm + AOF_P;
    uint32_t* sM = (uint32_t*)(sm + AOF_M);
    float* sL = sm + AOF_L;

    const int tid = threadIdx.x, lane = tid & 31, wid = tid >> 5;
    const int wm = wid & 3, wn = wid >> 2;
    const int lr = lane >> 2, lc = lane & 3;
    const int q0 = blockIdx.x * 64, h = blockIdx.y, b = blockIdx.z;

    const float* Qg = qb + ((size_t)(b * 1024 + q0)) * 512 + h * 64;
    const float* Kg = kb + ((size_t)(b * 4096)) * 512 + h * 64;
    const float* Vg = vb + ((size_t)(b * 4096)) * 512 + h * 64;
    const uint32_t* mbase = g_mbits + ((size_t)(b * 1024 + q0)) * 128;
    const uint32_t uK = smem_u32(sK), uV = smem_u32(sV);
    const uint32_t uP = smem_u32(sP), uM = smem_u32(sM);

#pragma unroll
    for (int it = 0; it < 4; ++it) {
        int id = it * 256 + tid, row = id >> 4, seg = id & 15;
        CP16(uP + (row * AP + seg * 4) * 4, Qg + (size_t)row * 512 + seg * 4);
        CP16(uK + (row * AK + seg * 4) * 4, Kg + (size_t)row * 512 + seg * 4);
        CP16(uV + (row * AV + seg * 4) * 4, Vg + (size_t)row * 512 + seg * 4);
    }
    if (tid < 64) CP8(uM + tid * 8, (const char*)(mbase + (size_t)tid * 128));
    CP_COMMIT();
    CP_WAIT(0);
    __syncthreads();

    const uint32_t* sPu = (const uint32_t*)sP;
    const int ar = wm * 16 + lr;
    uint32_t aq[8][4];
#pragma unroll
    for (int ks = 0; ks < 8; ++ks) {
        const int kb0 = ks * 8;
        aq[ks][0] = sPu[ar * AP + kb0 + lc];
        aq[ks][1] = sPu[(ar + 8) * AP + kb0 + lc];
        aq[ks][2] = sPu[ar * AP + kb0 + 4 + lc];
        aq[ks][3] = sPu[(ar + 8) * AP + kb0 + 4 + lc];
    }
    __syncthreads();

    float o[4][4];
    float l_acc[2] = {0.f, 0.f};
#pragma unroll
    for (int j = 0; j < 4; ++j)
#pragma unroll
        for (int e = 0; e < 4; ++e) o[j][e] = 0.f;

    for (int t = 0; t < 64; ++t) {
        const int s = t & 1;
        if (t > 0) { CP_WAIT(0); __syncthreads(); }

        const uint32_t* sKu = (const uint32_t*)(sK + s * 64 * AK);
        float sv[4][4];
#pragma unroll
        for (int j = 0; j < 4; ++j)
#pragma unroll
            for (int e = 0; e < 4; ++e) sv[j][e] = 0.f;
#pragma unroll
        for (int ks = 0; ks < 8; ++ks) {
            const int kb0 = ks * 8;
            uint32_t bk[4][2];
#pragma unroll
            for (int nf = 0; nf < 4; ++nf) {
                int nrow = wn * 32 + nf * 8 + lr;
                bk[nf][0] = sKu[nrow * AK + kb0 + lc];
                bk[nf][1] = sKu[nrow * AK + kb0 + 4 + lc];
            }
#pragma unroll
            for (int nf = 0; nf < 4; ++nf) mma8(sv[nf], aq[ks], bk[nf]);
        }

#pragma unroll
        for (int u = 0; u < 2; ++u) {
            int row = wm * 16 + lr + u * 8;
            uint32_t mw = sM[s * 128 + row * 2 + wn];
            float rs = 0.f;
#pragma unroll
            for (int nf = 0; nf < 4; ++nf) {
#pragma unroll
                for (int q2 = 0; q2 < 2; ++q2) {
                    int cr = u * 2 + q2;
                    int cl = nf * 8 + 2 * lc + q2;
                    float p = tf32_rn(fast_exp2(sv[nf][cr] * EXP2C));
                    p = ((mw >> cl) & 1u) ? p : 0.f;
                    rs += p;
                    sv[nf][cr] = p;
                }
            }
            l_acc[u] += rs;
#pragma unroll
            for (int nf = 0; nf < 4; ++nf)
                *(float2*)(sP + row * AP + wn * 32 + nf * 8 + 2 * lc) =
                    make_float2(sv[nf][u * 2], sv[nf][u * 2 + 1]);
        }
        __syncthreads();

        if (t < 63) {
            const float* Kn = Kg + (size_t)(t + 1) * 64 * 512;
            const float* Vn = Vg + (size_t)(t + 1) * 64 * 512;
            const uint32_t dK = uK + (s ^ 1) * 64 * AK * 4;
            const uint32_t dV = uV + (s ^ 1) * 64 * AV * 4;
#pragma unroll
            for (int it = 0; it < 4; ++it) {
                int id = it * 256 + tid, row = id >> 4, seg = id & 15;
                CP16(dK + (row * AK + seg * 4) * 4, Kn + (size_t)row * 512 + seg * 4);
                CP16(dV + (row * AV + seg * 4) * 4, Vn + (size_t)row * 512 + seg * 4);
            }
            if (tid < 64)
                CP8(uM + (s ^ 1) * 512 + tid * 8,
                    (const char*)(mbase + (size_t)tid * 128 + (t + 1) * 2));
            CP_COMMIT();
        }

        const uint32_t* sVu = (const uint32_t*)(sV + s * 64 * AV);
#pragma unroll
        for (int ks = 0; ks < 8; ++ks) {
            const int kb0 = ks * 8;
            uint32_t ap[4] = {sPu[ar * AP + kb0 + lc], sPu[(ar + 8) * AP + kb0 + lc],
                              sPu[ar * AP + kb0 + 4 + lc], sPu[(ar + 8) * AP + kb0 + 4 + lc]};
            uint32_t bv[4][2];
#pragma unroll
            for (int nf = 0; nf < 4; ++nf) {
                int drow = wn * 32 + nf * 8 + lr;
                bv[nf][0] = sVu[(kb0 + lc) * AV + drow];
                bv[nf][1] = sVu[(kb0 + 4 + lc) * AV + drow];
            }
#pragma unroll
            for (int nf = 0; nf < 4; ++nf) mma8(o[nf], ap, bv[nf]);
        }
    }

#pragma unroll
    for (int u = 0; u < 2; ++u) {
        float v = l_acc[u];
        v += __shfl_xor_sync(0xffffffffu, v, 1);
        v += __shfl_xor_sync(0xffffffffu, v, 2);
        l_acc[u] = v;
    }
    if (lc == 0) {
#pragma unroll
        for (int u = 0; u < 2; ++u)
            sL[wn * 64 + wm * 16 + lr + u * 8] = l_acc[u];
    }
    __syncthreads();

    float* Og = ob + ((size_t)(b * 1024 + q0)) * 512 + h * 64;
#pragma unroll
    for (int u = 0; u < 2; ++u) {
        int row = wm * 16 + lr + u * 8;
        float linv = 1.f / (sL[row] + sL[64 + row]);
#pragma unroll
        for (int nf = 0; nf < 4; ++nf) {
            int col = wn * 32 + nf * 8 + 2 * lc;
            *(float2*)(Og + (size_t)row * 512 + col) =
                make_float2(o[nf][u * 2] * linv, o[nf][u * 2 + 1] * linv);
        }
    }
}

// ================= launcher =================
extern "C" void kernel_launch(void* const* d_in, const int* in_sizes, int n_in,
                              void* d_out, int out_size) {
    const float* x        = (const float*)d_in[0];
    const float* context  = (const float*)d_in[1];
    const float* context2 = (const float*)d_in[2];
    const float* context3 = (const float*)d_in[3];
    const void*  mask1 = d_in[4];
    const void*  mask2 = d_in[5];
    const void*  mask3 = d_in[6];
    const float* Wq  = (const float*)d_in[7];
    const float* bq  = (const float*)d_in[8];
    const float* Wk1 = (const float*)d_in[9];
    const float* bk1 = (const float*)d_in[10];
    const float* Wv1 = (const float*)d_in[11];
    const float* bv1 = (const float*)d_in[12];
    const float* Wk2 = (const float*)d_in[13];
    const float* bk2 = (const float*)d_in[14];
    const float* Wv2 = (const float*)d_in[15];
    const float* bv2 = (const float*)d_in[16];
    const float* Wk3 = (const float*)d_in[17];
    const float* bk3 = (const float*)d_in[18];
    const float* Wv3 = (const float*)d_in[19];
    const float* bv3 = (const float*)d_in[20];
    const float* Wo  = (const float*)d_in[21];
    const float* bo  = (const float*)d_in[22];
    float* out = (float*)d_out;

    float *qp, *kp, *vp, *aop;
    cudaGetSymbolAddress((void**)&qp,  g_q);
    cudaGetSymbolAddress((void**)&kp,  g_k);
    cudaGetSymbolAddress((void**)&vp,  g_v);
    cudaGetSymbolAddress((void**)&aop, g_ao);

    const int smem_gemm = 2 * G_STW * 4;       // 110592
    const int smem_attn = ATTN_FLOATS * 4;
    static bool once = false;
    if (!once) {
        cudaFuncSetAttribute(gemm_mma, cudaFuncAttributeMaxDynamicSharedMemorySize, smem_gemm);
        cudaFuncSetAttribute(attn_mma, cudaFuncAttributeMaxDynamicSharedMemorySize, smem_attn);
        once = true;
    }

    detect_mask_kernel<<<1, 256>>>((const unsigned char*)mask1);
    pack_mask_kernel<<<2048, 256>>>(mask1, mask2, mask3);

    dim3 thr(256);
    gemm_mma<<<dim3(8, 32), thr, smem_gemm>>>(x,        Wq,  bq,  qp, 512, 1024, 0,    1024, 1);
    gemm_mma<<<dim3(8, 32), thr, smem_gemm>>>(context,  Wk1, bk1, kp, 512, 1024, 0,    4096, 1);
    gemm_mma<<<dim3(8, 32), thr, smem_gemm>>>(context2, Wk2, bk2, kp, 768, 1024, 1024, 4096, 1);
    gemm_mma<<<dim3(8, 64), thr, smem_gemm>>>(context3, Wk3, bk3, kp, 256, 2048, 2048, 4096, 1);
    gemm_mma<<<dim3(8, 32), thr, smem_gemm>>>(context,  Wv1, bv1, vp, 512, 1024, 0,    4096, 1);
    gemm_mma<<<dim3(8, 32), thr, smem_gemm>>>(context2, Wv2, bv2, vp, 768, 1024, 1024, 4096, 1);
    gemm_mma<<<dim3(8, 64), thr, smem_gemm>>>(context3, Wv3, bv3, vp, 256, 2048, 2048, 4096, 1);

    attn_mma<<<dim3(16, 8, 4), thr, smem_attn>>>(qp, kp, vp, aop);

    gemm_mma<<<dim3(8, 32), thr, smem_gemm>>>(aop, Wo, bo, out, 512, 1024, 0, 1024, 0);
}

// round 8
// speedup vs baseline: 4.2436x; 1.1643x over previous
#include <cuda_runtime.h>
#include <cstdint>

#define EXP2C 0.1803368801111204f   /* (1/8) * log2(e) */

// ================= pools / scratch =================
#define OFF_X   0
#define OFF_C1  2097152
#define OFF_C2  4194304
#define OFF_C3  7340032
#define OFF_AO  9437184
#define OFF_WQ  11534336
#define OFF_WK1 11796480
#define OFF_WV1 12058624
#define OFF_WK2 12320768
#define OFF_WV2 12713984
#define OFF_WK3 13107200
#define OFF_WV3 13238272
#define OFF_WO  13369344
#define POOL_N  13631488

__device__ uint16_t g_h[POOL_N];
__device__ uint16_t g_l[POOL_N];
__device__ uint16_t g_qb[4 * 1024 * 512];
__device__ uint16_t g_kb[4 * 4096 * 512];
__device__ float    g_v[4 * 4096 * 512];
__device__ float    g_ao[4 * 1024 * 512];
__device__ uint32_t g_mbits[4 * 1024 * 128];
__device__ int      g_mask_is_byte;

// ================= helpers =================
__device__ __forceinline__ uint32_t smem_u32(const void* p) {
    uint32_t a;
    asm("{ .reg .u64 t; cvta.to.shared.u64 t, %1; cvt.u32.u64 %0, t; }" : "=r"(a) : "l"(p));
    return a;
}
#define CP16(dst, src) \
    asm volatile("cp.async.cg.shared.global [%0], [%1], 16;" :: "r"(dst), "l"(src))
#define CP8(dst, src) \
    asm volatile("cp.async.ca.shared.global [%0], [%1], 8;" :: "r"(dst), "l"(src))
#define CP_COMMIT() asm volatile("cp.async.commit_group;" ::: "memory")
#define CP_WAIT(n)  asm volatile("cp.async.wait_group %0;" :: "n"(n) : "memory")

__device__ __forceinline__ float tf32_rn(float x) {
    return __uint_as_float((__float_as_uint(x) + 0x1000u) & 0xFFFFE000u);
}
__device__ __forceinline__ float bf16_rn(float x) {
    uint32_t u = __float_as_uint(x);
    u += 0x7FFFu + ((u >> 16) & 1u);
    return __uint_as_float(u & 0xFFFF0000u);
}
__device__ __forceinline__ uint32_t pkh(float a, float b) {
    return (__float_as_uint(b) & 0xFFFF0000u) | (__float_as_uint(a) >> 16);
}
__device__ __forceinline__ uint32_t bf2(float a, float b) {
    uint32_t r;
    asm("cvt.rn.bf16x2.f32 %0, %1, %2;" : "=r"(r) : "f"(b), "f"(a));
    return r;
}
__device__ __forceinline__ float fast_exp2(float y) {
    float z = y + 12582912.0f;
    int n = __float_as_int(z) - 0x4B400000;
    float f = y - (z - 12582912.0f);
    float p = 1.3333558146e-3f;
    p = fmaf(p, f, 9.6181291076e-3f);
    p = fmaf(p, f, 5.5504108664e-2f);
    p = fmaf(p, f, 2.4022650696e-1f);
    p = fmaf(p, f, 6.9314718056e-1f);
    p = fmaf(p, f, 1.0f);
    return __int_as_float(__float_as_int(p) + (n << 23));
}
__device__ __forceinline__ void mma8(float* c, const uint32_t* a, const uint32_t* b) {
    asm volatile("mma.sync.aligned.m16n8k8.row.col.f32.tf32.tf32.f32 "
        "{%0,%1,%2,%3},{%4,%5,%6,%7},{%8,%9},{%0,%1,%2,%3};"
        : "+f"(c[0]), "+f"(c[1]), "+f"(c[2]), "+f"(c[3])
        : "r"(a[0]), "r"(a[1]), "r"(a[2]), "r"(a[3]), "r"(b[0]), "r"(b[1]));
}
__device__ __forceinline__ void mma16(float* c, const uint32_t* a, const uint32_t* b) {
    asm volatile("mma.sync.aligned.m16n8k16.row.col.f32.bf16.bf16.f32 "
        "{%0,%1,%2,%3},{%4,%5,%6,%7},{%8,%9},{%0,%1,%2,%3};"
        : "+f"(c[0]), "+f"(c[1]), "+f"(c[2]), "+f"(c[3])
        : "r"(a[0]), "r"(a[1]), "r"(a[2]), "r"(a[3]), "r"(b[0]), "r"(b[1]));
}
__device__ __forceinline__ void ldsm_x4(uint32_t* r, uint32_t addr) {
    asm volatile("ldmatrix.sync.aligned.m8n8.x4.shared.b16 {%0,%1,%2,%3}, [%4];"
        : "=r"(r[0]), "=r"(r[1]), "=r"(r[2]), "=r"(r[3]) : "r"(addr));
}
__device__ __forceinline__ void ldsm_x4_t(uint32_t* r, uint32_t addr) {
    asm volatile("ldmatrix.sync.aligned.m8n8.x4.trans.shared.b16 {%0,%1,%2,%3}, [%4];"
        : "=r"(r[0]), "=r"(r[1]), "=r"(r[2]), "=r"(r[3]) : "r"(addr));
}

// ================= mask detect + bit-pack =================
__global__ void detect_mask_kernel(const unsigned char* __restrict__ m) {
    __shared__ int any;
    if (threadIdx.x == 0) any = 0;
    __syncthreads();
    int found = 0;
    for (int i = threadIdx.x; i < 4096; i += blockDim.x)
        if ((i & 3) == 1 && m[i]) found = 1;
    if (found) atomicOr(&any, 1);
    __syncthreads();
    if (threadIdx.x == 0) g_mask_is_byte = any;
}

__global__ void pack_mask_kernel(const void* __restrict__ m1, const void* __restrict__ m2,
                                 const void* __restrict__ m3) {
    int idx = blockIdx.x * blockDim.x + threadIdx.x;
    if (idx >= 4 * 1024 * 128) return;
    int w = idx & 127, q = (idx >> 7) & 1023, b = idx >> 17;
    int k0 = w * 32;
    const void* mp; int nseg, jl;
    if (k0 < 1024)      { mp = m1; nseg = 1024; jl = k0; }
    else if (k0 < 2048) { mp = m2; nseg = 1024; jl = k0 - 1024; }
    else                { mp = m3; nseg = 2048; jl = k0 - 2048; }
    size_t base = (size_t)(b * 1024 + q) * nseg + jl;
    uint32_t bits = 0;
    if (g_mask_is_byte) {
        const uint4* p = (const uint4*)((const unsigned char*)mp + base);
        uint4 a = p[0], c = p[1];
        uint32_t ws[8] = {a.x, a.y, a.z, a.w, c.x, c.y, c.z, c.w};
#pragma unroll
        for (int wi = 0; wi < 8; ++wi)
#pragma unroll
            for (int by = 0; by < 4; ++by)
                if ((ws[wi] >> (8 * by)) & 0xFFu) bits |= 1u << (wi * 4 + by);
    } else {
        const uint4* p = (const uint4*)((const uint32_t*)mp + base);
#pragma unroll
        for (int wi = 0; wi < 8; ++wi) {
            uint4 v = p[wi];
            if (v.x) bits |= 1u << (wi * 4 + 0);
            if (v.y) bits |= 1u << (wi * 4 + 1);
            if (v.z) bits |= 1u << (wi * 4 + 2);
            if (v.w) bits |= 1u << (wi * 4 + 3);
        }
    }
    g_mbits[idx] = bits;
}

// ================= bf16 hi/lo split (pre-pass) =================
struct SplitJobs {
    const float* src[12];
    int nblk[13];    // cumulative block offsets
    int off[12];     // pool element offsets
};
__global__ __launch_bounds__(256) void split_kernel(SplitJobs j, int njobs) {
    int bid = blockIdx.x;
    int ji = 0;
    while (ji + 1 < njobs && bid >= j.nblk[ji + 1]) ++ji;
    int local = bid - j.nblk[ji];
    const float4* src = (const float4*)j.src[ji];
    uint2* dh = (uint2*)(g_h + j.off[ji]);
    uint2* dl = (uint2*)(g_l + j.off[ji]);
    size_t base4 = (size_t)local * 1024;
#pragma unroll
    for (int it = 0; it < 4; ++it) {
        size_t i4 = base4 + it * 256 + threadIdx.x;
        float4 v = src[i4];
        float h0 = bf16_rn(v.x), h1 = bf16_rn(v.y), h2 = bf16_rn(v.z), h3 = bf16_rn(v.w);
        dh[i4] = make_uint2(pkh(h0, h1), pkh(h2, h3));
        dl[i4] = make_uint2(bf2(v.x - h0, v.y - h1), bf2(v.z - h2, v.w - h3));
    }
}

// ================= 3xBF16 HMMA GEMM (pre-split planes, cp.async 2-stage) =================
// Block 128Mx64N, 8 warps (4m x 2n), chunk K=64.
// Stage layout (words): Ah[128][36] | Al | Bh[64][36] | Bl
#define G_OAL 4608
#define G_OBH 9216
#define G_OBL 11520
#define G_STW 13824
// mode: 0 = fp32 out, 1 = tf32-rounded fp32 out, 2 = bf16 out
__global__ __launch_bounds__(256, 2) void gemm_mma(
    const uint16_t* __restrict__ Ah, const uint16_t* __restrict__ Al,
    const uint16_t* __restrict__ Wh, const uint16_t* __restrict__ Wl,
    const float* __restrict__ bias, void* __restrict__ Cv,
    int K, int Mb, int rowOff, int bStride, int mode)
{
    extern __shared__ uint32_t smw[];
    const int tid = threadIdx.x, lane = tid & 31, wid = tid >> 5;
    const int wm = wid & 3, wn = wid >> 2;
    const int lr = lane >> 2, lc = lane & 3;
    const int m0 = blockIdx.y * 128, n0 = blockIdx.x * 64;
    const int l16 = lane & 15, lh8 = (lane >> 4) << 3;

    float acc[2][4][4];
#pragma unroll
    for (int i = 0; i < 2; ++i)
#pragma unroll
        for (int j = 0; j < 4; ++j)
#pragma unroll
            for (int e = 0; e < 4; ++e) acc[i][j][e] = 0.f;

    const int nK = K >> 6;
    const uint32_t ub = smem_u32(smw);

#define STAGE(c, s) do { \
    const uint32_t d0 = ub + (s) * G_STW * 4; \
    _Pragma("unroll") \
    for (int it = 0; it < 4; ++it) { \
        int id = it * 256 + tid, row = id >> 3, seg = id & 7; \
        size_t so = (size_t)(m0 + row) * K + (c) * 64 + seg * 8; \
        uint32_t dw = (row * 36 + seg * 4) * 4; \
        CP16(d0 + dw, Ah + so); \
        CP16(d0 + G_OAL * 4 + dw, Al + so); \
    } \
    _Pragma("unroll") \
    for (int it = 0; it < 2; ++it) { \
        int id = it * 256 + tid, row = id >> 3, seg = id & 7; \
        size_t so = (size_t)((c) * 64 + row) * 512 + n0 + seg * 8; \
        uint32_t dw = (row * 36 + seg * 4) * 4; \
        CP16(d0 + G_OBH * 4 + dw, Wh + so); \
        CP16(d0 + G_OBL * 4 + dw, Wl + so); \
    } \
    CP_COMMIT(); \
} while (0)

    STAGE(0, 0);
    for (int c = 0; c < nK; ++c) {
        const int s = c & 1;
        if (c + 1 < nK) { STAGE(c + 1, s ^ 1); CP_WAIT(1); }
        else            { CP_WAIT(0); }
        __syncthreads();
        const uint32_t sb = ub + s * G_STW * 4;
#pragma unroll
        for (int st = 0; st < 4; ++st) {
            const int k0 = st * 16;
            uint32_t ah[2][4], al_[2][4], bh[2][4], bl_[2][4];
#pragma unroll
            for (int mf = 0; mf < 2; ++mf) {
                int row = wm * 32 + mf * 16 + l16;
                uint32_t ad = sb + (row * 36 + ((k0 + lh8) >> 1)) * 4;
                ldsm_x4(ah[mf], ad);
                ldsm_x4(al_[mf], ad + G_OAL * 4);
            }
#pragma unroll
            for (int p = 0; p < 2; ++p) {
                int row = k0 + l16;
                int col = wn * 32 + p * 16 + lh8;
                uint32_t bd = sb + (G_OBH + row * 36 + (col >> 1)) * 4;
                ldsm_x4_t(bh[p], bd);
                ldsm_x4_t(bl_[p], bd + (G_OBL - G_OBH) * 4);
            }
#pragma unroll
            for (int mf = 0; mf < 2; ++mf)
#pragma unroll
                for (int p = 0; p < 2; ++p) {
                    mma16(acc[mf][p * 2 + 0], ah[mf], &bh[p][0]);
                    mma16(acc[mf][p * 2 + 1], ah[mf], &bh[p][2]);
                    mma16(acc[mf][p * 2 + 0], ah[mf], &bl_[p][0]);
                    mma16(acc[mf][p * 2 + 1], ah[mf], &bl_[p][2]);
                    mma16(acc[mf][p * 2 + 0], al_[mf], &bh[p][0]);
                    mma16(acc[mf][p * 2 + 1], al_[mf], &bh[p][2]);
                }
        }
        __syncthreads();
    }
#undef STAGE
    // epilogue
#pragma unroll
    for (int mf = 0; mf < 2; ++mf) {
        int r = m0 + wm * 32 + mf * 16 + lr;
        int b0i = r / Mb;
        size_t or0 = (size_t)b0i * bStride + rowOff + (r - b0i * Mb);
        int r2 = r + 8;
        int b1i = r2 / Mb;
        size_t or1 = (size_t)b1i * bStride + rowOff + (r2 - b1i * Mb);
#pragma unroll
        for (int nf = 0; nf < 4; ++nf) {
            int col = n0 + wn * 32 + nf * 8 + 2 * lc;
            float bv0 = bias[col], bv1 = bias[col + 1];
            float v00 = acc[mf][nf][0] + bv0, v01 = acc[mf][nf][1] + bv1;
            float v10 = acc[mf][nf][2] + bv0, v11 = acc[mf][nf][3] + bv1;
            if (mode == 2) {
                uint16_t* Cb = (uint16_t*)Cv;
                *(uint32_t*)(Cb + or0 * 512 + col) = pkh(bf16_rn(v00), bf16_rn(v01));
                *(uint32_t*)(Cb + or1 * 512 + col) = pkh(bf16_rn(v10), bf16_rn(v11));
            } else {
                float* C = (float*)Cv;
                if (mode == 1) {
                    v00 = tf32_rn(v00); v01 = tf32_rn(v01);
                    v10 = tf32_rn(v10); v11 = tf32_rn(v11);
                }
                *(float2*)(C + or0 * 512 + col) = make_float2(v00, v01);
                *(float2*)(C + or1 * 512 + col) = make_float2(v10, v11);
            }
        }
    }
}

// ================= flash attention: bf16 QK^T + tf32 PV, 64q x 64k =================
// smem word offsets
#define A_QW 0
#define A_KW 2304
#define A_VW 6912
#define A_PW 16128
#define A_MW 20480
#define A_LW 20736
#define A_TOTW 20864
#define AV 72
#define AP 68

__global__ __launch_bounds__(256, 2) void attn_mma(
    const uint16_t* __restrict__ qb, const uint16_t* __restrict__ kb,
    const float* __restrict__ vb, float* __restrict__ ob)
{
    extern __shared__ uint32_t smw[];
    float* smf = (float*)smw;
    uint32_t* sM = smw + A_MW;
    float* sP = smf + A_PW;
    float* sL = smf + A_LW;
    const uint32_t* sPu = smw + A_PW;

    const int tid = threadIdx.x, lane = tid & 31, wid = tid >> 5;
    const int wm = wid & 3, wn = wid >> 2;
    const int lr = lane >> 2, lc = lane & 3;
    const int ln8 = lane & 7;
    const int q0 = blockIdx.x * 64, h = blockIdx.y, b = blockIdx.z;

    const uint16_t* Qg = qb + ((size_t)(b * 1024 + q0)) * 512 + h * 64;
    const uint16_t* Kg = kb + ((size_t)(b * 4096)) * 512 + h * 64;
    const float*    Vg = vb + ((size_t)(b * 4096)) * 512 + h * 64;
    const uint32_t* mbase = g_mbits + ((size_t)(b * 1024 + q0)) * 128;
    const uint32_t ubase = smem_u32(smw);
    const uint32_t uQ = ubase + A_QW * 4, uK = ubase + A_KW * 4;
    const uint32_t uV = ubase + A_VW * 4, uM = ubase + A_MW * 4;

    // ---- prologue: Q, K(0), V(0), M(0) ----
#pragma unroll
    for (int it = 0; it < 2; ++it) {
        int id = it * 256 + tid, row = id >> 3, seg = id & 7;
        CP16(uQ + (row * 36 + seg * 4) * 4, Qg + (size_t)row * 512 + seg * 8);
        CP16(uK + (row * 36 + seg * 4) * 4, Kg + (size_t)row * 512 + seg * 8);
    }
#pragma unroll
    for (int it = 0; it < 4; ++it) {
        int id = it * 256 + tid, row = id >> 4, seg = id & 15;
        CP16(uV + (row * AV + seg * 4) * 4, Vg + (size_t)row * 512 + seg * 4);
    }
    if (tid < 64) CP8(uM + tid * 8, (const char*)(mbase + (size_t)tid * 128));
    CP_COMMIT();
    CP_WAIT(0);
    __syncthreads();

    // Q fragments (bf16, 16 regs)
    uint32_t aq[4][4];
#pragma unroll
    for (int ks = 0; ks < 4; ++ks) {
        int qrow = wm * 16 + ((lane >> 3) & 1) * 8 + ln8;
        int kc = ks * 16 + (lane >> 4) * 8;
        ldsm_x4(aq[ks], uQ + (qrow * 36 + (kc >> 1)) * 4);
    }

    float o[4][4];
    float l_acc[2] = {0.f, 0.f};
#pragma unroll
    for (int j = 0; j < 4; ++j)
#pragma unroll
        for (int e = 0; e < 4; ++e) o[j][e] = 0.f;

    for (int t = 0; t < 64; ++t) {
        const int s = t & 1;
        if (t > 0) { CP_WAIT(0); __syncthreads(); }

        // ---- S = Q K^T (bf16 m16n8k16; warp: 16q x 32k) ----
        const uint32_t uKs = uK + s * 2304 * 4;
        float sv[4][4];
#pragma unroll
        for (int j = 0; j < 4; ++j)
#pragma unroll
            for (int e = 0; e < 4; ++e) sv[j][e] = 0.f;
#pragma unroll
        for (int ks = 0; ks < 4; ++ks) {
            int kcb = ks * 16 + ((lane >> 3) & 1) * 8;
            int nrow = wn * 32 + (lane >> 4) * 8 + ln8;
            uint32_t bk0[4], bk1[4];
            ldsm_x4(bk0, uKs + (nrow * 36 + (kcb >> 1)) * 4);
            ldsm_x4(bk1, uKs + ((nrow + 16) * 36 + (kcb >> 1)) * 4);
            mma16(sv[0], aq[ks], &bk0[0]);
            mma16(sv[1], aq[ks], &bk0[2]);
            mma16(sv[2], aq[ks], &bk1[0]);
            mma16(sv[3], aq[ks], &bk1[2]);
        }

        // ---- masked no-max softmax + P write ----
#pragma unroll
        for (int u = 0; u < 2; ++u) {
            int row = wm * 16 + lr + u * 8;
            uint32_t mw = sM[s * 128 + row * 2 + wn];
            float rs = 0.f;
#pragma unroll
            for (int nf = 0; nf < 4; ++nf) {
#pragma unroll
                for (int q2 = 0; q2 < 2; ++q2) {
                    int cr = u * 2 + q2;
                    int cl = nf * 8 + 2 * lc + q2;
                    float p = tf32_rn(fast_exp2(sv[nf][cr] * EXP2C));
                    p = ((mw >> cl) & 1u) ? p : 0.f;
                    rs += p;
                    sv[nf][cr] = p;
                }
            }
            l_acc[u] += rs;
#pragma unroll
            for (int nf = 0; nf < 4; ++nf)
                *(float2*)(sP + row * AP + wn * 32 + nf * 8 + 2 * lc) =
                    make_float2(sv[nf][u * 2], sv[nf][u * 2 + 1]);
        }
        __syncthreads();   // P visible; K[s], M[s] free

        // ---- stage tile t+1 ----
        if (t < 63) {
            const uint16_t* Kn = Kg + (size_t)(t + 1) * 64 * 512;
            const float* Vn = Vg + (size_t)(t + 1) * 64 * 512;
            const uint32_t dK = uK + (s ^ 1) * 2304 * 4;
            const uint32_t dV = uV + (s ^ 1) * 64 * AV * 4;
#pragma unroll
            for (int it = 0; it < 2; ++it) {
                int id = it * 256 + tid, row = id >> 3, seg = id & 7;
                CP16(dK + (row * 36 + seg * 4) * 4, Kn + (size_t)row * 512 + seg * 8);
            }
#pragma unroll
            for (int it = 0; it < 4; ++it) {
                int id = it * 256 + tid, row = id >> 4, seg = id & 15;
                CP16(dV + (row * AV + seg * 4) * 4, Vn + (size_t)row * 512 + seg * 4);
            }
            if (tid < 64)
                CP8(uM + (s ^ 1) * 512 + tid * 8,
                    (const char*)(mbase + (size_t)tid * 128 + (t + 1) * 2));
            CP_COMMIT();
        }

        // ---- O += P @ V (tf32 m16n8k8; warp: 16q x 32d) ----
        const uint32_t* sVu = smw + A_VW + s * 64 * AV;
        const int ar = wm * 16 + lr;
#pragma unroll
        for (int ks = 0; ks < 8; ++ks) {
            const int kb0 = ks * 8;
            uint32_t ap[4] = {sPu[ar * AP + kb0 + lc], sPu[(ar + 8) * AP + kb0 + lc],
                              sPu[ar * AP + kb0 + 4 + lc], sPu[(ar + 8) * AP + kb0 + 4 + lc]};
            uint32_t bv[4][2];
#pragma unroll
            for (int nf = 0; nf < 4; ++nf) {
                int drow = wn * 32 + nf * 8 + lr;
                bv[nf][0] = sVu[(kb0 + lc) * AV + drow];
                bv[nf][1] = sVu[(kb0 + 4 + lc) * AV + drow];
            }
#pragma unroll
            for (int nf = 0; nf < 4; ++nf) mma8(o[nf], ap, bv[nf]);
        }
    }

    // ---- l reduce: quads, then the 2 n-warps via smem ----
#pragma unroll
    for (int u = 0; u < 2; ++u) {
        float v = l_acc[u];
        v += __shfl_xor_sync(0xffffffffu, v, 1);
        v += __shfl_xor_sync(0xffffffffu, v, 2);
        l_acc[u] = v;
    }
    if (lc == 0) {
#pragma unroll
        for (int u = 0; u < 2; ++u)
            sL[wn * 64 + wm * 16 + lr + u * 8] = l_acc[u];
    }
    __syncthreads();

    float* Og = ob + ((size_t)(b * 1024 + q0)) * 512 + h * 64;
#pragma unroll
    for (int u = 0; u < 2; ++u) {
        int row = wm * 16 + lr + u * 8;
        float linv = 1.f / (sL[row] + sL[64 + row]);
#pragma unroll
        for (int nf = 0; nf < 4; ++nf) {
            int col = wn * 32 + nf * 8 + 2 * lc;
            *(float2*)(Og + (size_t)row * 512 + col) =
                make_float2(o[nf][u * 2] * linv, o[nf][u * 2 + 1] * linv);
        }
    }
}

// ================= launcher =================
extern "C" void kernel_launch(void* const* d_in, const int* in_sizes, int n_in,
                              void* d_out, int out_size) {
    const float* x        = (const float*)d_in[0];
    const float* context  = (const float*)d_in[1];
    const float* context2 = (const float*)d_in[2];
    const float* context3 = (const float*)d_in[3];
    const void*  mask1 = d_in[4];
    const void*  mask2 = d_in[5];
    const void*  mask3 = d_in[6];
    const float* Wq  = (const float*)d_in[7];
    const float* bq  = (const float*)d_in[8];
    const float* Wk1 = (const float*)d_in[9];
    const float* bk1 = (const float*)d_in[10];
    const float* Wv1 = (const float*)d_in[11];
    const float* bv1 = (const float*)d_in[12];
    const float* Wk2 = (const float*)d_in[13];
    const float* bk2 = (const float*)d_in[14];
    const float* Wv2 = (const float*)d_in[15];
    const float* bv2 = (const float*)d_in[16];
    const float* Wk3 = (const float*)d_in[17];
    const float* bk3 = (const float*)d_in[18];
    const float* Wv3 = (const float*)d_in[19];
    const float* bv3 = (const float*)d_in[20];
    const float* Wo  = (const float*)d_in[21];
    const float* bo  = (const float*)d_in[22];
    float* out = (float*)d_out;

    uint16_t *hp, *lp, *qbp, *kbp;
    float *vp, *aop;
    cudaGetSymbolAddress((void**)&hp,  g_h);
    cudaGetSymbolAddress((void**)&lp,  g_l);
    cudaGetSymbolAddress((void**)&qbp, g_qb);
    cudaGetSymbolAddress((void**)&kbp, g_kb);
    cudaGetSymbolAddress((void**)&vp,  g_v);
    cudaGetSymbolAddress((void**)&aop, g_ao);

    const int smem_gemm = 2 * G_STW * 4;    // 110592
    const int smem_attn = A_TOTW * 4;       // 83456
    static bool once = false;
    if (!once) {
        cudaFuncSetAttribute(gemm_mma, cudaFuncAttributeMaxDynamicSharedMemorySize, smem_gemm);
        cudaFuncSetAttribute(attn_mma, cudaFuncAttributeMaxDynamicSharedMemorySize, smem_attn);
        once = true;
    }

    detect_mask_kernel<<<1, 256>>>((const unsigned char*)mask1);
    pack_mask_kernel<<<2048, 256>>>(mask1, mask2, mask3);

    // pre-split inputs + weights into bf16 h/l planes
    {
        SplitJobs js;
        const float* srcs[12] = {x, context, context2, context3,
                                 Wq, Wk1, Wv1, Wk2, Wv2, Wk3, Wv3, Wo};
        int offs[12] = {OFF_X, OFF_C1, OFF_C2, OFF_C3,
                        OFF_WQ, OFF_WK1, OFF_WV1, OFF_WK2, OFF_WV2,
                        OFF_WK3, OFF_WV3, OFF_WO};
        int cnts[12] = {512, 512, 768, 512, 64, 64, 64, 96, 96, 32, 32, 64};
        int cum = 0;
        for (int i = 0; i < 12; ++i) {
            js.src[i] = srcs[i]; js.off[i] = offs[i];
            js.nblk[i] = cum; cum += cnts[i];
        }
        js.nblk[12] = cum;
        split_kernel<<<cum, 256>>>(js, 12);
    }

    dim3 thr(256);
    // Q, K projections -> bf16 buffers (mode 2)
    gemm_mma<<<dim3(8, 32), thr, smem_gemm>>>(hp + OFF_X,  lp + OFF_X,  hp + OFF_WQ,  lp + OFF_WQ,  bq,  qbp, 512, 1024, 0,    1024, 2);
    gemm_mma<<<dim3(8, 32), thr, smem_gemm>>>(hp + OFF_C1, lp + OFF_C1, hp + OFF_WK1, lp + OFF_WK1, bk1, kbp, 512, 1024, 0,    4096, 2);
    gemm_mma<<<dim3(8, 32), thr, smem_gemm>>>(hp + OFF_C2, lp + OFF_C2, hp + OFF_WK2, lp + OFF_WK2, bk2, kbp, 768, 1024, 1024, 4096, 2);
    gemm_mma<<<dim3(8, 64), thr, smem_gemm>>>(hp + OFF_C3, lp + OFF_C3, hp + OFF_WK3, lp + OFF_WK3, bk3, kbp, 256, 2048, 2048, 4096, 2);
    // V projections -> tf32 fp32 (mode 1)
    gemm_mma<<<dim3(8, 32), thr, smem_gemm>>>(hp + OFF_C1, lp + OFF_C1, hp + OFF_WV1, lp + OFF_WV1, bv1, vp, 512, 1024, 0,    4096, 1);
    gemm_mma<<<dim3(8, 32), thr, smem_gemm>>>(hp + OFF_C2, lp + OFF_C2, hp + OFF_WV2, lp + OFF_WV2, bv2, vp, 768, 1024, 1024, 4096, 1);
    gemm_mma<<<dim3(8, 64), thr, smem_gemm>>>(hp + OFF_C3, lp + OFF_C3, hp + OFF_WV3, lp + OFF_WV3, bv3, vp, 256, 2048, 2048, 4096, 1);

    attn_mma<<<dim3(16, 8, 4), thr, smem_attn>>>(qbp, kbp, vp, aop);

    // split attention output, then final projection -> d_out (mode 0)
    {
        SplitJobs ja;
        ja.src[0] = aop; ja.off[0] = OFF_AO;
        ja.nblk[0] = 0; ja.nblk[1] = 512;
        split_kernel<<<512, 256>>>(ja, 1);
    }
    gemm_mma<<<dim3(8, 32), thr, smem_gemm>>>(hp + OFF_AO, lp + OFF_AO, hp + OFF_WO, lp + OFF_WO, bo, out, 512, 1024, 0, 1024, 0);
}

// round 9
// speedup vs baseline: 5.1227x; 1.2072x over previous
#include <cuda_runtime.h>
#include <cstdint>

#define EXP2C 0.1803368801111204f   /* (1/8) * log2(e) */

// ================= pools / scratch =================
#define OFF_X   0
#define OFF_C1  2097152
#define OFF_C2  4194304
#define OFF_C3  7340032
#define OFF_AO  9437184
#define OFF_WQ  11534336
#define OFF_WK1 11796480
#define OFF_WV1 12058624
#define OFF_WK2 12320768
#define OFF_WV2 12713984
#define OFF_WK3 13107200
#define OFF_WV3 13238272
#define OFF_WO  13369344
#define POOL_N  13631488

__device__ uint16_t g_h[POOL_N];
__device__ uint16_t g_l[POOL_N];
__device__ uint16_t g_qb[4 * 1024 * 512];
__device__ uint16_t g_kb[4 * 4096 * 512];
__device__ float    g_v[4 * 4096 * 512];
__device__ float    g_ao[4 * 1024 * 512];
__device__ uint32_t g_mbits[4 * 1024 * 128];
__device__ int      g_mask_is_byte;

// ================= helpers =================
__device__ __forceinline__ uint32_t smem_u32(const void* p) {
    uint32_t a;
    asm("{ .reg .u64 t; cvta.to.shared.u64 t, %1; cvt.u32.u64 %0, t; }" : "=r"(a) : "l"(p));
    return a;
}
#define CP16(dst, src) \
    asm volatile("cp.async.cg.shared.global [%0], [%1], 16;" :: "r"(dst), "l"(src))
#define CP8(dst, src) \
    asm volatile("cp.async.ca.shared.global [%0], [%1], 8;" :: "r"(dst), "l"(src))
#define CP_COMMIT() asm volatile("cp.async.commit_group;" ::: "memory")
#define CP_WAIT(n)  asm volatile("cp.async.wait_group %0;" :: "n"(n) : "memory")

__device__ __forceinline__ float tf32_rn(float x) {
    return __uint_as_float((__float_as_uint(x) + 0x1000u) & 0xFFFFE000u);
}
__device__ __forceinline__ float bf16_rn(float x) {
    uint32_t u = __float_as_uint(x);
    u += 0x7FFFu + ((u >> 16) & 1u);
    return __uint_as_float(u & 0xFFFF0000u);
}
__device__ __forceinline__ uint32_t pkh(float a, float b) {
    return (__float_as_uint(b) & 0xFFFF0000u) | (__float_as_uint(a) >> 16);
}
__device__ __forceinline__ uint32_t bf2(float a, float b) {
    uint32_t r;
    asm("cvt.rn.bf16x2.f32 %0, %1, %2;" : "=r"(r) : "f"(b), "f"(a));
    return r;
}
__device__ __forceinline__ float fast_exp2(float y) {
    float z = y + 12582912.0f;
    int n = __float_as_int(z) - 0x4B400000;
    float f = y - (z - 12582912.0f);
    float p = 1.3333558146e-3f;
    p = fmaf(p, f, 9.6181291076e-3f);
    p = fmaf(p, f, 5.5504108664e-2f);
    p = fmaf(p, f, 2.4022650696e-1f);
    p = fmaf(p, f, 6.9314718056e-1f);
    p = fmaf(p, f, 1.0f);
    return __int_as_float(__float_as_int(p) + (n << 23));
}
__device__ __forceinline__ void mma8(float* c, const uint32_t* a, const uint32_t* b) {
    asm volatile("mma.sync.aligned.m16n8k8.row.col.f32.tf32.tf32.f32 "
        "{%0,%1,%2,%3},{%4,%5,%6,%7},{%8,%9},{%0,%1,%2,%3};"
        : "+f"(c[0]), "+f"(c[1]), "+f"(c[2]), "+f"(c[3])
        : "r"(a[0]), "r"(a[1]), "r"(a[2]), "r"(a[3]), "r"(b[0]), "r"(b[1]));
}
__device__ __forceinline__ void mma16(float* c, const uint32_t* a, const uint32_t* b) {
    asm volatile("mma.sync.aligned.m16n8k16.row.col.f32.bf16.bf16.f32 "
        "{%0,%1,%2,%3},{%4,%5,%6,%7},{%8,%9},{%0,%1,%2,%3};"
        : "+f"(c[0]), "+f"(c[1]), "+f"(c[2]), "+f"(c[3])
        : "r"(a[0]), "r"(a[1]), "r"(a[2]), "r"(a[3]), "r"(b[0]), "r"(b[1]));
}
__device__ __forceinline__ void ldsm_x4(uint32_t* r, uint32_t addr) {
    asm volatile("ldmatrix.sync.aligned.m8n8.x4.shared.b16 {%0,%1,%2,%3}, [%4];"
        : "=r"(r[0]), "=r"(r[1]), "=r"(r[2]), "=r"(r[3]) : "r"(addr));
}
__device__ __forceinline__ void ldsm_x4_t(uint32_t* r, uint32_t addr) {
    asm volatile("ldmatrix.sync.aligned.m8n8.x4.trans.shared.b16 {%0,%1,%2,%3}, [%4];"
        : "=r"(r[0]), "=r"(r[1]), "=r"(r[2]), "=r"(r[3]) : "r"(addr));
}

// ================= mask detect + bit-pack =================
__global__ void detect_mask_kernel(const unsigned char* __restrict__ m) {
    __shared__ int any;
    if (threadIdx.x == 0) any = 0;
    __syncthreads();
    int found = 0;
    for (int i = threadIdx.x; i < 4096; i += blockDim.x)
        if ((i & 3) == 1 && m[i]) found = 1;
    if (found) atomicOr(&any, 1);
    __syncthreads();
    if (threadIdx.x == 0) g_mask_is_byte = any;
}

__global__ void pack_mask_kernel(const void* __restrict__ m1, const void* __restrict__ m2,
                                 const void* __restrict__ m3) {
    int idx = blockIdx.x * blockDim.x + threadIdx.x;
    if (idx >= 4 * 1024 * 128) return;
    int w = idx & 127, q = (idx >> 7) & 1023, b = idx >> 17;
    int k0 = w * 32;
    const void* mp; int nseg, jl;
    if (k0 < 1024)      { mp = m1; nseg = 1024; jl = k0; }
    else if (k0 < 2048) { mp = m2; nseg = 1024; jl = k0 - 1024; }
    else                { mp = m3; nseg = 2048; jl = k0 - 2048; }
    size_t base = (size_t)(b * 1024 + q) * nseg + jl;
    uint32_t bits = 0;
    if (g_mask_is_byte) {
        const uint4* p = (const uint4*)((const unsigned char*)mp + base);
        uint4 a = p[0], c = p[1];
        uint32_t ws[8] = {a.x, a.y, a.z, a.w, c.x, c.y, c.z, c.w};
#pragma unroll
        for (int wi = 0; wi < 8; ++wi)
#pragma unroll
            for (int by = 0; by < 4; ++by)
                if ((ws[wi] >> (8 * by)) & 0xFFu) bits |= 1u << (wi * 4 + by);
    } else {
        const uint4* p = (const uint4*)((const uint32_t*)mp + base);
#pragma unroll
        for (int wi = 0; wi < 8; ++wi) {
            uint4 v = p[wi];
            if (v.x) bits |= 1u << (wi * 4 + 0);
            if (v.y) bits |= 1u << (wi * 4 + 1);
            if (v.z) bits |= 1u << (wi * 4 + 2);
            if (v.w) bits |= 1u << (wi * 4 + 3);
        }
    }
    g_mbits[idx] = bits;
}

// ================= bf16 hi/lo split (pre-pass) =================
struct SplitJobs {
    const float* src[12];
    int nblk[13];
    int off[12];
};
__global__ __launch_bounds__(256) void split_kernel(SplitJobs j, int njobs) {
    int bid = blockIdx.x;
    int ji = 0;
    while (ji + 1 < njobs && bid >= j.nblk[ji + 1]) ++ji;
    int local = bid - j.nblk[ji];
    const float4* src = (const float4*)j.src[ji];
    uint2* dh = (uint2*)(g_h + j.off[ji]);
    uint2* dl = (uint2*)(g_l + j.off[ji]);
    size_t base4 = (size_t)local * 1024;
#pragma unroll
    for (int it = 0; it < 4; ++it) {
        size_t i4 = base4 + it * 256 + threadIdx.x;
        float4 v = src[i4];
        float h0 = bf16_rn(v.x), h1 = bf16_rn(v.y), h2 = bf16_rn(v.z), h3 = bf16_rn(v.w);
        dh[i4] = make_uint2(pkh(h0, h1), pkh(h2, h3));
        dl[i4] = make_uint2(bf2(v.x - h0, v.y - h1), bf2(v.z - h2, v.w - h3));
    }
}

// ================= 3xBF16 HMMA GEMM, job-table, cp.async 2-stage =================
// Block 128Mx64N, 8 warps (4m x 2n), chunk K=64.
#define G_OAL 4608
#define G_OBH 9216
#define G_OBL 11520
#define G_STW 13824
struct GJobs {
    const uint16_t* Ah[7]; const uint16_t* Al[7];
    const uint16_t* Wh[7]; const uint16_t* Wl[7];
    const float* bias[7];  void* C[7];
    int K[7], Mb[7], rowOff[7], bStride[7], mode[7];
    int blk0[8];
    int njobs;
};
__global__ __launch_bounds__(256, 2) void gemm_jobs(GJobs J) {
    extern __shared__ uint32_t smw[];
    int j = 0;
    while (j + 1 < J.njobs && (int)blockIdx.x >= J.blk0[j + 1]) ++j;
    const int lb = blockIdx.x - J.blk0[j];
    const uint16_t* __restrict__ Ah = J.Ah[j];
    const uint16_t* __restrict__ Al = J.Al[j];
    const uint16_t* __restrict__ Wh = J.Wh[j];
    const uint16_t* __restrict__ Wl = J.Wl[j];
    const float* __restrict__ bias = J.bias[j];
    void* Cv = J.C[j];
    const int K = J.K[j], Mb = J.Mb[j], rowOff = J.rowOff[j];
    const int bStride = J.bStride[j], mode = J.mode[j];

    const int tid = threadIdx.x, lane = tid & 31, wid = tid >> 5;
    const int wm = wid & 3, wn = wid >> 2;
    const int lr = lane >> 2, lc = lane & 3;
    const int m0 = (lb >> 3) * 128, n0 = (lb & 7) * 64;
    const int l16 = lane & 15, lh8 = (lane >> 4) << 3;

    float acc[2][4][4];
#pragma unroll
    for (int i = 0; i < 2; ++i)
#pragma unroll
        for (int jj = 0; jj < 4; ++jj)
#pragma unroll
            for (int e = 0; e < 4; ++e) acc[i][jj][e] = 0.f;

    const int nK = K >> 6;
    const uint32_t ub = smem_u32(smw);

#define STAGE(c, s) do { \
    const uint32_t d0 = ub + (s) * G_STW * 4; \
    _Pragma("unroll") \
    for (int it = 0; it < 4; ++it) { \
        int id = it * 256 + tid, row = id >> 3, seg = id & 7; \
        size_t so = (size_t)(m0 + row) * K + (c) * 64 + seg * 8; \
        uint32_t dw = (row * 36 + seg * 4) * 4; \
        CP16(d0 + dw, Ah + so); \
        CP16(d0 + G_OAL * 4 + dw, Al + so); \
    } \
    _Pragma("unroll") \
    for (int it = 0; it < 2; ++it) { \
        int id = it * 256 + tid, row = id >> 3, seg = id & 7; \
        size_t so = (size_t)((c) * 64 + row) * 512 + n0 + seg * 8; \
        uint32_t dw = (row * 36 + seg * 4) * 4; \
        CP16(d0 + G_OBH * 4 + dw, Wh + so); \
        CP16(d0 + G_OBL * 4 + dw, Wl + so); \
    } \
    CP_COMMIT(); \
} while (0)

    STAGE(0, 0);
    for (int c = 0; c < nK; ++c) {
        const int s = c & 1;
        if (c + 1 < nK) { STAGE(c + 1, s ^ 1); CP_WAIT(1); }
        else            { CP_WAIT(0); }
        __syncthreads();
        const uint32_t sb = ub + s * G_STW * 4;
#pragma unroll
        for (int st = 0; st < 4; ++st) {
            const int k0 = st * 16;
            uint32_t ah[2][4], al_[2][4], bh[2][4], bl_[2][4];
#pragma unroll
            for (int mf = 0; mf < 2; ++mf) {
                int row = wm * 32 + mf * 16 + l16;
                uint32_t ad = sb + (row * 36 + ((k0 + lh8) >> 1)) * 4;
                ldsm_x4(ah[mf], ad);
                ldsm_x4(al_[mf], ad + G_OAL * 4);
            }
#pragma unroll
            for (int p = 0; p < 2; ++p) {
                int row = k0 + l16;
                int col = wn * 32 + p * 16 + lh8;
                uint32_t bd = sb + (G_OBH + row * 36 + (col >> 1)) * 4;
                ldsm_x4_t(bh[p], bd);
                ldsm_x4_t(bl_[p], bd + (G_OBL - G_OBH) * 4);
            }
#pragma unroll
            for (int mf = 0; mf < 2; ++mf)
#pragma unroll
                for (int p = 0; p < 2; ++p) {
                    mma16(acc[mf][p * 2 + 0], ah[mf], &bh[p][0]);
                    mma16(acc[mf][p * 2 + 1], ah[mf], &bh[p][2]);
                    mma16(acc[mf][p * 2 + 0], ah[mf], &bl_[p][0]);
                    mma16(acc[mf][p * 2 + 1], ah[mf], &bl_[p][2]);
                    mma16(acc[mf][p * 2 + 0], al_[mf], &bh[p][0]);
                    mma16(acc[mf][p * 2 + 1], al_[mf], &bh[p][2]);
                }
        }
        __syncthreads();
    }
#undef STAGE
#pragma unroll
    for (int mf = 0; mf < 2; ++mf) {
        int r = m0 + wm * 32 + mf * 16 + lr;
        int b0i = r / Mb;
        size_t or0 = (size_t)b0i * bStride + rowOff + (r - b0i * Mb);
        int r2 = r + 8;
        int b1i = r2 / Mb;
        size_t or1 = (size_t)b1i * bStride + rowOff + (r2 - b1i * Mb);
#pragma unroll
        for (int nf = 0; nf < 4; ++nf) {
            int col = n0 + wn * 32 + nf * 8 + 2 * lc;
            float bv0 = bias[col], bv1 = bias[col + 1];
            float v00 = acc[mf][nf][0] + bv0, v01 = acc[mf][nf][1] + bv1;
            float v10 = acc[mf][nf][2] + bv0, v11 = acc[mf][nf][3] + bv1;
            if (mode == 2) {
                uint16_t* Cb = (uint16_t*)Cv;
                *(uint32_t*)(Cb + or0 * 512 + col) = pkh(bf16_rn(v00), bf16_rn(v01));
                *(uint32_t*)(Cb + or1 * 512 + col) = pkh(bf16_rn(v10), bf16_rn(v11));
            } else {
                float* C = (float*)Cv;
                if (mode == 1) {
                    v00 = tf32_rn(v00); v01 = tf32_rn(v01);
                    v10 = tf32_rn(v10); v11 = tf32_rn(v11);
                }
                *(float2*)(C + or0 * 512 + col) = make_float2(v00, v01);
                *(float2*)(C + or1 * 512 + col) = make_float2(v10, v11);
            }
        }
    }
}

// ================= flash attention: 128q x 64k, single wave =================
// 256 thr = 8 warps (4m x 2n): warp = 32q x 32k (QK) / 32q x 32d (PV).
// smem word offsets
#define A_QW 0
#define A_KW 4608
#define A_VW 9216
#define A_PW 18432
#define A_MW 27136
#define A_LW 27648
#define A_TOTW 27904
#define AV 72
#define AP 68

__global__ __launch_bounds__(256, 2) void attn_mma(
    const uint16_t* __restrict__ qb, const uint16_t* __restrict__ kb,
    const float* __restrict__ vb, float* __restrict__ ob)
{
    extern __shared__ uint32_t smw[];
    float* smf = (float*)smw;
    uint32_t* sM = smw + A_MW;
    float* sP = smf + A_PW;
    float* sL = smf + A_LW;
    const uint32_t* sPu = smw + A_PW;

    const int tid = threadIdx.x, lane = tid & 31, wid = tid >> 5;
    const int wm = wid & 3, wn = wid >> 2;
    const int lr = lane >> 2, lc = lane & 3;
    const int ln8 = lane & 7;
    const int q0 = blockIdx.x * 128, h = blockIdx.y, b = blockIdx.z;

    const uint16_t* Qg = qb + ((size_t)(b * 1024 + q0)) * 512 + h * 64;
    const uint16_t* Kg = kb + ((size_t)(b * 4096)) * 512 + h * 64;
    const float*    Vg = vb + ((size_t)(b * 4096)) * 512 + h * 64;
    const uint32_t* mbase = g_mbits + ((size_t)(b * 1024 + q0)) * 128;
    const uint32_t ubase = smem_u32(smw);
    const uint32_t uQ = ubase + A_QW * 4, uK = ubase + A_KW * 4;
    const uint32_t uV = ubase + A_VW * 4, uM = ubase + A_MW * 4;

    // ---- prologue: Q(128 rows), K(0), V(0), M(0) ----
#pragma unroll
    for (int it = 0; it < 4; ++it) {
        int id = it * 256 + tid, row = id >> 3, seg = id & 7;
        CP16(uQ + (row * 36 + seg * 4) * 4, Qg + (size_t)row * 512 + seg * 8);
    }
#pragma unroll
    for (int it = 0; it < 2; ++it) {
        int id = it * 256 + tid, row = id >> 3, seg = id & 7;
        CP16(uK + (row * 36 + seg * 4) * 4, Kg + (size_t)row * 512 + seg * 8);
    }
#pragma unroll
    for (int it = 0; it < 4; ++it) {
        int id = it * 256 + tid, row = id >> 4, seg = id & 15;
        CP16(uV + (row * AV + seg * 4) * 4, Vg + (size_t)row * 512 + seg * 4);
    }
    if (tid < 128) CP8(uM + tid * 8, (const char*)(mbase + (size_t)tid * 128));
    CP_COMMIT();
    CP_WAIT(0);
    __syncthreads();

    float o[2][4][4];
    float l_acc[2][2];
#pragma unroll
    for (int i = 0; i < 2; ++i) {
        l_acc[i][0] = 0.f; l_acc[i][1] = 0.f;
#pragma unroll
        for (int jj = 0; jj < 4; ++jj)
#pragma unroll
            for (int e = 0; e < 4; ++e) o[i][jj][e] = 0.f;
    }

    for (int t = 0; t < 64; ++t) {
        const int s = t & 1;
        if (t > 0) { CP_WAIT(0); __syncthreads(); }

        // ---- S = Q K^T (bf16 m16n8k16) ----
        const uint32_t uKs = uK + s * 2304 * 4;
        float sv[2][4][4];
#pragma unroll
        for (int i = 0; i < 2; ++i)
#pragma unroll
            for (int jj = 0; jj < 4; ++jj)
#pragma unroll
                for (int e = 0; e < 4; ++e) sv[i][jj][e] = 0.f;
#pragma unroll
        for (int ks = 0; ks < 4; ++ks) {
            int kcb = ks * 16 + ((lane >> 3) & 1) * 8;
            int nrow = wn * 32 + (lane >> 4) * 8 + ln8;
            uint32_t bk0[4], bk1[4];
            ldsm_x4(bk0, uKs + (nrow * 36 + (kcb >> 1)) * 4);
            ldsm_x4(bk1, uKs + ((nrow + 16) * 36 + (kcb >> 1)) * 4);
#pragma unroll
            for (int mf = 0; mf < 2; ++mf) {
                int qrow = wm * 32 + mf * 16 + ((lane >> 3) & 1) * 8 + ln8;
                int kc = ks * 16 + (lane >> 4) * 8;
                uint32_t aq[4];
                ldsm_x4(aq, uQ + (qrow * 36 + (kc >> 1)) * 4);
                mma16(sv[mf][0], aq, &bk0[0]);
                mma16(sv[mf][1], aq, &bk0[2]);
                mma16(sv[mf][2], aq, &bk1[0]);
                mma16(sv[mf][3], aq, &bk1[2]);
            }
        }

        // ---- masked no-max softmax + P write ----
#pragma unroll
        for (int mf = 0; mf < 2; ++mf)
#pragma unroll
            for (int u = 0; u < 2; ++u) {
                int row = wm * 32 + mf * 16 + lr + u * 8;
                uint32_t mw = sM[s * 256 + row * 2 + wn];
                float rs = 0.f;
#pragma unroll
                for (int nf = 0; nf < 4; ++nf) {
#pragma unroll
                    for (int q2 = 0; q2 < 2; ++q2) {
                        int cr = u * 2 + q2;
                        int cl = nf * 8 + 2 * lc + q2;
                        float p = tf32_rn(fast_exp2(sv[mf][nf][cr] * EXP2C));
                        p = ((mw >> cl) & 1u) ? p : 0.f;
                        rs += p;
                        sv[mf][nf][cr] = p;
                    }
                }
                l_acc[mf][u] += rs;
#pragma unroll
                for (int nf = 0; nf < 4; ++nf)
                    *(float2*)(sP + row * AP + wn * 32 + nf * 8 + 2 * lc) =
                        make_float2(sv[mf][nf][u * 2], sv[mf][nf][u * 2 + 1]);
            }
        __syncthreads();   // P visible; K[s], M[s] free

        // ---- stage tile t+1 ----
        if (t < 63) {
            const uint16_t* Kn = Kg + (size_t)(t + 1) * 64 * 512;
            const float* Vn = Vg + (size_t)(t + 1) * 64 * 512;
            const uint32_t dK = uK + (s ^ 1) * 2304 * 4;
            const uint32_t dV = uV + (s ^ 1) * 64 * AV * 4;
#pragma unroll
            for (int it = 0; it < 2; ++it) {
                int id = it * 256 + tid, row = id >> 3, seg = id & 7;
                CP16(dK + (row * 36 + seg * 4) * 4, Kn + (size_t)row * 512 + seg * 8);
            }
#pragma unroll
            for (int it = 0; it < 4; ++it) {
                int id = it * 256 + tid, row = id >> 4, seg = id & 15;
                CP16(dV + (row * AV + seg * 4) * 4, Vn + (size_t)row * 512 + seg * 4);
            }
            if (tid < 128)
                CP8(uM + (s ^ 1) * 1024 + tid * 8,
                    (const char*)(mbase + (size_t)tid * 128 + (t + 1) * 2));
            CP_COMMIT();
        }

        // ---- O += P @ V (tf32 m16n8k8) ----
        const uint32_t* sVu = smw + A_VW + s * 64 * AV;
#pragma unroll
        for (int ks = 0; ks < 8; ++ks) {
            const int kb0 = ks * 8;
            uint32_t bv[4][2];
#pragma unroll
            for (int nf = 0; nf < 4; ++nf) {
                int drow = wn * 32 + nf * 8 + lr;
                bv[nf][0] = sVu[(kb0 + lc) * AV + drow];
                bv[nf][1] = sVu[(kb0 + 4 + lc) * AV + drow];
            }
#pragma unroll
            for (int mf = 0; mf < 2; ++mf) {
                int ar = wm * 32 + mf * 16 + lr;
                uint32_t ap[4] = {sPu[ar * AP + kb0 + lc], sPu[(ar + 8) * AP + kb0 + lc],
                                  sPu[ar * AP + kb0 + 4 + lc], sPu[(ar + 8) * AP + kb0 + 4 + lc]};
#pragma unroll
                for (int nf = 0; nf < 4; ++nf) mma8(o[mf][nf], ap, bv[nf]);
            }
        }
    }

    // ---- l reduce: quads, then the 2 n-warps via smem ----
#pragma unroll
    for (int mf = 0; mf < 2; ++mf)
#pragma unroll
        for (int u = 0; u < 2; ++u) {
            float v = l_acc[mf][u];
            v += __shfl_xor_sync(0xffffffffu, v, 1);
            v += __shfl_xor_sync(0xffffffffu, v, 2);
            l_acc[mf][u] = v;
        }
    if (lc == 0) {
#pragma unroll
        for (int mf = 0; mf < 2; ++mf)
#pragma unroll
            for (int u = 0; u < 2; ++u)
                sL[wn * 128 + wm * 32 + mf * 16 + lr + u * 8] = l_acc[mf][u];
    }
    __syncthreads();

    float* Og = ob + ((size_t)(b * 1024 + q0)) * 512 + h * 64;
#pragma unroll
    for (int mf = 0; mf < 2; ++mf)
#pragma unroll
        for (int u = 0; u < 2; ++u) {
            int row = wm * 32 + mf * 16 + lr + u * 8;
            float linv = 1.f / (sL[row] + sL[128 + row]);
#pragma unroll
            for (int nf = 0; nf < 4; ++nf) {
                int col = wn * 32 + nf * 8 + 2 * lc;
                *(float2*)(Og + (size_t)row * 512 + col) =
                    make_float2(o[mf][nf][u * 2] * linv, o[mf][nf][u * 2 + 1] * linv);
            }
        }
}

// ================= launcher =================
extern "C" void kernel_launch(void* const* d_in, const int* in_sizes, int n_in,
                              void* d_out, int out_size) {
    const float* x        = (const float*)d_in[0];
    const float* context  = (const float*)d_in[1];
    const float* context2 = (const float*)d_in[2];
    const float* context3 = (const float*)d_in[3];
    const void*  mask1 = d_in[4];
    const void*  mask2 = d_in[5];
    const void*  mask3 = d_in[6];
    const float* bq  = (const float*)d_in[8];
    const float* bk1 = (const float*)d_in[10];
    const float* bv1 = (const float*)d_in[12];
    const float* bk2 = (const float*)d_in[14];
    const float* bv2 = (const float*)d_in[16];
    const float* bk3 = (const float*)d_in[18];
    const float* bv3 = (const float*)d_in[20];
    const float* Wo  = (const float*)d_in[21];
    const float* bo  = (const float*)d_in[22];
    float* out = (float*)d_out;

    uint16_t *hp, *lp, *qbp, *kbp;
    float *vp, *aop;
    cudaGetSymbolAddress((void**)&hp,  g_h);
    cudaGetSymbolAddress((void**)&lp,  g_l);
    cudaGetSymbolAddress((void**)&qbp, g_qb);
    cudaGetSymbolAddress((void**)&kbp, g_kb);
    cudaGetSymbolAddress((void**)&vp,  g_v);
    cudaGetSymbolAddress((void**)&aop, g_ao);

    const int smem_gemm = 2 * G_STW * 4;    // 110592
    const int smem_attn = A_TOTW * 4;       // 111616
    static bool once = false;
    if (!once) {
        cudaFuncSetAttribute(gemm_jobs, cudaFuncAttributeMaxDynamicSharedMemorySize, smem_gemm);
        cudaFuncSetAttribute(attn_mma, cudaFuncAttributeMaxDynamicSharedMemorySize, smem_attn);
        once = true;
    }

    detect_mask_kernel<<<1, 256>>>((const unsigned char*)mask1);
    pack_mask_kernel<<<2048, 256>>>(mask1, mask2, mask3);

    // pre-split inputs + weights into bf16 h/l planes
    {
        SplitJobs js;
        const float* srcs[12] = {x, context, context2, context3,
                                 (const float*)d_in[7], (const float*)d_in[9],
                                 (const float*)d_in[11], (const float*)d_in[13],
                                 (const float*)d_in[15], (const float*)d_in[17],
                                 (const float*)d_in[19], Wo};
        int offs[12] = {OFF_X, OFF_C1, OFF_C2, OFF_C3,
                        OFF_WQ, OFF_WK1, OFF_WV1, OFF_WK2, OFF_WV2,
                        OFF_WK3, OFF_WV3, OFF_WO};
        int cnts[12] = {512, 512, 768, 512, 64, 64, 64, 96, 96, 32, 32, 64};
        int cum = 0;
        for (int i = 0; i < 12; ++i) {
            js.src[i] = srcs[i]; js.off[i] = offs[i];
            js.nblk[i] = cum; cum += cnts[i];
        }
        js.nblk[12] = cum;
        split_kernel<<<cum, 256>>>(js, 12);
    }

    // merged projection GEMMs (7 jobs, one launch)
    {
        GJobs J;
        int aoffs[7]  = {OFF_X, OFF_C1, OFF_C2, OFF_C3, OFF_C1, OFF_C2, OFF_C3};
        int woffs[7]  = {OFF_WQ, OFF_WK1, OFF_WK2, OFF_WK3, OFF_WV1, OFF_WV2, OFF_WV3};
        const float* biases[7] = {bq, bk1, bk2, bk3, bv1, bv2, bv3};
        void* Cs[7]   = {qbp, kbp, kbp, kbp, vp, vp, vp};
        int Ks[7]     = {512, 512, 768, 256, 512, 768, 256};
        int Mbs[7]    = {1024, 1024, 1024, 2048, 1024, 1024, 2048};
        int ros[7]    = {0, 0, 1024, 2048, 0, 1024, 2048};
        int bss[7]    = {1024, 4096, 4096, 4096, 4096, 4096, 4096};
        int modes[7]  = {2, 2, 2, 2, 1, 1, 1};
        int blks[7]   = {256, 256, 256, 512, 256, 256, 512};
        int cum = 0;
        for (int i = 0; i < 7; ++i) {
            J.Ah[i] = hp + aoffs[i]; J.Al[i] = lp + aoffs[i];
            J.Wh[i] = hp + woffs[i]; J.Wl[i] = lp + woffs[i];
            J.bias[i] = biases[i]; J.C[i] = Cs[i];
            J.K[i] = Ks[i]; J.Mb[i] = Mbs[i]; J.rowOff[i] = ros[i];
            J.bStride[i] = bss[i]; J.mode[i] = modes[i];
            J.blk0[i] = cum; cum += blks[i];
        }
        J.blk0[7] = cum; J.njobs = 7;
        gemm_jobs<<<cum, 256, smem_gemm>>>(J);
    }

    attn_mma<<<dim3(8, 8, 4), 256, smem_attn>>>(qbp, kbp, vp, aop);

    // split attention output, then final projection -> d_out
    {
        SplitJobs ja;
        ja.src[0] = aop; ja.off[0] = OFF_AO;
        ja.nblk[0] = 0; ja.nblk[1] = 512;
        split_kernel<<<512, 256>>>(ja, 1);
    }
    {
        GJobs J;
        J.Ah[0] = hp + OFF_AO; J.Al[0] = lp + OFF_AO;
        J.Wh[0] = hp + OFF_WO; J.Wl[0] = lp + OFF_WO;
        J.bias[0] = bo; J.C[0] = out;
        J.K[0] = 512; J.Mb[0] = 1024; J.rowOff[0] = 0;
        J.bStride[0] = 1024; J.mode[0] = 0;
        J.blk0[0] = 0; J.blk0[1] = 256; J.njobs = 1;
        gemm_jobs<<<256, 256, smem_gemm>>>(J);
    }
}

// round 10
// speedup vs baseline: 5.4601x; 1.0659x over previous
#include <cuda_runtime.h>
#include <cstdint>

#define EXP2C 0.1803368801111204f   /* (1/8) * log2(e) */

// ================= pools / scratch =================
#define OFF_X   0
#define OFF_C1  2097152
#define OFF_C2  4194304
#define OFF_C3  7340032
#define OFF_AO  9437184
#define OFF_WQ  11534336
#define OFF_WK1 11796480
#define OFF_WV1 12058624
#define OFF_WK2 12320768
#define OFF_WV2 12713984
#define OFF_WK3 13107200
#define OFF_WV3 13238272
#define OFF_WO  13369344
#define POOL_N  13631488

__device__ uint16_t g_h[POOL_N];
__device__ uint16_t g_l[POOL_N];
__device__ uint16_t g_qb[4 * 1024 * 512];
__device__ uint16_t g_kb[4 * 4096 * 512];
__device__ float    g_v[4 * 4096 * 512];
__device__ uint32_t g_mbits[4 * 1024 * 128];
__device__ int      g_mask_is_byte;

// ================= helpers =================
__device__ __forceinline__ uint32_t smem_u32(const void* p) {
    uint32_t a;
    asm("{ .reg .u64 t; cvta.to.shared.u64 t, %1; cvt.u32.u64 %0, t; }" : "=r"(a) : "l"(p));
    return a;
}
#define CP16(dst, src) \
    asm volatile("cp.async.cg.shared.global [%0], [%1], 16;" :: "r"(dst), "l"(src))
#define CP8(dst, src) \
    asm volatile("cp.async.ca.shared.global [%0], [%1], 8;" :: "r"(dst), "l"(src))
#define CP_COMMIT() asm volatile("cp.async.commit_group;" ::: "memory")
#define CP_WAIT(n)  asm volatile("cp.async.wait_group %0;" :: "n"(n) : "memory")

__device__ __forceinline__ float tf32_rn(float x) {
    return __uint_as_float((__float_as_uint(x) + 0x1000u) & 0xFFFFE000u);
}
__device__ __forceinline__ float bf16_rn(float x) {
    uint32_t u = __float_as_uint(x);
    u += 0x7FFFu + ((u >> 16) & 1u);
    return __uint_as_float(u & 0xFFFF0000u);
}
__device__ __forceinline__ uint32_t pkh(float a, float b) {
    return (__float_as_uint(b) & 0xFFFF0000u) | (__float_as_uint(a) >> 16);
}
__device__ __forceinline__ uint32_t bf2(float a, float b) {
    uint32_t r;
    asm("cvt.rn.bf16x2.f32 %0, %1, %2;" : "=r"(r) : "f"(b), "f"(a));
    return r;
}
__device__ __forceinline__ float ex2f(float y) {
    float r;
    asm("ex2.approx.f32 %0, %1;" : "=f"(r) : "f"(y));
    return r;
}
__device__ __forceinline__ void mma8(float* c, const uint32_t* a, const uint32_t* b) {
    asm volatile("mma.sync.aligned.m16n8k8.row.col.f32.tf32.tf32.f32 "
        "{%0,%1,%2,%3},{%4,%5,%6,%7},{%8,%9},{%0,%1,%2,%3};"
        : "+f"(c[0]), "+f"(c[1]), "+f"(c[2]), "+f"(c[3])
        : "r"(a[0]), "r"(a[1]), "r"(a[2]), "r"(a[3]), "r"(b[0]), "r"(b[1]));
}
__device__ __forceinline__ void mma16(float* c, const uint32_t* a, const uint32_t* b) {
    asm volatile("mma.sync.aligned.m16n8k16.row.col.f32.bf16.bf16.f32 "
        "{%0,%1,%2,%3},{%4,%5,%6,%7},{%8,%9},{%0,%1,%2,%3};"
        : "+f"(c[0]), "+f"(c[1]), "+f"(c[2]), "+f"(c[3])
        : "r"(a[0]), "r"(a[1]), "r"(a[2]), "r"(a[3]), "r"(b[0]), "r"(b[1]));
}
__device__ __forceinline__ void ldsm_x4(uint32_t* r, uint32_t addr) {
    asm volatile("ldmatrix.sync.aligned.m8n8.x4.shared.b16 {%0,%1,%2,%3}, [%4];"
        : "=r"(r[0]), "=r"(r[1]), "=r"(r[2]), "=r"(r[3]) : "r"(addr));
}
__device__ __forceinline__ void ldsm_x4_t(uint32_t* r, uint32_t addr) {
    asm volatile("ldmatrix.sync.aligned.m8n8.x4.trans.shared.b16 {%0,%1,%2,%3}, [%4];"
        : "=r"(r[0]), "=r"(r[1]), "=r"(r[2]), "=r"(r[3]) : "r"(addr));
}

// ================= mask detect + bit-pack =================
__global__ void detect_mask_kernel(const unsigned char* __restrict__ m) {
    __shared__ int any;
    if (threadIdx.x == 0) any = 0;
    __syncthreads();
    int found = 0;
    for (int i = threadIdx.x; i < 4096; i += blockDim.x)
        if ((i & 3) == 1 && m[i]) found = 1;
    if (found) atomicOr(&any, 1);
    __syncthreads();
    if (threadIdx.x == 0) g_mask_is_byte = any;
}

__global__ void pack_mask_kernel(const void* __restrict__ m1, const void* __restrict__ m2,
                                 const void* __restrict__ m3) {
    int idx = blockIdx.x * blockDim.x + threadIdx.x;
    if (idx >= 4 * 1024 * 128) return;
    int w = idx & 127, q = (idx >> 7) & 1023, b = idx >> 17;
    int k0 = w * 32;
    const void* mp; int nseg, jl;
    if (k0 < 1024)      { mp = m1; nseg = 1024; jl = k0; }
    else if (k0 < 2048) { mp = m2; nseg = 1024; jl = k0 - 1024; }
    else                { mp = m3; nseg = 2048; jl = k0 - 2048; }
    size_t base = (size_t)(b * 1024 + q) * nseg + jl;
    uint32_t bits = 0;
    if (g_mask_is_byte) {
        const uint4* p = (const uint4*)((const unsigned char*)mp + base);
        uint4 a = p[0], c = p[1];
        uint32_t ws[8] = {a.x, a.y, a.z, a.w, c.x, c.y, c.z, c.w};
#pragma unroll
        for (int wi = 0; wi < 8; ++wi)
#pragma unroll
            for (int by = 0; by < 4; ++by)
                if ((ws[wi] >> (8 * by)) & 0xFFu) bits |= 1u << (wi * 4 + by);
    } else {
        const uint4* p = (const uint4*)((const uint32_t*)mp + base);
#pragma unroll
        for (int wi = 0; wi < 8; ++wi) {
            uint4 v = p[wi];
            if (v.x) bits |= 1u << (wi * 4 + 0);
            if (v.y) bits |= 1u << (wi * 4 + 1);
            if (v.z) bits |= 1u << (wi * 4 + 2);
            if (v.w) bits |= 1u << (wi * 4 + 3);
        }
    }
    g_mbits[idx] = bits;
}

// ================= bf16 hi/lo split (pre-pass) =================
struct SplitJobs {
    const float* src[12];
    int nblk[13];
    int off[12];
};
__global__ __launch_bounds__(256) void split_kernel(SplitJobs j, int njobs) {
    int bid = blockIdx.x;
    int ji = 0;
    while (ji + 1 < njobs && bid >= j.nblk[ji + 1]) ++ji;
    int local = bid - j.nblk[ji];
    const float4* src = (const float4*)j.src[ji];
    uint2* dh = (uint2*)(g_h + j.off[ji]);
    uint2* dl = (uint2*)(g_l + j.off[ji]);
    size_t base4 = (size_t)local * 1024;
#pragma unroll
    for (int it = 0; it < 4; ++it) {
        size_t i4 = base4 + it * 256 + threadIdx.x;
        float4 v = src[i4];
        float h0 = bf16_rn(v.x), h1 = bf16_rn(v.y), h2 = bf16_rn(v.z), h3 = bf16_rn(v.w);
        dh[i4] = make_uint2(pkh(h0, h1), pkh(h2, h3));
        dl[i4] = make_uint2(bf2(v.x - h0, v.y - h1), bf2(v.z - h2, v.w - h3));
    }
}

// ================= 3xBF16 HMMA GEMM, job-table, cp.async 2-stage =================
// Block 128Mx64N, 8 warps (4m x 2n), chunk K=64.
#define G_OAL 4608
#define G_OBH 9216
#define G_OBL 11520
#define G_STW 13824
struct GJobs {
    const uint16_t* Ah[7]; const uint16_t* Al[7];
    const uint16_t* Wh[7]; const uint16_t* Wl[7];
    const float* bias[7];  void* C[7];
    int K[7], Mb[7], rowOff[7], bStride[7], mode[7];
    int blk0[8];
    int njobs;
};
// mode: 0 = fp32 out, 1 = tf32-rounded fp32 out, 2 = bf16 out, 4 = bf16 out scaled by EXP2C
__global__ __launch_bounds__(256, 2) void gemm_jobs(GJobs J) {
    extern __shared__ uint32_t smw[];
    int j = 0;
    while (j + 1 < J.njobs && (int)blockIdx.x >= J.blk0[j + 1]) ++j;
    const int lb = blockIdx.x - J.blk0[j];
    const uint16_t* __restrict__ Ah = J.Ah[j];
    const uint16_t* __restrict__ Al = J.Al[j];
    const uint16_t* __restrict__ Wh = J.Wh[j];
    const uint16_t* __restrict__ Wl = J.Wl[j];
    const float* __restrict__ bias = J.bias[j];
    void* Cv = J.C[j];
    const int K = J.K[j], Mb = J.Mb[j], rowOff = J.rowOff[j];
    const int bStride = J.bStride[j], mode = J.mode[j];

    const int tid = threadIdx.x, lane = tid & 31, wid = tid >> 5;
    const int wm = wid & 3, wn = wid >> 2;
    const int lr = lane >> 2, lc = lane & 3;
    const int m0 = (lb >> 3) * 128, n0 = (lb & 7) * 64;
    const int l16 = lane & 15, lh8 = (lane >> 4) << 3;

    float acc[2][4][4];
#pragma unroll
    for (int i = 0; i < 2; ++i)
#pragma unroll
        for (int jj = 0; jj < 4; ++jj)
#pragma unroll
            for (int e = 0; e < 4; ++e) acc[i][jj][e] = 0.f;

    const int nK = K >> 6;
    const uint32_t ub = smem_u32(smw);

#define STAGE(c, s) do { \
    const uint32_t d0 = ub + (s) * G_STW * 4; \
    _Pragma("unroll") \
    for (int it = 0; it < 4; ++it) { \
        int id = it * 256 + tid, row = id >> 3, seg = id & 7; \
        size_t so = (size_t)(m0 + row) * K + (c) * 64 + seg * 8; \
        uint32_t dw = (row * 36 + seg * 4) * 4; \
        CP16(d0 + dw, Ah + so); \
        CP16(d0 + G_OAL * 4 + dw, Al + so); \
    } \
    _Pragma("unroll") \
    for (int it = 0; it < 2; ++it) { \
        int id = it * 256 + tid, row = id >> 3, seg = id & 7; \
        size_t so = (size_t)((c) * 64 + row) * 512 + n0 + seg * 8; \
        uint32_t dw = (row * 36 + seg * 4) * 4; \
        CP16(d0 + G_OBH * 4 + dw, Wh + so); \
        CP16(d0 + G_OBL * 4 + dw, Wl + so); \
    } \
    CP_COMMIT(); \
} while (0)

    STAGE(0, 0);
    for (int c = 0; c < nK; ++c) {
        const int s = c & 1;
        if (c + 1 < nK) { STAGE(c + 1, s ^ 1); CP_WAIT(1); }
        else            { CP_WAIT(0); }
        __syncthreads();
        const uint32_t sb = ub + s * G_STW * 4;
#pragma unroll
        for (int st = 0; st < 4; ++st) {
            const int k0 = st * 16;
            uint32_t ah[2][4], al_[2][4], bh[2][4], bl_[2][4];
#pragma unroll
            for (int mf = 0; mf < 2; ++mf) {
                int row = wm * 32 + mf * 16 + l16;
                uint32_t ad = sb + (row * 36 + ((k0 + lh8) >> 1)) * 4;
                ldsm_x4(ah[mf], ad);
                ldsm_x4(al_[mf], ad + G_OAL * 4);
            }
#pragma unroll
            for (int p = 0; p < 2; ++p) {
                int row = k0 + l16;
                int col = wn * 32 + p * 16 + lh8;
                uint32_t bd = sb + (G_OBH + row * 36 + (col >> 1)) * 4;
                ldsm_x4_t(bh[p], bd);
                ldsm_x4_t(bl_[p], bd + (G_OBL - G_OBH) * 4);
            }
#pragma unroll
            for (int mf = 0; mf < 2; ++mf)
#pragma unroll
                for (int p = 0; p < 2; ++p) {
                    mma16(acc[mf][p * 2 + 0], ah[mf], &bh[p][0]);
                    mma16(acc[mf][p * 2 + 1], ah[mf], &bh[p][2]);
                    mma16(acc[mf][p * 2 + 0], ah[mf], &bl_[p][0]);
                    mma16(acc[mf][p * 2 + 1], ah[mf], &bl_[p][2]);
                    mma16(acc[mf][p * 2 + 0], al_[mf], &bh[p][0]);
                    mma16(acc[mf][p * 2 + 1], al_[mf], &bh[p][2]);
                }
        }
        __syncthreads();
    }
#undef STAGE
#pragma unroll
    for (int mf = 0; mf < 2; ++mf) {
        int r = m0 + wm * 32 + mf * 16 + lr;
        int b0i = r / Mb;
        size_t or0 = (size_t)b0i * bStride + rowOff + (r - b0i * Mb);
        int r2 = r + 8;
        int b1i = r2 / Mb;
        size_t or1 = (size_t)b1i * bStride + rowOff + (r2 - b1i * Mb);
#pragma unroll
        for (int nf = 0; nf < 4; ++nf) {
            int col = n0 + wn * 32 + nf * 8 + 2 * lc;
            float bv0 = bias[col], bv1 = bias[col + 1];
            float v00 = acc[mf][nf][0] + bv0, v01 = acc[mf][nf][1] + bv1;
            float v10 = acc[mf][nf][2] + bv0, v11 = acc[mf][nf][3] + bv1;
            if (mode >= 2) {
                if (mode == 4) { v00 *= EXP2C; v01 *= EXP2C; v10 *= EXP2C; v11 *= EXP2C; }
                uint16_t* Cb = (uint16_t*)Cv;
                *(uint32_t*)(Cb + or0 * 512 + col) = pkh(bf16_rn(v00), bf16_rn(v01));
                *(uint32_t*)(Cb + or1 * 512 + col) = pkh(bf16_rn(v10), bf16_rn(v11));
            } else {
                float* C = (float*)Cv;
                if (mode == 1) {
                    v00 = tf32_rn(v00); v01 = tf32_rn(v01);
                    v10 = tf32_rn(v10); v11 = tf32_rn(v11);
                }
                *(float2*)(C + or0 * 512 + col) = make_float2(v00, v01);
                *(float2*)(C + or1 * 512 + col) = make_float2(v10, v11);
            }
        }
    }
}

// ================= flash attention: 128q x 64k, Q pre-scaled, MUFU exp =================
// 256 thr = 8 warps (4m x 2n). Output written as bf16 h/l planes (skips split pass).
#define A_QW 0
#define A_KW 4608
#define A_VW 9216
#define A_PW 18432
#define A_MW 27136
#define A_LW 27648
#define A_TOTW 27904
#define AV 72
#define AP 68

__global__ __launch_bounds__(256, 2) void attn_mma(
    const uint16_t* __restrict__ qb, const uint16_t* __restrict__ kb,
    const float* __restrict__ vb,
    uint16_t* __restrict__ oh, uint16_t* __restrict__ ol)
{
    extern __shared__ uint32_t smw[];
    float* smf = (float*)smw;
    uint32_t* sM = smw + A_MW;
    float* sP = smf + A_PW;
    float* sL = smf + A_LW;
    const uint32_t* sPu = smw + A_PW;

    const int tid = threadIdx.x, lane = tid & 31, wid = tid >> 5;
    const int wm = wid & 3, wn = wid >> 2;
    const int lr = lane >> 2, lc = lane & 3;
    const int ln8 = lane & 7;
    const int q0 = blockIdx.x * 128, h = blockIdx.y, b = blockIdx.z;

    const uint16_t* Qg = qb + ((size_t)(b * 1024 + q0)) * 512 + h * 64;
    const uint16_t* Kg = kb + ((size_t)(b * 4096)) * 512 + h * 64;
    const float*    Vg = vb + ((size_t)(b * 4096)) * 512 + h * 64;
    const uint32_t* mbase = g_mbits + ((size_t)(b * 1024 + q0)) * 128;
    const uint32_t ubase = smem_u32(smw);
    const uint32_t uQ = ubase + A_QW * 4, uK = ubase + A_KW * 4;
    const uint32_t uV = ubase + A_VW * 4, uM = ubase + A_MW * 4;

    // ---- prologue: Q(128 rows), K(0), V(0), M(0) ----
#pragma unroll
    for (int it = 0; it < 4; ++it) {
        int id = it * 256 + tid, row = id >> 3, seg = id & 7;
        CP16(uQ + (row * 36 + seg * 4) * 4, Qg + (size_t)row * 512 + seg * 8);
    }
#pragma unroll
    for (int it = 0; it < 2; ++it) {
        int id = it * 256 + tid, row = id >> 3, seg = id & 7;
        CP16(uK + (row * 36 + seg * 4) * 4, Kg + (size_t)row * 512 + seg * 8);
    }
#pragma unroll
    for (int it = 0; it < 4; ++it) {
        int id = it * 256 + tid, row = id >> 4, seg = id & 15;
        CP16(uV + (row * AV + seg * 4) * 4, Vg + (size_t)row * 512 + seg * 4);
    }
    if (tid < 128) CP8(uM + tid * 8, (const char*)(mbase + (size_t)tid * 128));
    CP_COMMIT();
    CP_WAIT(0);
    __syncthreads();

    float o[2][4][4];
    float l_acc[2][2];
#pragma unroll
    for (int i = 0; i < 2; ++i) {
        l_acc[i][0] = 0.f; l_acc[i][1] = 0.f;
#pragma unroll
        for (int jj = 0; jj < 4; ++jj)
#pragma unroll
            for (int e = 0; e < 4; ++e) o[i][jj][e] = 0.f;
    }

    for (int t = 0; t < 64; ++t) {
        const int s = t & 1;
        if (t > 0) { CP_WAIT(0); __syncthreads(); }

        // ---- S' = (Q*EXP2C) K^T (bf16 m16n8k16); exponent-ready ----
        const uint32_t uKs = uK + s * 2304 * 4;
        float sv[2][4][4];
#pragma unroll
        for (int i = 0; i < 2; ++i)
#pragma unroll
            for (int jj = 0; jj < 4; ++jj)
#pragma unroll
                for (int e = 0; e < 4; ++e) sv[i][jj][e] = 0.f;
#pragma unroll
        for (int ks = 0; ks < 4; ++ks) {
            int kcb = ks * 16 + ((lane >> 3) & 1) * 8;
            int nrow = wn * 32 + (lane >> 4) * 8 + ln8;
            uint32_t bk0[4], bk1[4];
            ldsm_x4(bk0, uKs + (nrow * 36 + (kcb >> 1)) * 4);
            ldsm_x4(bk1, uKs + ((nrow + 16) * 36 + (kcb >> 1)) * 4);
#pragma unroll
            for (int mf = 0; mf < 2; ++mf) {
                int qrow = wm * 32 + mf * 16 + ((lane >> 3) & 1) * 8 + ln8;
                int kc = ks * 16 + (lane >> 4) * 8;
                uint32_t aq[4];
                ldsm_x4(aq, uQ + (qrow * 36 + (kc >> 1)) * 4);
                mma16(sv[mf][0], aq, &bk0[0]);
                mma16(sv[mf][1], aq, &bk0[2]);
                mma16(sv[mf][2], aq, &bk1[0]);
                mma16(sv[mf][3], aq, &bk1[2]);
            }
        }

        // ---- masked no-max softmax (MUFU ex2) + P write ----
#pragma unroll
        for (int mf = 0; mf < 2; ++mf)
#pragma unroll
            for (int u = 0; u < 2; ++u) {
                int row = wm * 32 + mf * 16 + lr + u * 8;
                uint32_t mw = sM[s * 256 + row * 2 + wn];
                float rs = 0.f;
#pragma unroll
                for (int nf = 0; nf < 4; ++nf) {
#pragma unroll
                    for (int q2 = 0; q2 < 2; ++q2) {
                        int cr = u * 2 + q2;
                        int cl = nf * 8 + 2 * lc + q2;
                        float p = tf32_rn(ex2f(sv[mf][nf][cr]));
                        p = ((mw >> cl) & 1u) ? p : 0.f;
                        rs += p;
                        sv[mf][nf][cr] = p;
                    }
                }
                l_acc[mf][u] += rs;
#pragma unroll
                for (int nf = 0; nf < 4; ++nf)
                    *(float2*)(sP + row * AP + wn * 32 + nf * 8 + 2 * lc) =
                        make_float2(sv[mf][nf][u * 2], sv[mf][nf][u * 2 + 1]);
            }
        __syncthreads();   // P visible; K[s], M[s] free

        // ---- stage tile t+1 ----
        if (t < 63) {
            const uint16_t* Kn = Kg + (size_t)(t + 1) * 64 * 512;
            const float* Vn = Vg + (size_t)(t + 1) * 64 * 512;
            const uint32_t dK = uK + (s ^ 1) * 2304 * 4;
            const uint32_t dV = uV + (s ^ 1) * 64 * AV * 4;
#pragma unroll
            for (int it = 0; it < 2; ++it) {
                int id = it * 256 + tid, row = id >> 3, seg = id & 7;
                CP16(dK + (row * 36 + seg * 4) * 4, Kn + (size_t)row * 512 + seg * 8);
            }
#pragma unroll
            for (int it = 0; it < 4; ++it) {
                int id = it * 256 + tid, row = id >> 4, seg = id & 15;
                CP16(dV + (row * AV + seg * 4) * 4, Vn + (size_t)row * 512 + seg * 4);
            }
            if (tid < 128)
                CP8(uM + (s ^ 1) * 1024 + tid * 8,
                    (const char*)(mbase + (size_t)tid * 128 + (t + 1) * 2));
            CP_COMMIT();
        }

        // ---- O += P @ V (tf32 m16n8k8) ----
        const uint32_t* sVu = smw + A_VW + s * 64 * AV;
#pragma unroll
        for (int ks = 0; ks < 8; ++ks) {
            const int kb0 = ks * 8;
            uint32_t bv[4][2];
#pragma unroll
            for (int nf = 0; nf < 4; ++nf) {
                int drow = wn * 32 + nf * 8 + lr;
                bv[nf][0] = sVu[(kb0 + lc) * AV + drow];
                bv[nf][1] = sVu[(kb0 + 4 + lc) * AV + drow];
            }
#pragma unroll
            for (int mf = 0; mf < 2; ++mf) {
                int ar = wm * 32 + mf * 16 + lr;
                uint32_t ap[4] = {sPu[ar * AP + kb0 + lc], sPu[(ar + 8) * AP + kb0 + lc],
                                  sPu[ar * AP + kb0 + 4 + lc], sPu[(ar + 8) * AP + kb0 + 4 + lc]};
#pragma unroll
                for (int nf = 0; nf < 4; ++nf) mma8(o[mf][nf], ap, bv[nf]);
            }
        }
    }

    // ---- l reduce: quads, then the 2 n-warps via smem ----
#pragma unroll
    for (int mf = 0; mf < 2; ++mf)
#pragma unroll
        for (int u = 0; u < 2; ++u) {
            float v = l_acc[mf][u];
            v += __shfl_xor_sync(0xffffffffu, v, 1);
            v += __shfl_xor_sync(0xffffffffu, v, 2);
            l_acc[mf][u] = v;
        }
    if (lc == 0) {
#pragma unroll
        for (int mf = 0; mf < 2; ++mf)
#pragma unroll
            for (int u = 0; u < 2; ++u)
                sL[wn * 128 + wm * 32 + mf * 16 + lr + u * 8] = l_acc[mf][u];
    }
    __syncthreads();

    // normalize + write bf16 h/l planes (feeds final projection directly)
    uint16_t* Oh = oh + ((size_t)(b * 1024 + q0)) * 512 + h * 64;
    uint16_t* Ol = ol + ((size_t)(b * 1024 + q0)) * 512 + h * 64;
#pragma unroll
    for (int mf = 0; mf < 2; ++mf)
#pragma unroll
        for (int u = 0; u < 2; ++u) {
            int row = wm * 32 + mf * 16 + lr + u * 8;
            float linv = 1.f / (sL[row] + sL[128 + row]);
#pragma unroll
            for (int nf = 0; nf < 4; ++nf) {
                int col = wn * 32 + nf * 8 + 2 * lc;
                float v0 = o[mf][nf][u * 2] * linv;
                float v1 = o[mf][nf][u * 2 + 1] * linv;
                float h0 = bf16_rn(v0), h1 = bf16_rn(v1);
                *(uint32_t*)(Oh + (size_t)row * 512 + col) = pkh(h0, h1);
                *(uint32_t*)(Ol + (size_t)row * 512 + col) = bf2(v0 - h0, v1 - h1);
            }
        }
}

// ================= launcher =================
extern "C" void kernel_launch(void* const* d_in, const int* in_sizes, int n_in,
                              void* d_out, int out_size) {
    const float* x        = (const float*)d_in[0];
    const float* context  = (const float*)d_in[1];
    const float* context2 = (const float*)d_in[2];
    const float* context3 = (const float*)d_in[3];
    const void*  mask1 = d_in[4];
    const void*  mask2 = d_in[5];
    const void*  mask3 = d_in[6];
    const float* bq  = (const float*)d_in[8];
    const float* bk1 = (const float*)d_in[10];
    const float* bv1 = (const float*)d_in[12];
    const float* bk2 = (const float*)d_in[14];
    const float* bv2 = (const float*)d_in[16];
    const float* bk3 = (const float*)d_in[18];
    const float* bv3 = (const float*)d_in[20];
    const float* Wo  = (const float*)d_in[21];
    const float* bo  = (const float*)d_in[22];
    float* out = (float*)d_out;

    uint16_t *hp, *lp, *qbp, *kbp;
    float *vp;
    cudaGetSymbolAddress((void**)&hp,  g_h);
    cudaGetSymbolAddress((void**)&lp,  g_l);
    cudaGetSymbolAddress((void**)&qbp, g_qb);
    cudaGetSymbolAddress((void**)&kbp, g_kb);
    cudaGetSymbolAddress((void**)&vp,  g_v);

    const int smem_gemm = 2 * G_STW * 4;    // 110592
    const int smem_attn = A_TOTW * 4;       // 111616
    static bool once = false;
    if (!once) {
        cudaFuncSetAttribute(gemm_jobs, cudaFuncAttributeMaxDynamicSharedMemorySize, smem_gemm);
        cudaFuncSetAttribute(attn_mma, cudaFuncAttributeMaxDynamicSharedMemorySize, smem_attn);
        once = true;
    }

    detect_mask_kernel<<<1, 256>>>((const unsigned char*)mask1);
    pack_mask_kernel<<<2048, 256>>>(mask1, mask2, mask3);

    // pre-split inputs + weights into bf16 h/l planes
    {
        SplitJobs js;
        const float* srcs[12] = {x, context, context2, context3,
                                 (const float*)d_in[7], (const float*)d_in[9],
                                 (const float*)d_in[11], (const float*)d_in[13],
                                 (const float*)d_in[15], (const float*)d_in[17],
                                 (const float*)d_in[19], Wo};
        int offs[12] = {OFF_X, OFF_C1, OFF_C2, OFF_C3,
                        OFF_WQ, OFF_WK1, OFF_WV1, OFF_WK2, OFF_WV2,
                        OFF_WK3, OFF_WV3, OFF_WO};
        int cnts[12] = {512, 512, 768, 512, 64, 64, 64, 96, 96, 32, 32, 64};
        int cum = 0;
        for (int i = 0; i < 12; ++i) {
            js.src[i] = srcs[i]; js.off[i] = offs[i];
            js.nblk[i] = cum; cum += cnts[i];
        }
        js.nblk[12] = cum;
        split_kernel<<<cum, 256>>>(js, 12);
    }

    // merged projection GEMMs (7 jobs, one launch); Q scaled by EXP2C (mode 4)
    {
        GJobs J;
        int aoffs[7]  = {OFF_X, OFF_C1, OFF_C2, OFF_C3, OFF_C1, OFF_C2, OFF_C3};
        int woffs[7]  = {OFF_WQ, OFF_WK1, OFF_WK2, OFF_WK3, OFF_WV1, OFF_WV2, OFF_WV3};
        const float* biases[7] = {bq, bk1, bk2, bk3, bv1, bv2, bv3};
        void* Cs[7]   = {qbp, kbp, kbp, kbp, vp, vp, vp};
        int Ks[7]     = {512, 512, 768, 256, 512, 768, 256};
        int Mbs[7]    = {1024, 1024, 1024, 2048, 1024, 1024, 2048};
        int ros[7]    = {0, 0, 1024, 2048, 0, 1024, 2048};
        int bss[7]    = {1024, 4096, 4096, 4096, 4096, 4096, 4096};
        int modes[7]  = {4, 2, 2, 2, 1, 1, 1};
        int blks[7]   = {256, 256, 256, 512, 256, 256, 512};
        int cum = 0;
        for (int i = 0; i < 7; ++i) {
            J.Ah[i] = hp + aoffs[i]; J.Al[i] = lp + aoffs[i];
            J.Wh[i] = hp + woffs[i]; J.Wl[i] = lp + woffs[i];
            J.bias[i] = biases[i]; J.C[i] = Cs[i];
            J.K[i] = Ks[i]; J.Mb[i] = Mbs[i]; J.rowOff[i] = ros[i];
            J.bStride[i] = bss[i]; J.mode[i] = modes[i];
            J.blk0[i] = cum; cum += blks[i];
        }
        J.blk0[7] = cum; J.njobs = 7;
        gemm_jobs<<<cum, 256, smem_gemm>>>(J);
    }

    // attention -> bf16 h/l planes at OFF_AO (no separate split pass)
    attn_mma<<<dim3(8, 8, 4), 256, smem_attn>>>(qbp, kbp, vp, hp + OFF_AO, lp + OFF_AO);

    // final projection -> d_out
    {
        GJobs J;
        J.Ah[0] = hp + OFF_AO; J.Al[0] = lp + OFF_AO;
        J.Wh[0] = hp + OFF_WO; J.Wl[0] = lp + OFF_WO;
        J.bias[0] = bo; J.C[0] = out;
        J.K[0] = 512; J.Mb[0] = 1024; J.rowOff[0] = 0;
        J.bStride[0] = 1024; J.mode[0] = 0;
        J.blk0[0] = 0; J.blk0[1] = 256; J.njobs = 1;
        gemm_jobs<<<256, 256, smem_gemm>>>(J);
    }
}

// round 11
// speedup vs baseline: 5.5348x; 1.0137x over previous
#include <cuda_runtime.h>
#include <cstdint>

#define EXP2C 0.1803368801111204f   /* (1/8) * log2(e) */

// ================= pools / scratch =================
#define OFF_X   0
#define OFF_C1  2097152
#define OFF_C2  4194304
#define OFF_C3  7340032
#define OFF_AO  9437184
#define OFF_WQ  11534336
#define OFF_WK1 11796480
#define OFF_WV1 12058624
#define OFF_WK2 12320768
#define OFF_WV2 12713984
#define OFF_WK3 13107200
#define OFF_WV3 13238272
#define OFF_WO  13369344
#define POOL_N  13631488

__device__ uint16_t g_h[POOL_N];
__device__ uint16_t g_l[POOL_N];
__device__ uint16_t g_qb[4 * 1024 * 512];
__device__ uint16_t g_kb[4 * 4096 * 512];
__device__ float    g_v[4 * 4096 * 512];
__device__ uint32_t g_mbits[4 * 1024 * 128];
__device__ int      g_mask_is_byte;

// ================= helpers =================
__device__ __forceinline__ uint32_t smem_u32(const void* p) {
    uint32_t a;
    asm("{ .reg .u64 t; cvta.to.shared.u64 t, %1; cvt.u32.u64 %0, t; }" : "=r"(a) : "l"(p));
    return a;
}
#define CP16(dst, src) \
    asm volatile("cp.async.cg.shared.global [%0], [%1], 16;" :: "r"(dst), "l"(src))
#define CP8(dst, src) \
    asm volatile("cp.async.ca.shared.global [%0], [%1], 8;" :: "r"(dst), "l"(src))
#define CP_COMMIT() asm volatile("cp.async.commit_group;" ::: "memory")
#define CP_WAIT(n)  asm volatile("cp.async.wait_group %0;" :: "n"(n) : "memory")

__device__ __forceinline__ float tf32_rn(float x) {
    return __uint_as_float((__float_as_uint(x) + 0x1000u) & 0xFFFFE000u);
}
__device__ __forceinline__ float bf16_rn(float x) {
    uint32_t u = __float_as_uint(x);
    u += 0x7FFFu + ((u >> 16) & 1u);
    return __uint_as_float(u & 0xFFFF0000u);
}
__device__ __forceinline__ uint32_t pkh(float a, float b) {
    return (__float_as_uint(b) & 0xFFFF0000u) | (__float_as_uint(a) >> 16);
}
__device__ __forceinline__ uint32_t bf2(float a, float b) {
    uint32_t r;
    asm("cvt.rn.bf16x2.f32 %0, %1, %2;" : "=r"(r) : "f"(b), "f"(a));
    return r;
}
__device__ __forceinline__ float ex2f(float y) {
    float r;
    asm("ex2.approx.f32 %0, %1;" : "=f"(r) : "f"(y));
    return r;
}
__device__ __forceinline__ void mma8(float* c, const uint32_t* a, const uint32_t* b) {
    asm volatile("mma.sync.aligned.m16n8k8.row.col.f32.tf32.tf32.f32 "
        "{%0,%1,%2,%3},{%4,%5,%6,%7},{%8,%9},{%0,%1,%2,%3};"
        : "+f"(c[0]), "+f"(c[1]), "+f"(c[2]), "+f"(c[3])
        : "r"(a[0]), "r"(a[1]), "r"(a[2]), "r"(a[3]), "r"(b[0]), "r"(b[1]));
}
__device__ __forceinline__ void mma16(float* c, const uint32_t* a, const uint32_t* b) {
    asm volatile("mma.sync.aligned.m16n8k16.row.col.f32.bf16.bf16.f32 "
        "{%0,%1,%2,%3},{%4,%5,%6,%7},{%8,%9},{%0,%1,%2,%3};"
        : "+f"(c[0]), "+f"(c[1]), "+f"(c[2]), "+f"(c[3])
        : "r"(a[0]), "r"(a[1]), "r"(a[2]), "r"(a[3]), "r"(b[0]), "r"(b[1]));
}
__device__ __forceinline__ void ldsm_x4(uint32_t* r, uint32_t addr) {
    asm volatile("ldmatrix.sync.aligned.m8n8.x4.shared.b16 {%0,%1,%2,%3}, [%4];"
        : "=r"(r[0]), "=r"(r[1]), "=r"(r[2]), "=r"(r[3]) : "r"(addr));
}
__device__ __forceinline__ void ldsm_x4_t(uint32_t* r, uint32_t addr) {
    asm volatile("ldmatrix.sync.aligned.m8n8.x4.trans.shared.b16 {%0,%1,%2,%3}, [%4];"
        : "=r"(r[0]), "=r"(r[1]), "=r"(r[2]), "=r"(r[3]) : "r"(addr));
}

// ================= mask detect + bit-pack =================
__global__ void detect_mask_kernel(const unsigned char* __restrict__ m) {
    __shared__ int any;
    if (threadIdx.x == 0) any = 0;
    __syncthreads();
    int found = 0;
    for (int i = threadIdx.x; i < 4096; i += blockDim.x)
        if ((i & 3) == 1 && m[i]) found = 1;
    if (found) atomicOr(&any, 1);
    __syncthreads();
    if (threadIdx.x == 0) g_mask_is_byte = any;
}

__global__ void pack_mask_kernel(const void* __restrict__ m1, const void* __restrict__ m2,
                                 const void* __restrict__ m3) {
    int idx = blockIdx.x * blockDim.x + threadIdx.x;
    if (idx >= 4 * 1024 * 128) return;
    int w = idx & 127, q = (idx >> 7) & 1023, b = idx >> 17;
    int k0 = w * 32;
    const void* mp; int nseg, jl;
    if (k0 < 1024)      { mp = m1; nseg = 1024; jl = k0; }
    else if (k0 < 2048) { mp = m2; nseg = 1024; jl = k0 - 1024; }
    else                { mp = m3; nseg = 2048; jl = k0 - 2048; }
    size_t base = (size_t)(b * 1024 + q) * nseg + jl;
    uint32_t bits = 0;
    if (g_mask_is_byte) {
        const uint4* p = (const uint4*)((const unsigned char*)mp + base);
        uint4 a = p[0], c = p[1];
        uint32_t ws[8] = {a.x, a.y, a.z, a.w, c.x, c.y, c.z, c.w};
#pragma unroll
        for (int wi = 0; wi < 8; ++wi)
#pragma unroll
            for (int by = 0; by < 4; ++by)
                if ((ws[wi] >> (8 * by)) & 0xFFu) bits |= 1u << (wi * 4 + by);
    } else {
        const uint4* p = (const uint4*)((const uint32_t*)mp + base);
#pragma unroll
        for (int wi = 0; wi < 8; ++wi) {
            uint4 v = p[wi];
            if (v.x) bits |= 1u << (wi * 4 + 0);
            if (v.y) bits |= 1u << (wi * 4 + 1);
            if (v.z) bits |= 1u << (wi * 4 + 2);
            if (v.w) bits |= 1u << (wi * 4 + 3);
        }
    }
    g_mbits[idx] = bits;
}

// ================= bf16 hi/lo split (pre-pass) =================
struct SplitJobs {
    const float* src[12];
    int nblk[13];
    int off[12];
};
__global__ __launch_bounds__(256) void split_kernel(SplitJobs j, int njobs) {
    int bid = blockIdx.x;
    int ji = 0;
    while (ji + 1 < njobs && bid >= j.nblk[ji + 1]) ++ji;
    int local = bid - j.nblk[ji];
    const float4* src = (const float4*)j.src[ji];
    uint2* dh = (uint2*)(g_h + j.off[ji]);
    uint2* dl = (uint2*)(g_l + j.off[ji]);
    size_t base4 = (size_t)local * 1024;
#pragma unroll
    for (int it = 0; it < 4; ++it) {
        size_t i4 = base4 + it * 256 + threadIdx.x;
        float4 v = src[i4];
        float h0 = bf16_rn(v.x), h1 = bf16_rn(v.y), h2 = bf16_rn(v.z), h3 = bf16_rn(v.w);
        dh[i4] = make_uint2(pkh(h0, h1), pkh(h2, h3));
        dl[i4] = make_uint2(bf2(v.x - h0, v.y - h1), bf2(v.z - h2, v.w - h3));
    }
}

// ================= 3xBF16 HMMA GEMM, job-table, cp.async 2-stage =================
// Block 128Mx64N, 8 warps (4m x 2n), chunk K=64.
#define G_OAL 4608
#define G_OBH 9216
#define G_OBL 11520
#define G_STW 13824
struct GJobs {
    const uint16_t* Ah[7]; const uint16_t* Al[7];
    const uint16_t* Wh[7]; const uint16_t* Wl[7];
    const float* bias[7];  void* C[7];
    int K[7], Mb[7], rowOff[7], bStride[7], mode[7];
    int blk0[8];
    int njobs;
};
// mode: 0 = fp32 out, 1 = tf32-rounded fp32 out, 2 = bf16 out, 4 = bf16 out scaled by EXP2C
__global__ __launch_bounds__(256, 2) void gemm_jobs(GJobs J) {
    extern __shared__ uint32_t smw[];
    int j = 0;
    while (j + 1 < J.njobs && (int)blockIdx.x >= J.blk0[j + 1]) ++j;
    const int lb = blockIdx.x - J.blk0[j];
    const uint16_t* __restrict__ Ah = J.Ah[j];
    const uint16_t* __restrict__ Al = J.Al[j];
    const uint16_t* __restrict__ Wh = J.Wh[j];
    const uint16_t* __restrict__ Wl = J.Wl[j];
    const float* __restrict__ bias = J.bias[j];
    void* Cv = J.C[j];
    const int K = J.K[j], Mb = J.Mb[j], rowOff = J.rowOff[j];
    const int bStride = J.bStride[j], mode = J.mode[j];

    const int tid = threadIdx.x, lane = tid & 31, wid = tid >> 5;
    const int wm = wid & 3, wn = wid >> 2;
    const int lr = lane >> 2, lc = lane & 3;
    const int m0 = (lb >> 3) * 128, n0 = (lb & 7) * 64;
    const int l16 = lane & 15, lh8 = (lane >> 4) << 3;

    float acc[2][4][4];
#pragma unroll
    for (int i = 0; i < 2; ++i)
#pragma unroll
        for (int jj = 0; jj < 4; ++jj)
#pragma unroll
            for (int e = 0; e < 4; ++e) acc[i][jj][e] = 0.f;

    const int nK = K >> 6;
    const uint32_t ub = smem_u32(smw);

#define STAGE(c, s) do { \
    const uint32_t d0 = ub + (s) * G_STW * 4; \
    _Pragma("unroll") \
    for (int it = 0; it < 4; ++it) { \
        int id = it * 256 + tid, row = id >> 3, seg = id & 7; \
        size_t so = (size_t)(m0 + row) * K + (c) * 64 + seg * 8; \
        uint32_t dw = (row * 36 + seg * 4) * 4; \
        CP16(d0 + dw, Ah + so); \
        CP16(d0 + G_OAL * 4 + dw, Al + so); \
    } \
    _Pragma("unroll") \
    for (int it = 0; it < 2; ++it) { \
        int id = it * 256 + tid, row = id >> 3, seg = id & 7; \
        size_t so = (size_t)((c) * 64 + row) * 512 + n0 + seg * 8; \
        uint32_t dw = (row * 36 + seg * 4) * 4; \
        CP16(d0 + G_OBH * 4 + dw, Wh + so); \
        CP16(d0 + G_OBL * 4 + dw, Wl + so); \
    } \
    CP_COMMIT(); \
} while (0)

    STAGE(0, 0);
    for (int c = 0; c < nK; ++c) {
        const int s = c & 1;
        if (c + 1 < nK) { STAGE(c + 1, s ^ 1); CP_WAIT(1); }
        else            { CP_WAIT(0); }
        __syncthreads();
        const uint32_t sb = ub + s * G_STW * 4;
#pragma unroll
        for (int st = 0; st < 4; ++st) {
            const int k0 = st * 16;
            uint32_t ah[2][4], al_[2][4], bh[2][4], bl_[2][4];
#pragma unroll
            for (int mf = 0; mf < 2; ++mf) {
                int row = wm * 32 + mf * 16 + l16;
                uint32_t ad = sb + (row * 36 + ((k0 + lh8) >> 1)) * 4;
                ldsm_x4(ah[mf], ad);
                ldsm_x4(al_[mf], ad + G_OAL * 4);
            }
#pragma unroll
            for (int p = 0; p < 2; ++p) {
                int row = k0 + l16;
                int col = wn * 32 + p * 16 + lh8;
                uint32_t bd = sb + (G_OBH + row * 36 + (col >> 1)) * 4;
                ldsm_x4_t(bh[p], bd);
                ldsm_x4_t(bl_[p], bd + (G_OBL - G_OBH) * 4);
            }
#pragma unroll
            for (int mf = 0; mf < 2; ++mf)
#pragma unroll
                for (int p = 0; p < 2; ++p) {
                    mma16(acc[mf][p * 2 + 0], ah[mf], &bh[p][0]);
                    mma16(acc[mf][p * 2 + 1], ah[mf], &bh[p][2]);
                    mma16(acc[mf][p * 2 + 0], ah[mf], &bl_[p][0]);
                    mma16(acc[mf][p * 2 + 1], ah[mf], &bl_[p][2]);
                    mma16(acc[mf][p * 2 + 0], al_[mf], &bh[p][0]);
                    mma16(acc[mf][p * 2 + 1], al_[mf], &bh[p][2]);
                }
        }
        __syncthreads();
    }
#undef STAGE
#pragma unroll
    for (int mf = 0; mf < 2; ++mf) {
        int r = m0 + wm * 32 + mf * 16 + lr;
        int b0i = r / Mb;
        size_t or0 = (size_t)b0i * bStride + rowOff + (r - b0i * Mb);
        int r2 = r + 8;
        int b1i = r2 / Mb;
        size_t or1 = (size_t)b1i * bStride + rowOff + (r2 - b1i * Mb);
#pragma unroll
        for (int nf = 0; nf < 4; ++nf) {
            int col = n0 + wn * 32 + nf * 8 + 2 * lc;
            float bv0 = bias[col], bv1 = bias[col + 1];
            float v00 = acc[mf][nf][0] + bv0, v01 = acc[mf][nf][1] + bv1;
            float v10 = acc[mf][nf][2] + bv0, v11 = acc[mf][nf][3] + bv1;
            if (mode >= 2) {
                if (mode == 4) { v00 *= EXP2C; v01 *= EXP2C; v10 *= EXP2C; v11 *= EXP2C; }
                uint16_t* Cb = (uint16_t*)Cv;
                *(uint32_t*)(Cb + or0 * 512 + col) = pkh(bf16_rn(v00), bf16_rn(v01));
                *(uint32_t*)(Cb + or1 * 512 + col) = pkh(bf16_rn(v10), bf16_rn(v11));
            } else {
                float* C = (float*)Cv;
                if (mode == 1) {
                    v00 = tf32_rn(v00); v01 = tf32_rn(v01);
                    v10 = tf32_rn(v10); v11 = tf32_rn(v11);
                }
                *(float2*)(C + or0 * 512 + col) = make_float2(v00, v01);
                *(float2*)(C + or1 * 512 + col) = make_float2(v10, v11);
            }
        }
    }
}

// ================= flash attention: 128q x 64k, early-staged pipeline =================
// 256 thr = 8 warps (4m x 2n). K/V/M for tile t+1 staged at loop TOP (full-iter latency cover).
#define A_QW 0
#define A_KW 4608
#define A_VW 9216
#define A_PW 18432
#define A_MW 27136
#define A_LW 27648
#define A_TOTW 27904
#define AV 72
#define AP 68

__global__ __launch_bounds__(256, 2) void attn_mma(
    const uint16_t* __restrict__ qb, const uint16_t* __restrict__ kb,
    const float* __restrict__ vb,
    uint16_t* __restrict__ oh, uint16_t* __restrict__ ol)
{
    extern __shared__ uint32_t smw[];
    float* smf = (float*)smw;
    uint32_t* sM = smw + A_MW;
    float* sP = smf + A_PW;
    float* sL = smf + A_LW;
    const uint32_t* sPu = smw + A_PW;

    const int tid = threadIdx.x, lane = tid & 31, wid = tid >> 5;
    const int wm = wid & 3, wn = wid >> 2;
    const int lr = lane >> 2, lc = lane & 3;
    const int ln8 = lane & 7;
    const int q0 = blockIdx.x * 128, h = blockIdx.y, b = blockIdx.z;

    const uint16_t* Qg = qb + ((size_t)(b * 1024 + q0)) * 512 + h * 64;
    const uint16_t* Kg = kb + ((size_t)(b * 4096)) * 512 + h * 64;
    const float*    Vg = vb + ((size_t)(b * 4096)) * 512 + h * 64;
    const uint32_t* mbase = g_mbits + ((size_t)(b * 1024 + q0)) * 128;
    const uint32_t ubase = smem_u32(smw);
    const uint32_t uQ = ubase + A_QW * 4, uK = ubase + A_KW * 4;
    const uint32_t uV = ubase + A_VW * 4, uM = ubase + A_MW * 4;

    // ---- prologue: Q(128 rows), K(0), V(0), M(0) ----
#pragma unroll
    for (int it = 0; it < 4; ++it) {
        int id = it * 256 + tid, row = id >> 3, seg = id & 7;
        CP16(uQ + (row * 36 + seg * 4) * 4, Qg + (size_t)row * 512 + seg * 8);
    }
#pragma unroll
    for (int it = 0; it < 2; ++it) {
        int id = it * 256 + tid, row = id >> 3, seg = id & 7;
        CP16(uK + (row * 36 + seg * 4) * 4, Kg + (size_t)row * 512 + seg * 8);
    }
#pragma unroll
    for (int it = 0; it < 4; ++it) {
        int id = it * 256 + tid, row = id >> 4, seg = id & 15;
        CP16(uV + (row * AV + seg * 4) * 4, Vg + (size_t)row * 512 + seg * 4);
    }
    if (tid < 128) CP8(uM + tid * 8, (const char*)(mbase + (size_t)tid * 128));
    CP_COMMIT();
    CP_WAIT(0);
    __syncthreads();

    float o[2][4][4];
    float l_acc[2][2];
#pragma unroll
    for (int i = 0; i < 2; ++i) {
        l_acc[i][0] = 0.f; l_acc[i][1] = 0.f;
#pragma unroll
        for (int jj = 0; jj < 4; ++jj)
#pragma unroll
            for (int e = 0; e < 4; ++e) o[i][jj][e] = 0.f;
    }

    for (int t = 0; t < 64; ++t) {
        const int s = t & 1;
        if (t > 0) { CP_WAIT(0); __syncthreads(); }

        // ---- EARLY stage of tile t+1 into buffer s^1 (free since PV(t-1) completed) ----
        if (t < 63) {
            const uint16_t* Kn = Kg + (size_t)(t + 1) * 64 * 512;
            const float* Vn = Vg + (size_t)(t + 1) * 64 * 512;
            const uint32_t dK = uK + (s ^ 1) * 2304 * 4;
            const uint32_t dV = uV + (s ^ 1) * 64 * AV * 4;
#pragma unroll
            for (int it = 0; it < 2; ++it) {
                int id = it * 256 + tid, row = id >> 3, seg = id & 7;
                CP16(dK + (row * 36 + seg * 4) * 4, Kn + (size_t)row * 512 + seg * 8);
            }
#pragma unroll
            for (int it = 0; it < 4; ++it) {
                int id = it * 256 + tid, row = id >> 4, seg = id & 15;
                CP16(dV + (row * AV + seg * 4) * 4, Vn + (size_t)row * 512 + seg * 4);
            }
            if (tid < 128)
                CP8(uM + (s ^ 1) * 1024 + tid * 8,
                    (const char*)(mbase + (size_t)tid * 128 + (t + 1) * 2));
            CP_COMMIT();
        }

        // ---- S' = (Q*EXP2C) K^T (bf16 m16n8k16); exponent-ready ----
        const uint32_t uKs = uK + s * 2304 * 4;
        float sv[2][4][4];
#pragma unroll
        for (int i = 0; i < 2; ++i)
#pragma unroll
            for (int jj = 0; jj < 4; ++jj)
#pragma unroll
                for (int e = 0; e < 4; ++e) sv[i][jj][e] = 0.f;
#pragma unroll
        for (int ks = 0; ks < 4; ++ks) {
            int kcb = ks * 16 + ((lane >> 3) & 1) * 8;
            int nrow = wn * 32 + (lane >> 4) * 8 + ln8;
            uint32_t bk0[4], bk1[4];
            ldsm_x4(bk0, uKs + (nrow * 36 + (kcb >> 1)) * 4);
            ldsm_x4(bk1, uKs + ((nrow + 16) * 36 + (kcb >> 1)) * 4);
#pragma unroll
            for (int mf = 0; mf < 2; ++mf) {
                int qrow = wm * 32 + mf * 16 + ((lane >> 3) & 1) * 8 + ln8;
                int kc = ks * 16 + (lane >> 4) * 8;
                uint32_t aq[4];
                ldsm_x4(aq, uQ + (qrow * 36 + (kc >> 1)) * 4);
                mma16(sv[mf][0], aq, &bk0[0]);
                mma16(sv[mf][1], aq, &bk0[2]);
                mma16(sv[mf][2], aq, &bk1[0]);
                mma16(sv[mf][3], aq, &bk1[2]);
            }
        }

        // ---- masked no-max softmax (MUFU ex2) + P write ----
#pragma unroll
        for (int mf = 0; mf < 2; ++mf)
#pragma unroll
            for (int u = 0; u < 2; ++u) {
                int row = wm * 32 + mf * 16 + lr + u * 8;
                uint32_t mw = sM[s * 256 + row * 2 + wn];
                float rs = 0.f;
#pragma unroll
                for (int nf = 0; nf < 4; ++nf) {
#pragma unroll
                    for (int q2 = 0; q2 < 2; ++q2) {
                        int cr = u * 2 + q2;
                        int cl = nf * 8 + 2 * lc + q2;
                        float p = tf32_rn(ex2f(sv[mf][nf][cr]));
                        p = ((mw >> cl) & 1u) ? p : 0.f;
                        rs += p;
                        sv[mf][nf][cr] = p;
                    }
                }
                l_acc[mf][u] += rs;
#pragma unroll
                for (int nf = 0; nf < 4; ++nf)
                    *(float2*)(sP + row * AP + wn * 32 + nf * 8 + 2 * lc) =
                        make_float2(sv[mf][nf][u * 2], sv[mf][nf][u * 2 + 1]);
            }
        __syncthreads();   // P visible

        // ---- O += P @ V (tf32 m16n8k8) ----
        const uint32_t* sVu = smw + A_VW + s * 64 * AV;
#pragma unroll
        for (int ks = 0; ks < 8; ++ks) {
            const int kb0 = ks * 8;
            uint32_t bv[4][2];
#pragma unroll
            for (int nf = 0; nf < 4; ++nf) {
                int drow = wn * 32 + nf * 8 + lr;
                bv[nf][0] = sVu[(kb0 + lc) * AV + drow];
                bv[nf][1] = sVu[(kb0 + 4 + lc) * AV + drow];
            }
#pragma unroll
            for (int mf = 0; mf < 2; ++mf) {
                int ar = wm * 32 + mf * 16 + lr;
                uint32_t ap[4] = {sPu[ar * AP + kb0 + lc], sPu[(ar + 8) * AP + kb0 + lc],
                                  sPu[ar * AP + kb0 + 4 + lc], sPu[(ar + 8) * AP + kb0 + 4 + lc]};
#pragma unroll
                for (int nf = 0; nf < 4; ++nf) mma8(o[mf][nf], ap, bv[nf]);
            }
        }
    }

    // ---- l reduce: quads, then the 2 n-warps via smem ----
#pragma unroll
    for (int mf = 0; mf < 2; ++mf)
#pragma unroll
        for (int u = 0; u < 2; ++u) {
            float v = l_acc[mf][u];
            v += __shfl_xor_sync(0xffffffffu, v, 1);
            v += __shfl_xor_sync(0xffffffffu, v, 2);
            l_acc[mf][u] = v;
        }
    if (lc == 0) {
#pragma unroll
        for (int mf = 0; mf < 2; ++mf)
#pragma unroll
            for (int u = 0; u < 2; ++u)
                sL[wn * 128 + wm * 32 + mf * 16 + lr + u * 8] = l_acc[mf][u];
    }
    __syncthreads();

    // normalize + write bf16 h/l planes (feeds final projection directly)
    uint16_t* Oh = oh + ((size_t)(b * 1024 + q0)) * 512 + h * 64;
    uint16_t* Ol = ol + ((size_t)(b * 1024 + q0)) * 512 + h * 64;
#pragma unroll
    for (int mf = 0; mf < 2; ++mf)
#pragma unroll
        for (int u = 0; u < 2; ++u) {
            int row = wm * 32 + mf * 16 + lr + u * 8;
            float linv = 1.f / (sL[row] + sL[128 + row]);
#pragma unroll
            for (int nf = 0; nf < 4; ++nf) {
                int col = wn * 32 + nf * 8 + 2 * lc;
                float v0 = o[mf][nf][u * 2] * linv;
                float v1 = o[mf][nf][u * 2 + 1] * linv;
                float h0 = bf16_rn(v0), h1 = bf16_rn(v1);
                *(uint32_t*)(Oh + (size_t)row * 512 + col) = pkh(h0, h1);
                *(uint32_t*)(Ol + (size_t)row * 512 + col) = bf2(v0 - h0, v1 - h1);
            }
        }
}

// ================= launcher =================
extern "C" void kernel_launch(void* const* d_in, const int* in_sizes, int n_in,
                              void* d_out, int out_size) {
    const float* x        = (const float*)d_in[0];
    const float* context  = (const float*)d_in[1];
    const float* context2 = (const float*)d_in[2];
    const float* context3 = (const float*)d_in[3];
    const void*  mask1 = d_in[4];
    const void*  mask2 = d_in[5];
    const void*  mask3 = d_in[6];
    const float* bq  = (const float*)d_in[8];
    const float* bk1 = (const float*)d_in[10];
    const float* bv1 = (const float*)d_in[12];
    const float* bk2 = (const float*)d_in[14];
    const float* bv2 = (const float*)d_in[16];
    const float* bk3 = (const float*)d_in[18];
    const float* bv3 = (const float*)d_in[20];
    const float* Wo  = (const float*)d_in[21];
    const float* bo  = (const float*)d_in[22];
    float* out = (float*)d_out;

    uint16_t *hp, *lp, *qbp, *kbp;
    float *vp;
    cudaGetSymbolAddress((void**)&hp,  g_h);
    cudaGetSymbolAddress((void**)&lp,  g_l);
    cudaGetSymbolAddress((void**)&qbp, g_qb);
    cudaGetSymbolAddress((void**)&kbp, g_kb);
    cudaGetSymbolAddress((void**)&vp,  g_v);

    const int smem_gemm = 2 * G_STW * 4;    // 110592
    const int smem_attn = A_TOTW * 4;       // 111616
    static bool once = false;
    if (!once) {
        cudaFuncSetAttribute(gemm_jobs, cudaFuncAttributeMaxDynamicSharedMemorySize, smem_gemm);
        cudaFuncSetAttribute(attn_mma, cudaFuncAttributeMaxDynamicSharedMemorySize, smem_attn);
        once = true;
    }

    detect_mask_kernel<<<1, 256>>>((const unsigned char*)mask1);
    pack_mask_kernel<<<2048, 256>>>(mask1, mask2, mask3);

    // pre-split inputs + weights into bf16 h/l planes
    {
        SplitJobs js;
        const float* srcs[12] = {x, context, context2, context3,
                                 (const float*)d_in[7], (const float*)d_in[9],
                                 (const float*)d_in[11], (const float*)d_in[13],
                                 (const float*)d_in[15], (const float*)d_in[17],
                                 (const float*)d_in[19], Wo};
        int offs[12] = {OFF_X, OFF_C1, OFF_C2, OFF_C3,
                        OFF_WQ, OFF_WK1, OFF_WV1, OFF_WK2, OFF_WV2,
                        OFF_WK3, OFF_WV3, OFF_WO};
        int cnts[12] = {512, 512, 768, 512, 64, 64, 64, 96, 96, 32, 32, 64};
        int cum = 0;
        for (int i = 0; i < 12; ++i) {
            js.src[i] = srcs[i]; js.off[i] = offs[i];
            js.nblk[i] = cum; cum += cnts[i];
        }
        js.nblk[12] = cum;
        split_kernel<<<cum, 256>>>(js, 12);
    }

    // merged projection GEMMs (7 jobs, one launch); Q scaled by EXP2C (mode 4)
    {
        GJobs J;
        int aoffs[7]  = {OFF_X, OFF_C1, OFF_C2, OFF_C3, OFF_C1, OFF_C2, OFF_C3};
        int woffs[7]  = {OFF_WQ, OFF_WK1, OFF_WK2, OFF_WK3, OFF_WV1, OFF_WV2, OFF_WV3};
        const float* biases[7] = {bq, bk1, bk2, bk3, bv1, bv2, bv3};
        void* Cs[7]   = {qbp, kbp, kbp, kbp, vp, vp, vp};
        int Ks[7]     = {512, 512, 768, 256, 512, 768, 256};
        int Mbs[7]    = {1024, 1024, 1024, 2048, 1024, 1024, 2048};
        int ros[7]    = {0, 0, 1024, 2048, 0, 1024, 2048};
        int bss[7]    = {1024, 4096, 4096, 4096, 4096, 4096, 4096};
        int modes[7]  = {4, 2, 2, 2, 1, 1, 1};
        int blks[7]   = {256, 256, 256, 512, 256, 256, 512};
        int cum = 0;
        for (int i = 0; i < 7; ++i) {
            J.Ah[i] = hp + aoffs[i]; J.Al[i] = lp + aoffs[i];
            J.Wh[i] = hp + woffs[i]; J.Wl[i] = lp + woffs[i];
            J.bias[i] = biases[i]; J.C[i] = Cs[i];
            J.K[i] = Ks[i]; J.Mb[i] = Mbs[i]; J.rowOff[i] = ros[i];
            J.bStride[i] = bss[i]; J.mode[i] = modes[i];
            J.blk0[i] = cum; cum += blks[i];
        }
        J.blk0[7] = cum; J.njobs = 7;
        gemm_jobs<<<cum, 256, smem_gemm>>>(J);
    }

    // attention -> bf16 h/l planes at OFF_AO (no separate split pass)
    attn_mma<<<dim3(8, 8, 4), 256, smem_attn>>>(qbp, kbp, vp, hp + OFF_AO, lp + OFF_AO);

    // final projection -> d_out
    {
        GJobs J;
        J.Ah[0] = hp + OFF_AO; J.Al[0] = lp + OFF_AO;
        J.Wh[0] = hp + OFF_WO; J.Wl[0] = lp + OFF_WO;
        J.bias[0] = bo; J.C[0] = out;
        J.K[0] = 512; J.Mb[0] = 1024; J.rowOff[0] = 0;
        J.bStride[0] = 1024; J.mode[0] = 0;
        J.blk0[0] = 0; J.blk0[1] = 256; J.njobs = 1;
        gemm_jobs<<<256, 256, smem_gemm>>>(J);
    }
}